// round 13
// baseline (speedup 1.0000x reference)
#include <cuda_runtime.h>
#include <cuda_fp16.h>
#include <math.h>
#include <stdint.h>

#define BQ 4
#define PP 1024
#define DDA 1024
#define DDC 3072
#define HID 512
typedef __half h16;

// ---------------- scratch ----------------
__device__ float g_acos[(size_t)BQ*PP*PP];
__device__ float g_ccos[(size_t)BQ*PP*PP];
__device__ float g_na[BQ*PP];
__device__ float g_nc[BQ*PP];
__device__ h16 g_ah[(size_t)BQ*PP*DDA], g_al[(size_t)BQ*PP*DDA];
__device__ h16 g_ch[(size_t)BQ*PP*DDC], g_cl[(size_t)BQ*PP*DDC];
__device__ h16 g_t2h[(size_t)BQ*PP*HID], g_t2l[(size_t)BQ*PP*HID];
__device__ h16 g_w1ah[DDA*HID], g_w1al[DDA*HID];
__device__ h16 g_w2ah[HID*DDA], g_w2al[HID*DDA];
__device__ h16 g_w1ch[DDC*HID], g_w1cl[DDC*HID];
__device__ h16 g_w2ch[HID*DDC], g_w2cl[HID*DDC];
__device__ h16 g_wp1h[DDA*128], g_wp1l[DDA*128];
__device__ h16 g_wp2h[DDC*128], g_wp2l[DDC*128];
__device__ h16 g_s1h[HID*128], g_s1l[HID*128];
__device__ h16 g_s2h[HID*128], g_s2l[HID*128];
__device__ float g_hp1[(size_t)8*BQ*PP*128];
__device__ float g_hp2[(size_t)8*BQ*PP*128];
__device__ float g_kp[(size_t)2*BQ*PP*HID];
__device__ float g_t1f[(size_t)BQ*PP*HID];
__device__ float g_spa[(size_t)BQ*PP*128];
__device__ float g_spc[(size_t)BQ*PP*128];
__device__ float g_cba[128], g_cbc[128];
__device__ int   g_sidx[(size_t)BQ*PP*PP];
__device__ float g_swa[(size_t)BQ*PP*PP];
__device__ float g_swc[(size_t)BQ*PP*PP];
__device__ int   g_scnt[BQ*PP];

// ====================== helpers ======================
__device__ __forceinline__ uint32_t smem_u32(const void* p) {
    uint32_t a;
    asm("{ .reg .u64 t; cvta.to.shared.u64 t, %1; cvt.u32.u64 %0, t; }" : "=r"(a) : "l"(p));
    return a;
}
__device__ __forceinline__ void split2(float x, float y, uint32_t& h, uint32_t& l) {
    __half hx = __float2half_rn(x), hy = __float2half_rn(y);
    float rx = x - __half2float(hx), ry = y - __half2float(hy);
    __half lx = __float2half_rn(rx), ly = __float2half_rn(ry);
    h = (uint32_t)__half_as_ushort(hx) | ((uint32_t)__half_as_ushort(hy) << 16);
    l = (uint32_t)__half_as_ushort(lx) | ((uint32_t)__half_as_ushort(ly) << 16);
}
__device__ __forceinline__ void split1(float x, unsigned short& h, unsigned short& l) {
    __half hx = __float2half_rn(x);
    float rx = x - __half2float(hx);
    h = __half_as_ushort(hx);
    l = __half_as_ushort(__float2half_rn(rx));
}
__device__ __forceinline__ void ldmx4(uint32_t* r, uint32_t addr) {
    asm volatile("ldmatrix.sync.aligned.m8n8.x4.shared.b16 {%0,%1,%2,%3}, [%4];"
                 : "=r"(r[0]), "=r"(r[1]), "=r"(r[2]), "=r"(r[3]) : "r"(addr));
}
__device__ __forceinline__ void ldmx4t(uint32_t* r, uint32_t addr) {
    asm volatile("ldmatrix.sync.aligned.m8n8.x4.trans.shared.b16 {%0,%1,%2,%3}, [%4];"
                 : "=r"(r[0]), "=r"(r[1]), "=r"(r[2]), "=r"(r[3]) : "r"(addr));
}
__device__ __forceinline__ void mma_f16(float* c, const uint32_t* a, const uint32_t* b) {
    asm volatile(
        "mma.sync.aligned.m16n8k16.row.col.f32.f16.f16.f32 "
        "{%0,%1,%2,%3}, {%4,%5,%6,%7}, {%8,%9}, {%0,%1,%2,%3};"
        : "+f"(c[0]), "+f"(c[1]), "+f"(c[2]), "+f"(c[3])
        : "r"(a[0]), "r"(a[1]), "r"(a[2]), "r"(a[3]), "r"(b[0]), "r"(b[1]));
}
__device__ __forceinline__ void cp16(uint32_t dst, const void* src) {
    asm volatile("cp.async.cg.shared.global [%0], [%1], 16;" :: "r"(dst), "l"(src) : "memory");
}
#define CP_COMMIT() asm volatile("cp.async.commit_group;" ::: "memory")

__device__ __forceinline__ uint32_t ksw(int row, int c) {
    return (uint32_t)(row * 64) + ((uint32_t)(c ^ ((row >> 1) & 3)) << 4);
}

// ====================== fp16 pair GEMM ======================
#define ATILE 8192
#define ASTG  16384
#define SBYTES 32768
#define NSTAGE 3
#define GSMEM (NSTAGE*SBYTES)

template<int TBK, int TERMS>
__global__ __launch_bounds__(256, 2)
void gemmx_k(const h16* __restrict__ Ah, const h16* __restrict__ Al,
             const h16* __restrict__ Bh, const h16* __restrict__ Bl,
             float* __restrict__ C, h16* __restrict__ Ch, h16* __restrict__ Cl,
             int N, int K, int Klen, int symm,
             long sA, long sB, long sC,
             const float* __restrict__ bias,
             const float* __restrict__ resid, long sR,
             int ldc, int relu_flag)
{
    if (!Klen && symm && blockIdx.x < blockIdx.y) return;
    extern __shared__ char sm[];
    uint32_t smb = smem_u32(sm);

    const int tid = threadIdx.x;
    const int lane = tid & 31;
    const int wid = tid >> 5;
    const int wm = (wid >> 2) * 64;
    const int wn = (wid & 3) * 32;

    long bz = blockIdx.z;
    const int bm = blockIdx.y * 128;
    const int nxt = N >> 7;
    int bn, kbase, kslice = 0;
    if (Klen) {
        kslice = (int)blockIdx.x / nxt;
        bn = ((int)blockIdx.x - kslice * nxt) << 7;
        kbase = kslice * Klen;
    } else {
        bn = (int)blockIdx.x << 7;
        kbase = 0;
    }
    const int KL = Klen ? Klen : K;

    const h16* Ahb = Ah + bz * sA + (size_t)bm * K + kbase;
    const h16* Alb = Al + bz * sA + (size_t)bm * K + kbase;
    const h16* Bhb = TBK ? (Bh + bz * sB + (size_t)bn * K + kbase)
                         : (Bh + bz * sB + (size_t)kbase * N + bn);
    const h16* Blb = TBK ? (Bl + bz * sB + (size_t)bn * K + kbase)
                         : (Bl + bz * sB + (size_t)kbase * N + bn);
    float* Cb = C ? (Klen ? C + (size_t)kslice * sC : C + bz * sC) : (float*)0;
    h16* Chb = Ch ? Ch + bz * sC : (h16*)0;
    h16* Clb = Cl ? Cl + bz * sC : (h16*)0;
    const float* Rb = resid ? resid + bz * sR : (const float*)0;

    float acc[4][4][4];
#pragma unroll
    for (int i = 0; i < 4; i++)
#pragma unroll
        for (int j = 0; j < 4; j++)
#pragma unroll
            for (int r = 0; r < 4; r++) acc[i][j][r] = 0.f;

    const int nch = KL >> 5;

    auto load_stage = [&](int kt, int s) {
        uint32_t base = smb + (uint32_t)s * SBYTES;
        int k0 = kt << 5;
#pragma unroll
        for (int it = 0; it < 4; it++) {
            int id = it * 256 + tid;
            int hl = id >> 9, rid = id & 511;
            int row = rid >> 2, c = rid & 3;
            if (TERMS >= 3 || hl == 0)
                cp16(base + hl * ATILE + ksw(row, c),
                     (hl ? Alb : Ahb) + (size_t)row * K + k0 + c * 8);
        }
        if (TBK) {
#pragma unroll
            for (int it = 0; it < 4; it++) {
                int id = it * 256 + tid;
                int hl = id >> 9, rid = id & 511;
                int row = rid >> 2, c = rid & 3;
                cp16(base + ASTG + hl * ATILE + ksw(row, c),
                     (hl ? Blb : Bhb) + (size_t)row * K + k0 + c * 8);
            }
        } else {
#pragma unroll
            for (int it = 0; it < 4; it++) {
                int id = it * 256 + tid;
                int hl = id >> 9, rid = id & 511;
                int k = rid >> 4, c = rid & 15;
                cp16(base + ASTG + hl * ATILE + k * 256 + ((c ^ (k & 7)) << 4),
                     (hl ? Blb : Bhb) + (size_t)(k0 + k) * N + c * 8);
            }
        }
        CP_COMMIT();
    };

    load_stage(0, 0);
    load_stage(1, 1);

    int sc = 0, sl = 2;
    for (int kt = 0; kt < nch; kt++) {
        asm volatile("cp.async.wait_group 1;" ::: "memory");
        __syncthreads();
        if (kt + 2 < nch) {
            load_stage(kt + 2, sl);
            sl = (sl + 1 == NSTAGE) ? 0 : sl + 1;
        } else {
            CP_COMMIT();
        }
        uint32_t aB = smb + (uint32_t)sc * SBYTES;
        uint32_t bB = aB + ASTG;
        sc = (sc + 1 == NSTAGE) ? 0 : sc + 1;

#pragma unroll
        for (int kh = 0; kh < 2; kh++) {
            uint32_t ahi[4][4], alo[4][4];
            {
                int u = kh * 2 + (lane >> 4);
#pragma unroll
                for (int i = 0; i < 4; i++) {
                    int r = wm + (lane & 15) + i * 16;
                    uint32_t ro = ksw(r, u);
                    ldmx4(ahi[i], aB + ro);
                    if (TERMS >= 3) ldmx4(alo[i], aB + ATILE + ro);
                }
            }
#pragma unroll
            for (int jp = 0; jp < 2; jp++) {
                uint32_t bh2[4], bl2[4];
                if (TBK) {
                    int row = wn + jp * 16 + ((lane >> 4) << 3) + (lane & 7);
                    int u = kh * 2 + ((lane >> 3) & 1);
                    uint32_t ro = ksw(row, u);
                    ldmx4(bh2, bB + ro);
                    ldmx4(bl2, bB + ATILE + ro);
                } else {
                    int k = kh * 16 + ((lane >> 3) & 1) * 8 + (lane & 7);
                    uint32_t kro = (uint32_t)k << 8;
                    int colblk = (wn >> 3) + 2 * jp + (lane >> 4);
                    uint32_t ad = kro + ((uint32_t)(colblk ^ (k & 7)) << 4);
                    ldmx4t(bh2, bB + ad);
                    ldmx4t(bl2, bB + ATILE + ad);
                }
                int j0 = 2 * jp, j1 = 2 * jp + 1;
#pragma unroll
                for (int i = 0; i < 4; i++) {
                    mma_f16(acc[i][j0], ahi[i], bh2 + 0);
                    mma_f16(acc[i][j1], ahi[i], bh2 + 2);
                }
#pragma unroll
                for (int i = 0; i < 4; i++) {
                    mma_f16(acc[i][j0], ahi[i], bl2 + 0);
                    mma_f16(acc[i][j1], ahi[i], bl2 + 2);
                }
                if (TERMS >= 3) {
#pragma unroll
                    for (int i = 0; i < 4; i++) {
                        mma_f16(acc[i][j0], alo[i], bh2 + 0);
                        mma_f16(acc[i][j1], alo[i], bh2 + 2);
                    }
                }
            }
        }
    }

#pragma unroll
    for (int i = 0; i < 4; i++) {
        int r0 = bm + wm + i * 16 + (lane >> 2);
        int r1 = r0 + 8;
#pragma unroll
        for (int j = 0; j < 4; j++) {
            int gc = bn + wn + j * 8 + (lane & 3) * 2;
            float2 v0 = make_float2(acc[i][j][0], acc[i][j][1]);
            float2 v1 = make_float2(acc[i][j][2], acc[i][j][3]);
            if (bias) {
                float2 bv = *reinterpret_cast<const float2*>(bias + gc);
                v0.x += bv.x; v0.y += bv.y;
                v1.x += bv.x; v1.y += bv.y;
            }
            if (Rb) {
                float2 q0 = *reinterpret_cast<const float2*>(Rb + (size_t)r0 * ldc + gc);
                float2 q1 = *reinterpret_cast<const float2*>(Rb + (size_t)r1 * ldc + gc);
                v0.x += q0.x; v0.y += q0.y;
                v1.x += q1.x; v1.y += q1.y;
            }
            if (relu_flag) {
                v0.x = fmaxf(v0.x, 0.f); v0.y = fmaxf(v0.y, 0.f);
                v1.x = fmaxf(v1.x, 0.f); v1.y = fmaxf(v1.y, 0.f);
            }
            if (Cb) {
                *reinterpret_cast<float2*>(Cb + (size_t)r0 * ldc + gc) = v0;
                *reinterpret_cast<float2*>(Cb + (size_t)r1 * ldc + gc) = v1;
            }
            if (Chb) {
                uint32_t h0, l0, h1, l1;
                split2(v0.x, v0.y, h0, l0);
                split2(v1.x, v1.y, h1, l1);
                *reinterpret_cast<uint32_t*>(Chb + (size_t)r0 * ldc + gc) = h0;
                *reinterpret_cast<uint32_t*>(Clb + (size_t)r0 * ldc + gc) = l0;
                *reinterpret_cast<uint32_t*>(Chb + (size_t)r1 * ldc + gc) = h1;
                *reinterpret_cast<uint32_t*>(Clb + (size_t)r1 * ldc + gc) = l1;
            }
        }
    }
}

// ====================== sparse SpMM (wide, fp16 pair out) ======================
template<int NPT>
__global__ __launch_bounds__(256)
void spmm_k(const int* __restrict__ scnt, const int* __restrict__ sidx,
            const float* __restrict__ swgt, const float* __restrict__ X,
            const float* __restrict__ bias,
            h16* __restrict__ outH, h16* __restrict__ outL, int relu_flag)
{
    constexpr int W = NPT * 256;
    __shared__ int s_i[PP];
    __shared__ float s_w[PP];
    int row = blockIdx.x;
    int b = row >> 10;
    int tid = threadIdx.x;
    int cnt = scnt[row];
    const int* ip = sidx + (size_t)row * PP;
    const float* wp = swgt + (size_t)row * PP;
    for (int i = tid; i < cnt; i += 256) { s_i[i] = ip[i]; s_w[i] = wp[i]; }
    __syncthreads();
    const float* Xb = X + (((size_t)b << 10) * W);
    float a0[NPT], a1[NPT], a2[NPT], a3[NPT];
#pragma unroll
    for (int r = 0; r < NPT; r++) { a0[r] = a1[r] = a2[r] = a3[r] = 0.f; }
    int e = 0;
    for (; e + 4 <= cnt; e += 4) {
        const float* x0 = Xb + (size_t)s_i[e + 0] * W;
        const float* x1 = Xb + (size_t)s_i[e + 1] * W;
        const float* x2 = Xb + (size_t)s_i[e + 2] * W;
        const float* x3 = Xb + (size_t)s_i[e + 3] * W;
        float w0 = s_w[e], w1 = s_w[e + 1], w2 = s_w[e + 2], w3 = s_w[e + 3];
#pragma unroll
        for (int r = 0; r < NPT; r++) {
            int c = r * 256 + tid;
            a0[r] += w0 * x0[c];
            a1[r] += w1 * x1[c];
            a2[r] += w2 * x2[c];
            a3[r] += w3 * x3[c];
        }
    }
    for (; e < cnt; e++) {
        const float* x0 = Xb + (size_t)s_i[e] * W;
        float w0 = s_w[e];
#pragma unroll
        for (int r = 0; r < NPT; r++) a0[r] += w0 * x0[r * 256 + tid];
    }
    unsigned short* oh = reinterpret_cast<unsigned short*>(outH) + (size_t)row * W;
    unsigned short* ol = reinterpret_cast<unsigned short*>(outL) + (size_t)row * W;
#pragma unroll
    for (int r = 0; r < NPT; r++) {
        int c = r * 256 + tid;
        float v = (a0[r] + a1[r]) + (a2[r] + a3[r]);
        if (bias) v += bias[c];
        if (relu_flag) v = fmaxf(v, 0.f);
        unsigned short hq, lq;
        split1(v, hq, lq);
        oh[c] = hq;
        ol[c] = lq;
    }
}

// narrow SpMM: 128 cols, fp32 out (no epilogue)
__global__ __launch_bounds__(128)
void spmms_k(const int* __restrict__ scnt, const int* __restrict__ sidx,
             const float* __restrict__ swgt, const float* __restrict__ X,
             float* __restrict__ out)
{
    __shared__ int s_i[PP];
    __shared__ float s_w[PP];
    int row = blockIdx.x;
    int b = row >> 10;
    int tid = threadIdx.x;
    int cnt = scnt[row];
    const int* ip = sidx + (size_t)row * PP;
    const float* wp = swgt + (size_t)row * PP;
    for (int i = tid; i < cnt; i += 128) { s_i[i] = ip[i]; s_w[i] = wp[i]; }
    __syncthreads();
    const float* Xb = X + (((size_t)b << 10) * 128);
    float a0 = 0.f, a1 = 0.f, a2 = 0.f, a3 = 0.f;
    int e = 0;
    for (; e + 4 <= cnt; e += 4) {
        a0 += s_w[e]     * Xb[(size_t)s_i[e]     * 128 + tid];
        a1 += s_w[e + 1] * Xb[(size_t)s_i[e + 1] * 128 + tid];
        a2 += s_w[e + 2] * Xb[(size_t)s_i[e + 2] * 128 + tid];
        a3 += s_w[e + 3] * Xb[(size_t)s_i[e + 3] * 128 + tid];
    }
    for (; e < cnt; e++) a0 += s_w[e] * Xb[(size_t)s_i[e] * 128 + tid];
    out[(size_t)row * 128 + tid] = (a0 + a1) + (a2 + a3);
}

// ====================== elementwise kernels ======================
__global__ void split_k(const float* __restrict__ s, h16* __restrict__ h,
                        h16* __restrict__ l, size_t n4)
{
    for (size_t i = (size_t)blockIdx.x * blockDim.x + threadIdx.x; i < n4;
         i += (size_t)gridDim.x * blockDim.x) {
        float4 v = reinterpret_cast<const float4*>(s)[i];
        uint32_t h0, l0, h1, l1;
        split2(v.x, v.y, h0, l0);
        split2(v.z, v.w, h1, l1);
        reinterpret_cast<uint2*>(h)[i] = make_uint2(h0, h1);
        reinterpret_cast<uint2*>(l)[i] = make_uint2(l0, l1);
    }
}

// sum nsl slices (stride n4 float4s) into fp32
__global__ void addn_k(const float* __restrict__ p, size_t n4, int nsl,
                       float* __restrict__ o)
{
    for (size_t i = (size_t)blockIdx.x * blockDim.x + threadIdx.x; i < n4;
         i += (size_t)gridDim.x * blockDim.x) {
        float4 a = reinterpret_cast<const float4*>(p)[i];
        for (int s = 1; s < nsl; s++) {
            float4 b = reinterpret_cast<const float4*>(p)[(size_t)s * n4 + i];
            a.x += b.x; a.y += b.y; a.z += b.z; a.w += b.w;
        }
        reinterpret_cast<float4*>(o)[i] = a;
    }
}

// sum nsl slices then fp16-pair split
__global__ void rednsplit_k(const float* __restrict__ p, size_t n4, int nsl,
                            h16* __restrict__ h, h16* __restrict__ l)
{
    for (size_t i = (size_t)blockIdx.x * blockDim.x + threadIdx.x; i < n4;
         i += (size_t)gridDim.x * blockDim.x) {
        float4 a = reinterpret_cast<const float4*>(p)[i];
        for (int s = 1; s < nsl; s++) {
            float4 b = reinterpret_cast<const float4*>(p)[(size_t)s * n4 + i];
            a.x += b.x; a.y += b.y; a.z += b.z; a.w += b.w;
        }
        uint32_t h0, l0, h1, l1;
        split2(a.x, a.y, h0, l0);
        split2(a.z, a.w, h1, l1);
        reinterpret_cast<uint2*>(h)[i] = make_uint2(h0, h1);
        reinterpret_cast<uint2*>(l)[i] = make_uint2(l0, l1);
    }
}

__global__ void zero_k(uint4* __restrict__ p, size_t n16)
{
    for (size_t i = (size_t)blockIdx.x * blockDim.x + threadIdx.x; i < n16;
         i += (size_t)gridDim.x * blockDim.x)
        p[i] = make_uint4(0, 0, 0, 0);
}

__global__ void padsplit_k(const float* __restrict__ src, h16* __restrict__ h,
                           h16* __restrict__ l, int K, int Nsrc, int col0)
{
    int total = K * Nsrc;
    for (int i = blockIdx.x * blockDim.x + threadIdx.x; i < total;
         i += gridDim.x * blockDim.x) {
        int k = i / Nsrc, n = i - k * Nsrc;
        unsigned short hq, lq;
        split1(src[i], hq, lq);
        size_t d = (size_t)k * 128 + col0 + n;
        reinterpret_cast<unsigned short*>(h)[d] = hq;
        reinterpret_cast<unsigned short*>(l)[d] = lq;
    }
}

__global__ void norms_k(const float* __restrict__ G, float* __restrict__ nrm)
{
    int i = blockIdx.x * blockDim.x + threadIdx.x;
    if (i < BQ * PP) {
        int b = i >> 10, p = i & (PP - 1);
        nrm[i] = sqrtf(G[((size_t)b * PP + p) * PP + p]);
    }
}

__global__ __launch_bounds__(256)
void mirror_k(float* __restrict__ A, float* __restrict__ B)
{
    int tj = blockIdx.x, ti = blockIdx.y, b = blockIdx.z;
    if (ti <= tj || (ti >> 2) == (tj >> 2)) return;
    __shared__ float ta[32][33], tb[32][33];
    int tx = threadIdx.x & 31, ty = threadIdx.x >> 5;
    size_t base = (size_t)b * PP * PP;
#pragma unroll
    for (int it = 0; it < 4; it++) {
        int r = ty + it * 8;
        size_t src = base + (size_t)(tj * 32 + r) * PP + ti * 32 + tx;
        ta[r][tx] = A[src];
        tb[r][tx] = B[src];
    }
    __syncthreads();
#pragma unroll
    for (int it = 0; it < 4; it++) {
        int r = ty + it * 8;
        size_t dst = base + (size_t)(ti * 32 + r) * PP + tj * 32 + tx;
        A[dst] = ta[tx][r];
        B[dst] = tb[tx][r];
    }
}

// constant row: cba[c] = fa_b[c] + dot(b2a, fa_w[:,c]) for c<21
__global__ void cbias1_k(const float* __restrict__ b2, const float* __restrict__ w,
                         const float* __restrict__ bb, float* __restrict__ cb)
{
    int c = threadIdx.x;
    if (c >= 128) return;
    float v = 0.f;
    if (c < 21) {
        v = bb[c];
        for (int k = 0; k < DDA; k++) v += b2[k] * w[k * 21 + c];
    }
    cb[c] = v;
}

__global__ void cbias2_k(const float* __restrict__ b2,
                         const float* __restrict__ wc, const float* __restrict__ bc,
                         const float* __restrict__ wr, const float* __restrict__ br,
                         float* __restrict__ cb)
{
    int c = threadIdx.x;
    if (c >= 128) return;
    float v = 0.f;
    if (c < 20) {
        v = bc[c];
        for (int k = 0; k < DDC; k++) v += b2[k] * wc[k * 20 + c];
    } else if (c < 60) {
        int c2 = c - 20;
        v = br[c2];
        for (int k = 0; k < DDC; k++) v += b2[k] * wr[k * 40 + c2];
    }
    cb[c] = v;
}

// out[row,col] assembly
__global__ void outasm_k(const float* __restrict__ spa, const float* __restrict__ spc,
                         const float* __restrict__ hp1, const float* __restrict__ hp2,
                         const float* __restrict__ cba, const float* __restrict__ cbc,
                         float* __restrict__ out)
{
    int i = blockIdx.x * blockDim.x + threadIdx.x;
    int total = BQ * PP * 81;
    if (i >= total) return;
    int row = i / 81, col = i - row * 81;
    float v;
    if (col < 21) {
        v = spa[(size_t)row * 128 + col] + cba[col];
#pragma unroll
        for (int s = 0; s < 8; s++)
            v += hp1[((size_t)s * BQ * PP + row) * 128 + col];
    } else {
        int c2 = col - 21;
        v = spc[(size_t)row * 128 + c2] + cbc[c2];
#pragma unroll
        for (int s = 0; s < 8; s++)
            v += hp2[((size_t)s * BQ * PP + row) * 128 + c2];
    }
    out[i] = v;
}

// ---------------- graph construction -> compact sparse lists ----------------
__device__ __forceinline__ void warp_argmin(float& v, int& l)
{
#pragma unroll
    for (int off = 16; off; off >>= 1) {
        float ov = __shfl_down_sync(0xffffffffu, v, off);
        int ol = __shfl_down_sync(0xffffffffu, l, off);
        if (ov < v) { v = ov; l = ol; }
    }
    v = __shfl_sync(0xffffffffu, v, 0);
    l = __shfl_sync(0xffffffffu, l, 0);
}
__device__ __forceinline__ void warp_argmax(float& v, int& l)
{
#pragma unroll
    for (int off = 16; off; off >>= 1) {
        float ov = __shfl_down_sync(0xffffffffu, v, off);
        int ol = __shfl_down_sync(0xffffffffu, l, off);
        if (ov > v) { v = ov; l = ol; }
    }
    v = __shfl_sync(0xffffffffu, v, 0);
    l = __shfl_sync(0xffffffffu, l, 0);
}

__global__ __launch_bounds__(128)
void build_adj_k(const float* __restrict__ iou, const float* __restrict__ dis,
                 const float* __restrict__ acos_, const float* __restrict__ ccos_,
                 const float* __restrict__ na, const float* __restrict__ nc,
                 const int* __restrict__ props,
                 int* __restrict__ sidx, float* __restrict__ swa,
                 float* __restrict__ swc, int* __restrict__ scnt)
{
    __shared__ float sio[4][PP];
    int warp = threadIdx.x >> 5, lane = threadIdx.x & 31;
    int row = blockIdx.x * 4 + warp;
    if (row >= BQ * PP) return;
    int b = row >> 10;
    int p = row & (PP - 1);
    const float* iour = iou + (size_t)row * PP;
    const float* disr = dis + (size_t)row * PP;
    const float* ar = acos_ + (size_t)row * PP;
    const float* cr = ccos_ + (size_t)row * PP;
    const float* nab = na + (b << 10);
    const float* ncb = nc + (b << 10);
    float npa = nab[p], npc = ncb[p];
    int pn = props[b];
    bool pv = p < pn;

    float* io_s = sio[warp];
    for (int q = lane; q < PP; q += 32) io_s[q] = iour[q];
    __syncwarp();

    float dv[6]; int di[6];
#pragma unroll
    for (int j = 0; j < 6; j++) { dv[j] = 3.0e38f; di[j] = -1; }
    float sv[2] = {-3.0e38f, -3.0e38f};
    int si2[2] = {-1, -1};

    for (int q = lane; q < PP; q += 32) {
        float io = io_s[q];
        bool ip = io > 0.0f;
        bool qv = q < pn;
        bool v2 = pv && qv;

        float dm = v2 ? (ip ? 2.0f : disr[q]) : 1.0e9f;
        if (dm < dv[5]) {
            dv[5] = dm; di[5] = q;
#pragma unroll
            for (int j = 5; j > 0; j--) {
                if (dv[j] < dv[j - 1]) {
                    float tv = dv[j]; dv[j] = dv[j - 1]; dv[j - 1] = tv;
                    int ti = di[j]; di[j] = di[j - 1]; di[j - 1] = ti;
                }
            }
        }
        float av = ar[q] / (npa * nab[q] + 1e-6f);
        float sm = v2 ? (ip ? 0.0f : (av - (q == p ? 1.0f : 0.0f))) : -1.0e9f;
        if (sm > sv[1]) {
            if (sm > sv[0]) { sv[1] = sv[0]; si2[1] = si2[0]; sv[0] = sm; si2[0] = q; }
            else            { sv[1] = sm; si2[1] = q; }
        }
    }

    int sel[8];
    {
        int ptr = 0;
        for (int k = 0; k < 6; k++) {
            float cv = (ptr < 6) ? dv[ptr] : 3.0e38f;
            int ci = (ptr < 6) ? di[ptr] : -1;
            float v = cv; int l = lane;
            warp_argmin(v, l);
            sel[k] = __shfl_sync(0xffffffffu, ci, l);
            if (lane == l) ptr++;
        }
    }
    {
        int ptr = 0;
        for (int k = 0; k < 2; k++) {
            float cv = (ptr < 2) ? sv[ptr] : -3.0e38f;
            int ci = (ptr < 2) ? si2[ptr] : -1;
            float v = cv; int l = lane;
            warp_argmax(v, l);
            sel[6 + k] = __shfl_sync(0xffffffffu, ci, l);
            if (lane == l) ptr++;
        }
    }
#pragma unroll
    for (int k = 0; k < 8; k++) {
        int q = sel[k];
        bool ok = (q >= 0) && pv && (q < pn) && !(io_s[q] > 0.0f);
        sel[k] = ok ? q : -1;
    }

    unsigned mbits = 0;
    for (int i = 0; i < 32; i++) {
        int q = lane + 32 * i;
        float io = io_s[q];
        bool bit = (q != p) && (io > 0.7f);
#pragma unroll
        for (int k = 0; k < 8; k++) bit |= (sel[k] == q);
        mbits |= (bit ? 1u : 0u) << i;
    }
    int cnt = __popc(mbits);
#pragma unroll
    for (int off = 16; off; off >>= 1) cnt += __shfl_xor_sync(0xffffffffu, cnt, off);
    float inv = 1.0f / ((float)cnt + 1e-6f);

    int* rI = sidx + (size_t)row * PP;
    float* rA = swa + (size_t)row * PP;
    float* rC = swc + (size_t)row * PP;
    int base = 0;
    for (int i = 0; i < 32; i++) {
        int q = lane + 32 * i;
        float m = ((mbits >> i) & 1u) ? inv : 0.0f;
        if (q == p) m += 1.0f;
        bool en = m > 0.f;
        unsigned bal = __ballot_sync(0xffffffffu, en);
        if (en) {
            int pos = base + __popc(bal & ((1u << lane) - 1u));
            float av = ar[q] / (npa * nab[q] + 1e-6f);
            float cv = cr[q] / (npc * ncb[q] + 1e-6f);
            rI[pos] = q;
            rA[pos] = fmaxf(av * m, 0.f);
            rC[pos] = fmaxf(cv * m, 0.f);
        }
        base += __popc(bal);
    }
    if (lane == 0) scnt[row] = base;
}

// ---------------- host ----------------
static void gx(int tbk, int terms,
               const h16* Ah, const h16* Al, const h16* Bh, const h16* Bl,
               float* C, h16* Ch, h16* Cl,
               int M, int N, int K, int Klen, int symm,
               long sA, long sB, long sC, int batch,
               const float* bias, const float* resid, long sR,
               int ldc, int relu)
{
    int nxt = N >> 7;
    int gxd = Klen ? nxt * (K / Klen) : nxt;
    dim3 grid(gxd, M / 128, batch);
    if (tbk == 1 && terms == 3) {
        cudaFuncSetAttribute(gemmx_k<1,3>, cudaFuncAttributeMaxDynamicSharedMemorySize, GSMEM);
        gemmx_k<1,3><<<grid, 256, GSMEM>>>(Ah, Al, Bh, Bl, C, Ch, Cl, N, K, Klen, symm,
                                           sA, sB, sC, bias, resid, sR, ldc, relu);
    } else if (tbk == 1 && terms == 2) {
        cudaFuncSetAttribute(gemmx_k<1,2>, cudaFuncAttributeMaxDynamicSharedMemorySize, GSMEM);
        gemmx_k<1,2><<<grid, 256, GSMEM>>>(Ah, Al, Bh, Bl, C, Ch, Cl, N, K, Klen, symm,
                                           sA, sB, sC, bias, resid, sR, ldc, relu);
    } else if (tbk == 0 && terms == 2) {
        cudaFuncSetAttribute(gemmx_k<0,2>, cudaFuncAttributeMaxDynamicSharedMemorySize, GSMEM);
        gemmx_k<0,2><<<grid, 256, GSMEM>>>(Ah, Al, Bh, Bl, C, Ch, Cl, N, K, Klen, symm,
                                           sA, sB, sC, bias, resid, sR, ldc, relu);
    } else {
        cudaFuncSetAttribute(gemmx_k<0,3>, cudaFuncAttributeMaxDynamicSharedMemorySize, GSMEM);
        gemmx_k<0,3><<<grid, 256, GSMEM>>>(Ah, Al, Bh, Bl, C, Ch, Cl, N, K, Klen, symm,
                                           sA, sB, sC, bias, resid, sR, ldc, relu);
    }
}

#define SYM(var, sym) cudaGetSymbolAddress((void**)&var, sym)

extern "C" void kernel_launch(void* const* d_in, const int* in_sizes, int n_in,
                              void* d_out, int out_size)
{
    const float* act   = (const float*)d_in[0];
    const float* comp  = (const float*)d_in[1];
    const float* iou   = (const float*)d_in[2];
    const float* dis   = (const float*)d_in[3];
    const int*   props = (const int*)d_in[4];
    const float* a_w1  = (const float*)d_in[5];
    const float* a_b1  = (const float*)d_in[6];
    const float* a_w2  = (const float*)d_in[7];
    const float* a_b2  = (const float*)d_in[8];
    const float* c_w1  = (const float*)d_in[9];
    const float* c_b1  = (const float*)d_in[10];
    const float* c_w2  = (const float*)d_in[11];
    const float* c_b2  = (const float*)d_in[12];
    const float* fa_w  = (const float*)d_in[13];
    const float* fa_b  = (const float*)d_in[14];
    const float* fc_w  = (const float*)d_in[15];
    const float* fc_b  = (const float*)d_in[16];
    const float* fr_w  = (const float*)d_in[17];
    const float* fr_b  = (const float*)d_in[18];
    float* out = (float*)d_out;

    float *acos_, *ccos_, *na, *nc, *hp1, *hp2, *kp, *t1f, *spa, *spc;
    float *swa, *swc, *cba, *cbc;
    h16 *ah, *al, *ch_, *cl_, *t2h, *t2l;
    h16 *w1ah, *w1al, *w2ah, *w2al, *w1ch, *w1cl, *w2ch, *w2cl;
    h16 *wp1h, *wp1l, *wp2h, *wp2l, *s1h, *s1l, *s2h, *s2l;
    int *sidx, *scnt;
    SYM(acos_, g_acos); SYM(ccos_, g_ccos); SYM(na, g_na); SYM(nc, g_nc);
    SYM(ah, g_ah); SYM(al, g_al); SYM(ch_, g_ch); SYM(cl_, g_cl);
    SYM(t2h, g_t2h); SYM(t2l, g_t2l);
    SYM(w1ah, g_w1ah); SYM(w1al, g_w1al); SYM(w2ah, g_w2ah); SYM(w2al, g_w2al);
    SYM(w1ch, g_w1ch); SYM(w1cl, g_w1cl); SYM(w2ch, g_w2ch); SYM(w2cl, g_w2cl);
    SYM(wp1h, g_wp1h); SYM(wp1l, g_wp1l); SYM(wp2h, g_wp2h); SYM(wp2l, g_wp2l);
    SYM(s1h, g_s1h); SYM(s1l, g_s1l); SYM(s2h, g_s2h); SYM(s2l, g_s2l);
    SYM(hp1, g_hp1); SYM(hp2, g_hp2); SYM(kp, g_kp);
    SYM(t1f, g_t1f); SYM(spa, g_spa); SYM(spc, g_spc);
    SYM(cba, g_cba); SYM(cbc, g_cbc);
    SYM(sidx, g_sidx); SYM(swa, g_swa); SYM(swc, g_swc); SYM(scnt, g_scnt);

    // splits
    split_k<<<1024, 256>>>(act, ah, al, (size_t)BQ * PP * DDA / 4);
    split_k<<<2048, 256>>>(comp, ch_, cl_, (size_t)BQ * PP * DDC / 4);
    split_k<<<256, 256>>>(a_w1, w1ah, w1al, (size_t)DDA * HID / 4);
    split_k<<<256, 256>>>(a_w2, w2ah, w2al, (size_t)HID * DDA / 4);
    split_k<<<512, 256>>>(c_w1, w1ch, w1cl, (size_t)DDC * HID / 4);
    split_k<<<512, 256>>>(c_w2, w2ch, w2cl, (size_t)HID * DDC / 4);

    // head weight panels [K,128]
    zero_k<<<64, 256>>>((uint4*)wp1h, (size_t)DDA * 128 * 2 / 16);
    zero_k<<<64, 256>>>((uint4*)wp1l, (size_t)DDA * 128 * 2 / 16);
    zero_k<<<128, 256>>>((uint4*)wp2h, (size_t)DDC * 128 * 2 / 16);
    zero_k<<<128, 256>>>((uint4*)wp2l, (size_t)DDC * 128 * 2 / 16);
    padsplit_k<<<128, 256>>>(fa_w, wp1h, wp1l, DDA, 21, 0);
    padsplit_k<<<256, 256>>>(fc_w, wp2h, wp2l, DDC, 20, 0);
    padsplit_k<<<512, 256>>>(fr_w, wp2h, wp2l, DDC, 40, 20);

    // S1 = w2a @ Wh1 [512x128], K=1024, TERMS=3, Klen=64 -> 16 slices
    gx(0, 3, w2ah, w2al, wp1h, wp1l, kp, 0, 0, HID, 128, DDA, 64, 0,
       0, 0, (long)HID * 128, 1, 0, 0, 0, 128, 0);
    rednsplit_k<<<64, 256>>>(kp, (size_t)HID * 128 / 4, 16, s1h, s1l);
    // S2 = w2c @ Wh2 [512x128], K=3072, Klen=192 -> 16 slices
    gx(0, 3, w2ch, w2cl, wp2h, wp2l, kp, 0, 0, HID, 128, DDC, 192, 0,
       0, 0, (long)HID * 128, 1, 0, 0, 0, 128, 0);
    rednsplit_k<<<64, 256>>>(kp, (size_t)HID * 128 / 4, 16, s2h, s2l);

    // constant head rows
    cbias1_k<<<1, 128>>>(a_b2, fa_w, fa_b, cba);
    cbias2_k<<<1, 128>>>(c_b2, fc_w, fc_b, fr_w, fr_b, cbc);

    // grams + norms + mirror + sparse graph
    gx(1, 3, ah, al, ah, al, acos_, 0, 0, PP, PP, DDA, 0, 1,
       (long)PP * DDA, (long)PP * DDA, (long)PP * PP, BQ, 0, 0, 0, PP, 0);
    gx(1, 2, ch_, cl_, ch_, cl_, ccos_, 0, 0, PP, PP, DDC, 0, 1,
       (long)PP * DDC, (long)PP * DDC, (long)PP * PP, BQ, 0, 0, 0, PP, 0);
    norms_k<<<(BQ * PP + 255) / 256, 256>>>(acos_, na);
    norms_k<<<(BQ * PP + 255) / 256, 256>>>(ccos_, nc);
    mirror_k<<<dim3(32, 32, BQ), 256>>>(acos_, ccos_);
    build_adj_k<<<BQ * PP / 4, 128>>>(iou, dis, acos_, ccos_, na, nc, props,
                                      sidx, swa, swc, scnt);

    // ---- Act chain ----
    gx(0, 2, ah, al, w1ah, w1al, kp, 0, 0, BQ * PP, HID, DDA, 512, 0,
       0, 0, (long)BQ * PP * HID, 1, 0, 0, 0, HID, 0);
    addn_k<<<2048, 256>>>(kp, (size_t)BQ * PP * HID / 4, 2, t1f);
    spmm_k<2><<<BQ * PP, 256>>>(scnt, sidx, swa, t1f, a_b1, t2h, t2l, 1);
    // T1s = t2 @ S1, K=512, Klen=128 -> 4 slices
    gx(0, 3, t2h, t2l, s1h, s1l, kp, 0, 0, BQ * PP, 128, HID, 128, 0,
       0, 0, (long)BQ * PP * 128, 1, 0, 0, 0, 128, 0);
    addn_k<<<1024, 256>>>(kp, (size_t)BQ * PP * 128 / 4, 4, t1f);
    spmms_k<<<BQ * PP, 128>>>(scnt, sidx, swa, t1f, spa);
    // A1 = act @ Wh1 partials, K=1024, Klen=128 -> 8 slices
    gx(0, 2, ah, al, wp1h, wp1l, hp1, 0, 0, BQ * PP, 128, DDA, 128, 0,
       0, 0, (long)BQ * PP * 128, 1, 0, 0, 0, 128, 0);

    // ---- Comp chain ----
    gx(0, 2, ch_, cl_, w1ch, w1cl, kp, 0, 0, BQ * PP, HID, DDC, 1536, 0,
       0, 0, (long)BQ * PP * HID, 1, 0, 0, 0, HID, 0);
    addn_k<<<2048, 256>>>(kp, (size_t)BQ * PP * HID / 4, 2, t1f);
    spmm_k<2><<<BQ * PP, 256>>>(scnt, sidx, swc, t1f, c_b1, t2h, t2l, 1);
    // T2s = t2 @ S2, K=512, Klen=128 -> 4 slices
    gx(0, 3, t2h, t2l, s2h, s2l, kp, 0, 0, BQ * PP, 128, HID, 128, 0,
       0, 0, (long)BQ * PP * 128, 1, 0, 0, 0, 128, 0);
    addn_k<<<1024, 256>>>(kp, (size_t)BQ * PP * 128 / 4, 4, t1f);
    spmms_k<<<BQ * PP, 128>>>(scnt, sidx, swc, t1f, spc);
    // C1 = comp @ Wh2 partials, K=3072, Klen=384 -> 8 slices
    gx(0, 2, ch_, cl_, wp2h, wp2l, hp2, 0, 0, BQ * PP, 128, DDC, 384, 0,
       0, 0, (long)BQ * PP * 128, 1, 0, 0, 0, 128, 0);

    // final assembly
    outasm_k<<<(BQ * PP * 81 + 255) / 256, 256>>>(spa, spc, hp1, hp2, cba, cbc, out);
}

// round 14
// speedup vs baseline: 1.4857x; 1.4857x over previous
#include <cuda_runtime.h>
#include <cuda_fp16.h>
#include <math.h>
#include <stdint.h>

#define BQ 4
#define PP 1024
#define DDA 1024
#define DDC 3072
#define HID 512
typedef __half h16;

// ---------------- scratch ----------------
__device__ float g_acos[(size_t)BQ*PP*PP];
__device__ float g_na[BQ*PP];
__device__ float g_nc[BQ*PP];
__device__ h16 g_ah[(size_t)BQ*PP*DDA], g_al[(size_t)BQ*PP*DDA];
__device__ h16 g_ch[(size_t)BQ*PP*DDC], g_cl[(size_t)BQ*PP*DDC];
__device__ h16 g_t2h[(size_t)BQ*PP*HID], g_t2l[(size_t)BQ*PP*HID];
__device__ h16 g_ofah[(size_t)BQ*PP*DDA], g_ofal[(size_t)BQ*PP*DDA];
__device__ h16 g_w1ah[DDA*HID], g_w1al[DDA*HID];
__device__ h16 g_w2ah[HID*DDA], g_w2al[HID*DDA];
__device__ h16 g_w1ch[DDC*HID], g_w1cl[DDC*HID];
__device__ h16 g_w2ch[HID*DDC], g_w2cl[HID*DDC];
__device__ h16 g_wp1h[DDA*128], g_wp1l[DDA*128];
__device__ h16 g_wp2h[DDC*128], g_wp2l[DDC*128];
__device__ h16 g_s2h[HID*128], g_s2l[HID*128];
__device__ float g_hp1[(size_t)8*BQ*PP*128];
__device__ float g_hp2[(size_t)8*BQ*PP*128];
__device__ float g_kp[(size_t)2*BQ*PP*HID];
__device__ float g_t1f[(size_t)BQ*PP*HID];
__device__ float g_t3f[(size_t)BQ*PP*DDA];
__device__ float g_spc[(size_t)BQ*PP*128];
__device__ float g_cbc[128];
__device__ int   g_sidx[(size_t)BQ*PP*PP];
__device__ float g_swa[(size_t)BQ*PP*PP];
__device__ float g_swc[(size_t)BQ*PP*PP];
__device__ int   g_scnt[BQ*PP];

// ====================== helpers ======================
__device__ __forceinline__ uint32_t smem_u32(const void* p) {
    uint32_t a;
    asm("{ .reg .u64 t; cvta.to.shared.u64 t, %1; cvt.u32.u64 %0, t; }" : "=r"(a) : "l"(p));
    return a;
}
__device__ __forceinline__ void split2(float x, float y, uint32_t& h, uint32_t& l) {
    __half hx = __float2half_rn(x), hy = __float2half_rn(y);
    float rx = x - __half2float(hx), ry = y - __half2float(hy);
    __half lx = __float2half_rn(rx), ly = __float2half_rn(ry);
    h = (uint32_t)__half_as_ushort(hx) | ((uint32_t)__half_as_ushort(hy) << 16);
    l = (uint32_t)__half_as_ushort(lx) | ((uint32_t)__half_as_ushort(ly) << 16);
}
__device__ __forceinline__ void split1(float x, unsigned short& h, unsigned short& l) {
    __half hx = __float2half_rn(x);
    float rx = x - __half2float(hx);
    h = __half_as_ushort(hx);
    l = __half_as_ushort(__float2half_rn(rx));
}
__device__ __forceinline__ void ldmx4(uint32_t* r, uint32_t addr) {
    asm volatile("ldmatrix.sync.aligned.m8n8.x4.shared.b16 {%0,%1,%2,%3}, [%4];"
                 : "=r"(r[0]), "=r"(r[1]), "=r"(r[2]), "=r"(r[3]) : "r"(addr));
}
__device__ __forceinline__ void ldmx4t(uint32_t* r, uint32_t addr) {
    asm volatile("ldmatrix.sync.aligned.m8n8.x4.trans.shared.b16 {%0,%1,%2,%3}, [%4];"
                 : "=r"(r[0]), "=r"(r[1]), "=r"(r[2]), "=r"(r[3]) : "r"(addr));
}
__device__ __forceinline__ void mma_f16(float* c, const uint32_t* a, const uint32_t* b) {
    asm volatile(
        "mma.sync.aligned.m16n8k16.row.col.f32.f16.f16.f32 "
        "{%0,%1,%2,%3}, {%4,%5,%6,%7}, {%8,%9}, {%0,%1,%2,%3};"
        : "+f"(c[0]), "+f"(c[1]), "+f"(c[2]), "+f"(c[3])
        : "r"(a[0]), "r"(a[1]), "r"(a[2]), "r"(a[3]), "r"(b[0]), "r"(b[1]));
}
__device__ __forceinline__ void cp16(uint32_t dst, const void* src) {
    asm volatile("cp.async.cg.shared.global [%0], [%1], 16;" :: "r"(dst), "l"(src) : "memory");
}
#define CP_COMMIT() asm volatile("cp.async.commit_group;" ::: "memory")

__device__ __forceinline__ uint32_t ksw(int row, int c) {
    return (uint32_t)(row * 64) + ((uint32_t)(c ^ ((row >> 1) & 3)) << 4);
}

// ====================== fp16 pair GEMM ======================
#define ATILE 8192
#define ASTG  16384
#define SBYTES 32768
#define NSTAGE 3
#define GSMEM (NSTAGE*SBYTES)

template<int TBK, int TERMS>
__global__ __launch_bounds__(256, 2)
void gemmx_k(const h16* __restrict__ Ah, const h16* __restrict__ Al,
             const h16* __restrict__ Bh, const h16* __restrict__ Bl,
             float* __restrict__ C, h16* __restrict__ Ch, h16* __restrict__ Cl,
             int N, int K, int Klen, int symm,
             long sA, long sB, long sC,
             const float* __restrict__ bias,
             const float* __restrict__ resid, long sR,
             int ldc, int relu_flag)
{
    if (!Klen && symm && blockIdx.x < blockIdx.y) return;
    extern __shared__ char sm[];
    uint32_t smb = smem_u32(sm);

    const int tid = threadIdx.x;
    const int lane = tid & 31;
    const int wid = tid >> 5;
    const int wm = (wid >> 2) * 64;
    const int wn = (wid & 3) * 32;

    long bz = blockIdx.z;
    const int bm = blockIdx.y * 128;
    const int nxt = N >> 7;
    int bn, kbase, kslice = 0;
    if (Klen) {
        kslice = (int)blockIdx.x / nxt;
        bn = ((int)blockIdx.x - kslice * nxt) << 7;
        kbase = kslice * Klen;
    } else {
        bn = (int)blockIdx.x << 7;
        kbase = 0;
    }
    const int KL = Klen ? Klen : K;

    const h16* Ahb = Ah + bz * sA + (size_t)bm * K + kbase;
    const h16* Alb = Al + bz * sA + (size_t)bm * K + kbase;
    const h16* Bhb = TBK ? (Bh + bz * sB + (size_t)bn * K + kbase)
                         : (Bh + bz * sB + (size_t)kbase * N + bn);
    const h16* Blb = TBK ? (Bl + bz * sB + (size_t)bn * K + kbase)
                         : (Bl + bz * sB + (size_t)kbase * N + bn);
    float* Cb = C ? (Klen ? C + (size_t)kslice * sC : C + bz * sC) : (float*)0;
    h16* Chb = Ch ? Ch + bz * sC : (h16*)0;
    h16* Clb = Cl ? Cl + bz * sC : (h16*)0;
    const float* Rb = resid ? resid + bz * sR : (const float*)0;

    float acc[4][4][4];
#pragma unroll
    for (int i = 0; i < 4; i++)
#pragma unroll
        for (int j = 0; j < 4; j++)
#pragma unroll
            for (int r = 0; r < 4; r++) acc[i][j][r] = 0.f;

    const int nch = KL >> 5;

    auto load_stage = [&](int kt, int s) {
        uint32_t base = smb + (uint32_t)s * SBYTES;
        int k0 = kt << 5;
#pragma unroll
        for (int it = 0; it < 4; it++) {
            int id = it * 256 + tid;
            int hl = id >> 9, rid = id & 511;
            int row = rid >> 2, c = rid & 3;
            if (TERMS >= 3 || hl == 0)
                cp16(base + hl * ATILE + ksw(row, c),
                     (hl ? Alb : Ahb) + (size_t)row * K + k0 + c * 8);
        }
        if (TBK) {
#pragma unroll
            for (int it = 0; it < 4; it++) {
                int id = it * 256 + tid;
                int hl = id >> 9, rid = id & 511;
                int row = rid >> 2, c = rid & 3;
                cp16(base + ASTG + hl * ATILE + ksw(row, c),
                     (hl ? Blb : Bhb) + (size_t)row * K + k0 + c * 8);
            }
        } else {
#pragma unroll
            for (int it = 0; it < 4; it++) {
                int id = it * 256 + tid;
                int hl = id >> 9, rid = id & 511;
                int k = rid >> 4, c = rid & 15;
                cp16(base + ASTG + hl * ATILE + k * 256 + ((c ^ (k & 7)) << 4),
                     (hl ? Blb : Bhb) + (size_t)(k0 + k) * N + c * 8);
            }
        }
        CP_COMMIT();
    };

    load_stage(0, 0);
    load_stage(1, 1);

    int sc = 0, sl = 2;
    for (int kt = 0; kt < nch; kt++) {
        asm volatile("cp.async.wait_group 1;" ::: "memory");
        __syncthreads();
        if (kt + 2 < nch) {
            load_stage(kt + 2, sl);
            sl = (sl + 1 == NSTAGE) ? 0 : sl + 1;
        } else {
            CP_COMMIT();
        }
        uint32_t aB = smb + (uint32_t)sc * SBYTES;
        uint32_t bB = aB + ASTG;
        sc = (sc + 1 == NSTAGE) ? 0 : sc + 1;

#pragma unroll
        for (int kh = 0; kh < 2; kh++) {
            uint32_t ahi[4][4], alo[4][4];
            {
                int u = kh * 2 + (lane >> 4);
#pragma unroll
                for (int i = 0; i < 4; i++) {
                    int r = wm + (lane & 15) + i * 16;
                    uint32_t ro = ksw(r, u);
                    ldmx4(ahi[i], aB + ro);
                    if (TERMS >= 3) ldmx4(alo[i], aB + ATILE + ro);
                }
            }
#pragma unroll
            for (int jp = 0; jp < 2; jp++) {
                uint32_t bh2[4], bl2[4];
                if (TBK) {
                    int row = wn + jp * 16 + ((lane >> 4) << 3) + (lane & 7);
                    int u = kh * 2 + ((lane >> 3) & 1);
                    uint32_t ro = ksw(row, u);
                    ldmx4(bh2, bB + ro);
                    ldmx4(bl2, bB + ATILE + ro);
                } else {
                    int k = kh * 16 + ((lane >> 3) & 1) * 8 + (lane & 7);
                    uint32_t kro = (uint32_t)k << 8;
                    int colblk = (wn >> 3) + 2 * jp + (lane >> 4);
                    uint32_t ad = kro + ((uint32_t)(colblk ^ (k & 7)) << 4);
                    ldmx4t(bh2, bB + ad);
                    ldmx4t(bl2, bB + ATILE + ad);
                }
                int j0 = 2 * jp, j1 = 2 * jp + 1;
#pragma unroll
                for (int i = 0; i < 4; i++) {
                    mma_f16(acc[i][j0], ahi[i], bh2 + 0);
                    mma_f16(acc[i][j1], ahi[i], bh2 + 2);
                }
#pragma unroll
                for (int i = 0; i < 4; i++) {
                    mma_f16(acc[i][j0], ahi[i], bl2 + 0);
                    mma_f16(acc[i][j1], ahi[i], bl2 + 2);
                }
                if (TERMS >= 3) {
#pragma unroll
                    for (int i = 0; i < 4; i++) {
                        mma_f16(acc[i][j0], alo[i], bh2 + 0);
                        mma_f16(acc[i][j1], alo[i], bh2 + 2);
                    }
                }
            }
        }
    }

#pragma unroll
    for (int i = 0; i < 4; i++) {
        int r0 = bm + wm + i * 16 + (lane >> 2);
        int r1 = r0 + 8;
#pragma unroll
        for (int j = 0; j < 4; j++) {
            int gc = bn + wn + j * 8 + (lane & 3) * 2;
            float2 v0 = make_float2(acc[i][j][0], acc[i][j][1]);
            float2 v1 = make_float2(acc[i][j][2], acc[i][j][3]);
            if (bias) {
                float2 bv = *reinterpret_cast<const float2*>(bias + gc);
                v0.x += bv.x; v0.y += bv.y;
                v1.x += bv.x; v1.y += bv.y;
            }
            if (Rb) {
                float2 q0 = *reinterpret_cast<const float2*>(Rb + (size_t)r0 * ldc + gc);
                float2 q1 = *reinterpret_cast<const float2*>(Rb + (size_t)r1 * ldc + gc);
                v0.x += q0.x; v0.y += q0.y;
                v1.x += q1.x; v1.y += q1.y;
            }
            if (relu_flag) {
                v0.x = fmaxf(v0.x, 0.f); v0.y = fmaxf(v0.y, 0.f);
                v1.x = fmaxf(v1.x, 0.f); v1.y = fmaxf(v1.y, 0.f);
            }
            if (Cb) {
                *reinterpret_cast<float2*>(Cb + (size_t)r0 * ldc + gc) = v0;
                *reinterpret_cast<float2*>(Cb + (size_t)r1 * ldc + gc) = v1;
            }
            if (Chb) {
                uint32_t h0, l0, h1, l1;
                split2(v0.x, v0.y, h0, l0);
                split2(v1.x, v1.y, h1, l1);
                *reinterpret_cast<uint32_t*>(Chb + (size_t)r0 * ldc + gc) = h0;
                *reinterpret_cast<uint32_t*>(Clb + (size_t)r0 * ldc + gc) = l0;
                *reinterpret_cast<uint32_t*>(Chb + (size_t)r1 * ldc + gc) = h1;
                *reinterpret_cast<uint32_t*>(Clb + (size_t)r1 * ldc + gc) = l1;
            }
        }
    }
}

// ====================== wide SpMM (fp16 pair out) ======================
template<int NPT>
__global__ __launch_bounds__(256)
void spmm_k(const int* __restrict__ scnt, const int* __restrict__ sidx,
            const float* __restrict__ swgt, const float* __restrict__ X,
            const float* __restrict__ bias, const float* __restrict__ resid,
            h16* __restrict__ outH, h16* __restrict__ outL, int relu_flag)
{
    constexpr int W = NPT * 256;
    __shared__ int s_i[PP];
    __shared__ float s_w[PP];
    int row = blockIdx.x;
    int b = row >> 10;
    int tid = threadIdx.x;
    int cnt = scnt[row];
    const int* ip = sidx + (size_t)row * PP;
    const float* wp = swgt + (size_t)row * PP;
    for (int i = tid; i < cnt; i += 256) { s_i[i] = ip[i]; s_w[i] = wp[i]; }
    __syncthreads();
    const float* Xb = X + (((size_t)b << 10) * W);
    float a0[NPT], a1[NPT], a2[NPT], a3[NPT];
#pragma unroll
    for (int r = 0; r < NPT; r++) { a0[r] = a1[r] = a2[r] = a3[r] = 0.f; }
    int e = 0;
    for (; e + 4 <= cnt; e += 4) {
        const float* x0 = Xb + (size_t)s_i[e + 0] * W;
        const float* x1 = Xb + (size_t)s_i[e + 1] * W;
        const float* x2 = Xb + (size_t)s_i[e + 2] * W;
        const float* x3 = Xb + (size_t)s_i[e + 3] * W;
        float w0 = s_w[e], w1 = s_w[e + 1], w2 = s_w[e + 2], w3 = s_w[e + 3];
#pragma unroll
        for (int r = 0; r < NPT; r++) {
            int c = r * 256 + tid;
            a0[r] += w0 * x0[c];
            a1[r] += w1 * x1[c];
            a2[r] += w2 * x2[c];
            a3[r] += w3 * x3[c];
        }
    }
    for (; e < cnt; e++) {
        const float* x0 = Xb + (size_t)s_i[e] * W;
        float w0 = s_w[e];
#pragma unroll
        for (int r = 0; r < NPT; r++) a0[r] += w0 * x0[r * 256 + tid];
    }
    unsigned short* oh = reinterpret_cast<unsigned short*>(outH) + (size_t)row * W;
    unsigned short* ol = reinterpret_cast<unsigned short*>(outL) + (size_t)row * W;
#pragma unroll
    for (int r = 0; r < NPT; r++) {
        int c = r * 256 + tid;
        float v = (a0[r] + a1[r]) + (a2[r] + a3[r]);
        if (bias) v += bias[c];
        if (resid) v += resid[(size_t)row * W + c];
        if (relu_flag) v = fmaxf(v, 0.f);
        unsigned short hq, lq;
        split1(v, hq, lq);
        oh[c] = hq;
        ol[c] = lq;
    }
}

// narrow SpMM: 128 cols, fp32 out
__global__ __launch_bounds__(128)
void spmms_k(const int* __restrict__ scnt, const int* __restrict__ sidx,
             const float* __restrict__ swgt, const float* __restrict__ X,
             float* __restrict__ out)
{
    __shared__ int s_i[PP];
    __shared__ float s_w[PP];
    int row = blockIdx.x;
    int b = row >> 10;
    int tid = threadIdx.x;
    int cnt = scnt[row];
    const int* ip = sidx + (size_t)row * PP;
    const float* wp = swgt + (size_t)row * PP;
    for (int i = tid; i < cnt; i += 128) { s_i[i] = ip[i]; s_w[i] = wp[i]; }
    __syncthreads();
    const float* Xb = X + (((size_t)b << 10) * 128);
    float a0 = 0.f, a1 = 0.f, a2 = 0.f, a3 = 0.f;
    int e = 0;
    for (; e + 4 <= cnt; e += 4) {
        a0 += s_w[e]     * Xb[(size_t)s_i[e]     * 128 + tid];
        a1 += s_w[e + 1] * Xb[(size_t)s_i[e + 1] * 128 + tid];
        a2 += s_w[e + 2] * Xb[(size_t)s_i[e + 2] * 128 + tid];
        a3 += s_w[e + 3] * Xb[(size_t)s_i[e + 3] * 128 + tid];
    }
    for (; e < cnt; e++) a0 += s_w[e] * Xb[(size_t)s_i[e] * 128 + tid];
    out[(size_t)row * 128 + tid] = (a0 + a1) + (a2 + a3);
}

// edge-wise comp cosine: swc holds raw m in, weight out
__global__ __launch_bounds__(256)
void dotc_k(const int* __restrict__ scnt, const int* __restrict__ sidx,
            float* __restrict__ swc, const float* __restrict__ comp,
            const float* __restrict__ nc)
{
    __shared__ float4 xp4[DDC / 4];
    __shared__ int s_i[PP];
    __shared__ float s_m[PP];
    int row = blockIdx.x, b = row >> 10, tid = threadIdx.x;
    int cnt = scnt[row];
    const int* ip = sidx + (size_t)row * PP;
    float* wp = swc + (size_t)row * PP;
    for (int i = tid; i < cnt; i += 256) { s_i[i] = ip[i]; s_m[i] = wp[i]; }
    const float4* cp4 = reinterpret_cast<const float4*>(comp + (size_t)row * DDC);
    for (int i = tid; i < DDC / 4; i += 256) xp4[i] = cp4[i];
    __syncthreads();
    float ncp = nc[row];
    int wid = tid >> 5, lane = tid & 31;
    for (int e = wid; e < cnt; e += 8) {
        int q = s_i[e];
        const float4* xq4 = reinterpret_cast<const float4*>(
            comp + ((size_t)(b << 10) + q) * DDC);
        float acc = 0.f;
#pragma unroll 4
        for (int i = lane; i < DDC / 4; i += 32) {
            float4 a = xp4[i], c = __ldg(xq4 + i);
            acc += a.x * c.x + a.y * c.y + a.z * c.z + a.w * c.w;
        }
#pragma unroll
        for (int o = 16; o; o >>= 1) acc += __shfl_xor_sync(0xffffffffu, acc, o);
        if (lane == 0) {
            float cv = acc / (ncp * nc[(b << 10) + q] + 1e-6f);
            wp[e] = fmaxf(cv * s_m[e], 0.f);
        }
    }
}

// direct L2 norms of comp rows
__global__ __launch_bounds__(256)
void ncdirect_k(const float* __restrict__ comp, float* __restrict__ nc)
{
    int row = blockIdx.x * 8 + (threadIdx.x >> 5);
    int lane = threadIdx.x & 31;
    const float4* r4 = reinterpret_cast<const float4*>(comp + (size_t)row * DDC);
    float acc = 0.f;
#pragma unroll 4
    for (int i = lane; i < DDC / 4; i += 32) {
        float4 a = __ldg(r4 + i);
        acc += a.x * a.x + a.y * a.y + a.z * a.z + a.w * a.w;
    }
#pragma unroll
    for (int o = 16; o; o >>= 1) acc += __shfl_xor_sync(0xffffffffu, acc, o);
    if (lane == 0) nc[row] = sqrtf(acc);
}

// parallel constant head row for comp: cbc[c] = hb[c] + dot(c_b2, Wh[:,c])
__global__ __launch_bounds__(256)
void cbias2p_k(const float* __restrict__ b2,
               const float* __restrict__ wc, const float* __restrict__ bc,
               const float* __restrict__ wr, const float* __restrict__ br,
               float* __restrict__ cb)
{
    __shared__ float ws[8];
    int c = blockIdx.x;
    int tid = threadIdx.x;
    float acc = 0.f;
    if (c < 20) {
        for (int k = tid; k < DDC; k += 256) acc += b2[k] * wc[k * 20 + c];
    } else if (c < 60) {
        int c2 = c - 20;
        for (int k = tid; k < DDC; k += 256) acc += b2[k] * wr[k * 40 + c2];
    }
#pragma unroll
    for (int o = 16; o; o >>= 1) acc += __shfl_xor_sync(0xffffffffu, acc, o);
    if ((tid & 31) == 0) ws[tid >> 5] = acc;
    __syncthreads();
    if (tid == 0) {
        float v = 0.f;
        for (int i = 0; i < 8; i++) v += ws[i];
        if (c < 20) v += bc[c];
        else if (c < 60) v += br[c - 20];
        else v = 0.f;
        cb[c] = v;
    }
}

// ====================== elementwise kernels ======================
__global__ void split_k(const float* __restrict__ s, h16* __restrict__ h,
                        h16* __restrict__ l, size_t n4)
{
    for (size_t i = (size_t)blockIdx.x * blockDim.x + threadIdx.x; i < n4;
         i += (size_t)gridDim.x * blockDim.x) {
        float4 v = reinterpret_cast<const float4*>(s)[i];
        uint32_t h0, l0, h1, l1;
        split2(v.x, v.y, h0, l0);
        split2(v.z, v.w, h1, l1);
        reinterpret_cast<uint2*>(h)[i] = make_uint2(h0, h1);
        reinterpret_cast<uint2*>(l)[i] = make_uint2(l0, l1);
    }
}

__global__ void addn_k(const float* __restrict__ p, size_t n4, int nsl,
                       float* __restrict__ o)
{
    for (size_t i = (size_t)blockIdx.x * blockDim.x + threadIdx.x; i < n4;
         i += (size_t)gridDim.x * blockDim.x) {
        float4 a = reinterpret_cast<const float4*>(p)[i];
        for (int s = 1; s < nsl; s++) {
            float4 b = reinterpret_cast<const float4*>(p)[(size_t)s * n4 + i];
            a.x += b.x; a.y += b.y; a.z += b.z; a.w += b.w;
        }
        reinterpret_cast<float4*>(o)[i] = a;
    }
}

__global__ void rednsplit_k(const float* __restrict__ p, size_t n4, int nsl,
                            h16* __restrict__ h, h16* __restrict__ l)
{
    for (size_t i = (size_t)blockIdx.x * blockDim.x + threadIdx.x; i < n4;
         i += (size_t)gridDim.x * blockDim.x) {
        float4 a = reinterpret_cast<const float4*>(p)[i];
        for (int s = 1; s < nsl; s++) {
            float4 b = reinterpret_cast<const float4*>(p)[(size_t)s * n4 + i];
            a.x += b.x; a.y += b.y; a.z += b.z; a.w += b.w;
        }
        uint32_t h0, l0, h1, l1;
        split2(a.x, a.y, h0, l0);
        split2(a.z, a.w, h1, l1);
        reinterpret_cast<uint2*>(h)[i] = make_uint2(h0, h1);
        reinterpret_cast<uint2*>(l)[i] = make_uint2(l0, l1);
    }
}

__global__ void zero_k(uint4* __restrict__ p, size_t n16)
{
    for (size_t i = (size_t)blockIdx.x * blockDim.x + threadIdx.x; i < n16;
         i += (size_t)gridDim.x * blockDim.x)
        p[i] = make_uint4(0, 0, 0, 0);
}

__global__ void padsplit_k(const float* __restrict__ src, h16* __restrict__ h,
                           h16* __restrict__ l, int K, int Nsrc, int col0)
{
    int total = K * Nsrc;
    for (int i = blockIdx.x * blockDim.x + threadIdx.x; i < total;
         i += gridDim.x * blockDim.x) {
        int k = i / Nsrc, n = i - k * Nsrc;
        unsigned short hq, lq;
        split1(src[i], hq, lq);
        size_t d = (size_t)k * 128 + col0 + n;
        reinterpret_cast<unsigned short*>(h)[d] = hq;
        reinterpret_cast<unsigned short*>(l)[d] = lq;
    }
}

__global__ void norms_k(const float* __restrict__ G, float* __restrict__ nrm)
{
    int i = blockIdx.x * blockDim.x + threadIdx.x;
    if (i < BQ * PP) {
        int b = i >> 10, p = i & (PP - 1);
        nrm[i] = sqrtf(G[((size_t)b * PP + p) * PP + p]);
    }
}

__global__ __launch_bounds__(256)
void mirror1_k(float* __restrict__ A)
{
    int tj = blockIdx.x, ti = blockIdx.y, b = blockIdx.z;
    if (ti <= tj || (ti >> 2) == (tj >> 2)) return;
    __shared__ float ta[32][33];
    int tx = threadIdx.x & 31, ty = threadIdx.x >> 5;
    size_t base = (size_t)b * PP * PP;
#pragma unroll
    for (int it = 0; it < 4; it++) {
        int r = ty + it * 8;
        ta[r][tx] = A[base + (size_t)(tj * 32 + r) * PP + ti * 32 + tx];
    }
    __syncthreads();
#pragma unroll
    for (int it = 0; it < 4; it++) {
        int r = ty + it * 8;
        A[base + (size_t)(ti * 32 + r) * PP + tj * 32 + tx] = ta[tx][r];
    }
}

__global__ void outasm_k(const float* __restrict__ spc,
                         const float* __restrict__ hp1, const float* __restrict__ hp2,
                         const float* __restrict__ fab, const float* __restrict__ cbc,
                         float* __restrict__ out)
{
    int i = blockIdx.x * blockDim.x + threadIdx.x;
    int total = BQ * PP * 81;
    if (i >= total) return;
    int row = i / 81, col = i - row * 81;
    float v;
    if (col < 21) {
        v = fab[col];
#pragma unroll
        for (int s = 0; s < 8; s++)
            v += hp1[((size_t)s * BQ * PP + row) * 128 + col];
    } else {
        int c2 = col - 21;
        v = cbc[c2] + spc[(size_t)row * 128 + c2];
#pragma unroll
        for (int s = 0; s < 8; s++)
            v += hp2[((size_t)s * BQ * PP + row) * 128 + c2];
    }
    out[i] = v;
}

// ---------------- graph construction ----------------
__device__ __forceinline__ void warp_argmin(float& v, int& l)
{
#pragma unroll
    for (int off = 16; off; off >>= 1) {
        float ov = __shfl_down_sync(0xffffffffu, v, off);
        int ol = __shfl_down_sync(0xffffffffu, l, off);
        if (ov < v) { v = ov; l = ol; }
    }
    v = __shfl_sync(0xffffffffu, v, 0);
    l = __shfl_sync(0xffffffffu, l, 0);
}
__device__ __forceinline__ void warp_argmax(float& v, int& l)
{
#pragma unroll
    for (int off = 16; off; off >>= 1) {
        float ov = __shfl_down_sync(0xffffffffu, v, off);
        int ol = __shfl_down_sync(0xffffffffu, l, off);
        if (ov > v) { v = ov; l = ol; }
    }
    v = __shfl_sync(0xffffffffu, v, 0);
    l = __shfl_sync(0xffffffffu, l, 0);
}

__global__ __launch_bounds__(128)
void build_adj_k(const float* __restrict__ iou, const float* __restrict__ dis,
                 const float* __restrict__ acos_, const float* __restrict__ na,
                 const int* __restrict__ props,
                 int* __restrict__ sidx, float* __restrict__ swa,
                 float* __restrict__ swm, int* __restrict__ scnt)
{
    __shared__ float sio[4][PP];
    int warp = threadIdx.x >> 5, lane = threadIdx.x & 31;
    int row = blockIdx.x * 4 + warp;
    if (row >= BQ * PP) return;
    int b = row >> 10;
    int p = row & (PP - 1);
    const float* iour = iou + (size_t)row * PP;
    const float* disr = dis + (size_t)row * PP;
    const float* ar = acos_ + (size_t)row * PP;
    const float* nab = na + (b << 10);
    float npa = nab[p];
    int pn = props[b];
    bool pv = p < pn;

    float* io_s = sio[warp];
    for (int q = lane; q < PP; q += 32) io_s[q] = iour[q];
    __syncwarp();

    float dv[6]; int di[6];
#pragma unroll
    for (int j = 0; j < 6; j++) { dv[j] = 3.0e38f; di[j] = -1; }
    float sv[2] = {-3.0e38f, -3.0e38f};
    int si2[2] = {-1, -1};

    for (int q = lane; q < PP; q += 32) {
        float io = io_s[q];
        bool ip = io > 0.0f;
        bool qv = q < pn;
        bool v2 = pv && qv;

        float dm = v2 ? (ip ? 2.0f : disr[q]) : 1.0e9f;
        if (dm < dv[5]) {
            dv[5] = dm; di[5] = q;
#pragma unroll
            for (int j = 5; j > 0; j--) {
                if (dv[j] < dv[j - 1]) {
                    float tv = dv[j]; dv[j] = dv[j - 1]; dv[j - 1] = tv;
                    int ti = di[j]; di[j] = di[j - 1]; di[j - 1] = ti;
                }
            }
        }
        float av = ar[q] / (npa * nab[q] + 1e-6f);
        float sm = v2 ? (ip ? 0.0f : (av - (q == p ? 1.0f : 0.0f))) : -1.0e9f;
        if (sm > sv[1]) {
            if (sm > sv[0]) { sv[1] = sv[0]; si2[1] = si2[0]; sv[0] = sm; si2[0] = q; }
            else            { sv[1] = sm; si2[1] = q; }
        }
    }

    int sel[8];
    {
        int ptr = 0;
        for (int k = 0; k < 6; k++) {
            float cv = (ptr < 6) ? dv[ptr] : 3.0e38f;
            int ci = (ptr < 6) ? di[ptr] : -1;
            float v = cv; int l = lane;
            warp_argmin(v, l);
            sel[k] = __shfl_sync(0xffffffffu, ci, l);
            if (lane == l) ptr++;
        }
    }
    {
        int ptr = 0;
        for (int k = 0; k < 2; k++) {
            float cv = (ptr < 2) ? sv[ptr] : -3.0e38f;
            int ci = (ptr < 2) ? si2[ptr] : -1;
            float v = cv; int l = lane;
            warp_argmax(v, l);
            sel[6 + k] = __shfl_sync(0xffffffffu, ci, l);
            if (lane == l) ptr++;
        }
    }
#pragma unroll
    for (int k = 0; k < 8; k++) {
        int q = sel[k];
        bool ok = (q >= 0) && pv && (q < pn) && !(io_s[q] > 0.0f);
        sel[k] = ok ? q : -1;
    }

    unsigned mbits = 0;
    for (int i = 0; i < 32; i++) {
        int q = lane + 32 * i;
        float io = io_s[q];
        bool bit = (q != p) && (io > 0.7f);
#pragma unroll
        for (int k = 0; k < 8; k++) bit |= (sel[k] == q);
        mbits |= (bit ? 1u : 0u) << i;
    }
    int cnt = __popc(mbits);
#pragma unroll
    for (int off = 16; off; off >>= 1) cnt += __shfl_xor_sync(0xffffffffu, cnt, off);
    float inv = 1.0f / ((float)cnt + 1e-6f);

    int* rI = sidx + (size_t)row * PP;
    float* rA = swa + (size_t)row * PP;
    float* rM = swm + (size_t)row * PP;
    int base = 0;
    for (int i = 0; i < 32; i++) {
        int q = lane + 32 * i;
        float m = ((mbits >> i) & 1u) ? inv : 0.0f;
        if (q == p) m += 1.0f;
        bool en = m > 0.f;
        unsigned bal = __ballot_sync(0xffffffffu, en);
        if (en) {
            int pos = base + __popc(bal & ((1u << lane) - 1u));
            float av = ar[q] / (npa * nab[q] + 1e-6f);
            rI[pos] = q;
            rA[pos] = fmaxf(av * m, 0.f);
            rM[pos] = m;
        }
        base += __popc(bal);
    }
    if (lane == 0) scnt[row] = base;
}

// ---------------- host ----------------
static void gx(int tbk, int terms,
               const h16* Ah, const h16* Al, const h16* Bh, const h16* Bl,
               float* C, h16* Ch, h16* Cl,
               int M, int N, int K, int Klen, int symm,
               long sA, long sB, long sC, int batch,
               const float* bias, const float* resid, long sR,
               int ldc, int relu)
{
    int nxt = N >> 7;
    int gxd = Klen ? nxt * (K / Klen) : nxt;
    dim3 grid(gxd, M / 128, batch);
    if (tbk == 1 && terms == 3) {
        cudaFuncSetAttribute(gemmx_k<1,3>, cudaFuncAttributeMaxDynamicSharedMemorySize, GSMEM);
        gemmx_k<1,3><<<grid, 256, GSMEM>>>(Ah, Al, Bh, Bl, C, Ch, Cl, N, K, Klen, symm,
                                           sA, sB, sC, bias, resid, sR, ldc, relu);
    } else if (tbk == 0 && terms == 2) {
        cudaFuncSetAttribute(gemmx_k<0,2>, cudaFuncAttributeMaxDynamicSharedMemorySize, GSMEM);
        gemmx_k<0,2><<<grid, 256, GSMEM>>>(Ah, Al, Bh, Bl, C, Ch, Cl, N, K, Klen, symm,
                                           sA, sB, sC, bias, resid, sR, ldc, relu);
    } else {
        cudaFuncSetAttribute(gemmx_k<0,3>, cudaFuncAttributeMaxDynamicSharedMemorySize, GSMEM);
        gemmx_k<0,3><<<grid, 256, GSMEM>>>(Ah, Al, Bh, Bl, C, Ch, Cl, N, K, Klen, symm,
                                           sA, sB, sC, bias, resid, sR, ldc, relu);
    }
}

#define SYM(var, sym) cudaGetSymbolAddress((void**)&var, sym)

extern "C" void kernel_launch(void* const* d_in, const int* in_sizes, int n_in,
                              void* d_out, int out_size)
{
    const float* act   = (const float*)d_in[0];
    const float* comp  = (const float*)d_in[1];
    const float* iou   = (const float*)d_in[2];
    const float* dis   = (const float*)d_in[3];
    const int*   props = (const int*)d_in[4];
    const float* a_w1  = (const float*)d_in[5];
    const float* a_b1  = (const float*)d_in[6];
    const float* a_w2  = (const float*)d_in[7];
    const float* a_b2  = (const float*)d_in[8];
    const float* c_w1  = (const float*)d_in[9];
    const float* c_b1  = (const float*)d_in[10];
    const float* c_w2  = (const float*)d_in[11];
    const float* c_b2  = (const float*)d_in[12];
    const float* fa_w  = (const float*)d_in[13];
    const float* fa_b  = (const float*)d_in[14];
    const float* fc_w  = (const float*)d_in[15];
    const float* fc_b  = (const float*)d_in[16];
    const float* fr_w  = (const float*)d_in[17];
    const float* fr_b  = (const float*)d_in[18];
    float* out = (float*)d_out;

    float *acos_, *na, *nc, *hp1, *hp2, *kp, *t1f, *t3f, *spc, *cbc, *swa, *swc;
    h16 *ah, *al, *ch_, *cl_, *t2h, *t2l, *ofah, *ofal;
    h16 *w1ah, *w1al, *w2ah, *w2al, *w1ch, *w1cl, *w2ch, *w2cl;
    h16 *wp1h, *wp1l, *wp2h, *wp2l, *s2h, *s2l;
    int *sidx, *scnt;
    SYM(acos_, g_acos); SYM(na, g_na); SYM(nc, g_nc);
    SYM(ah, g_ah); SYM(al, g_al); SYM(ch_, g_ch); SYM(cl_, g_cl);
    SYM(t2h, g_t2h); SYM(t2l, g_t2l);
    SYM(ofah, g_ofah); SYM(ofal, g_ofal);
    SYM(w1ah, g_w1ah); SYM(w1al, g_w1al); SYM(w2ah, g_w2ah); SYM(w2al, g_w2al);
    SYM(w1ch, g_w1ch); SYM(w1cl, g_w1cl); SYM(w2ch, g_w2ch); SYM(w2cl, g_w2cl);
    SYM(wp1h, g_wp1h); SYM(wp1l, g_wp1l); SYM(wp2h, g_wp2h); SYM(wp2l, g_wp2l);
    SYM(s2h, g_s2h); SYM(s2l, g_s2l);
    SYM(hp1, g_hp1); SYM(hp2, g_hp2); SYM(kp, g_kp);
    SYM(t1f, g_t1f); SYM(t3f, g_t3f); SYM(spc, g_spc); SYM(cbc, g_cbc);
    SYM(sidx, g_sidx); SYM(swa, g_swa); SYM(swc, g_swc); SYM(scnt, g_scnt);

    // 1-5: splits; 6: gram act (ncu -s 5 -c 1 target)
    split_k<<<1024, 256>>>(act, ah, al, (size_t)BQ * PP * DDA / 4);
    split_k<<<2048, 256>>>(comp, ch_, cl_, (size_t)BQ * PP * DDC / 4);
    split_k<<<256, 256>>>(a_w1, w1ah, w1al, (size_t)DDA * HID / 4);
    split_k<<<256, 256>>>(a_w2, w2ah, w2al, (size_t)HID * DDA / 4);
    split_k<<<512, 256>>>(c_w1, w1ch, w1cl, (size_t)DDC * HID / 4);
    gx(1, 3, ah, al, ah, al, acos_, 0, 0, PP, PP, DDA, 0, 1,
       (long)PP * DDA, (long)PP * DDA, (long)PP * PP, BQ, 0, 0, 0, PP, 0);

    split_k<<<512, 256>>>(c_w2, w2ch, w2cl, (size_t)HID * DDC / 4);
    zero_k<<<64, 256>>>((uint4*)wp1h, (size_t)DDA * 128 * 2 / 16);
    zero_k<<<64, 256>>>((uint4*)wp1l, (size_t)DDA * 128 * 2 / 16);
    zero_k<<<128, 256>>>((uint4*)wp2h, (size_t)DDC * 128 * 2 / 16);
    zero_k<<<128, 256>>>((uint4*)wp2l, (size_t)DDC * 128 * 2 / 16);
    padsplit_k<<<128, 256>>>(fa_w, wp1h, wp1l, DDA, 21, 0);
    padsplit_k<<<256, 256>>>(fc_w, wp2h, wp2l, DDC, 20, 0);
    padsplit_k<<<512, 256>>>(fr_w, wp2h, wp2l, DDC, 40, 20);

    // S2 = w2c @ Wh2 [512x128]; K=3072, 16 slices of 192
    gx(0, 3, w2ch, w2cl, wp2h, wp2l, kp, 0, 0, HID, 128, DDC, 192, 0,
       0, 0, (long)HID * 128, 1, 0, 0, 0, 128, 0);
    rednsplit_k<<<64, 256>>>(kp, (size_t)HID * 128 / 4, 16, s2h, s2l);
    cbias2p_k<<<128, 256>>>(c_b2, fc_w, fc_b, fr_w, fr_b, cbc);

    // norms + mirror + graph (comp cos via sparse fp32 dots)
    norms_k<<<(BQ * PP + 255) / 256, 256>>>(acos_, na);
    ncdirect_k<<<BQ * PP / 8, 256>>>(comp, nc);
    mirror1_k<<<dim3(32, 32, BQ), 256>>>(acos_);
    build_adj_k<<<BQ * PP / 4, 128>>>(iou, dis, acos_, na, props,
                                      sidx, swa, swc, scnt);
    dotc_k<<<BQ * PP, 256>>>(scnt, sidx, swc, comp, nc);

    // ---- Act chain (R12 layout) ----
    gx(0, 2, ah, al, w1ah, w1al, kp, 0, 0, BQ * PP, HID, DDA, 512, 0,
       0, 0, (long)BQ * PP * HID, 1, 0, 0, 0, HID, 0);
    addn_k<<<2048, 256>>>(kp, (size_t)BQ * PP * HID / 4, 2, t1f);
    spmm_k<2><<<BQ * PP, 256>>>(scnt, sidx, swa, t1f, a_b1, 0, t2h, t2l, 1);
    gx(0, 2, t2h, t2l, w2ah, w2al, t3f, 0, 0, BQ * PP, DDA, HID, 0, 0,
       0, 0, 0, 1, 0, 0, 0, DDA, 0);
    spmm_k<4><<<BQ * PP, 256>>>(scnt, sidx, swa, t3f, a_b2, act, ofah, ofal, 0);
    gx(0, 2, ofah, ofal, wp1h, wp1l, hp1, 0, 0, BQ * PP, 128, DDA, 128, 0,
       0, 0, (long)BQ * PP * 128, 1, 0, 0, 0, 128, 0);

    // ---- Comp chain (head-associated) ----
    gx(0, 2, ch_, cl_, w1ch, w1cl, kp, 0, 0, BQ * PP, HID, DDC, 1536, 0,
       0, 0, (long)BQ * PP * HID, 1, 0, 0, 0, HID, 0);
    addn_k<<<2048, 256>>>(kp, (size_t)BQ * PP * HID / 4, 2, t1f);
    spmm_k<2><<<BQ * PP, 256>>>(scnt, sidx, swc, t1f, c_b1, 0, t2h, t2l, 1);
    gx(0, 3, t2h, t2l, s2h, s2l, kp, 0, 0, BQ * PP, 128, HID, 128, 0,
       0, 0, (long)BQ * PP * 128, 1, 0, 0, 0, 128, 0);
    addn_k<<<1024, 256>>>(kp, (size_t)BQ * PP * 128 / 4, 4, t1f);
    spmms_k<<<BQ * PP, 128>>>(scnt, sidx, swc, t1f, spc);
    gx(0, 2, ch_, cl_, wp2h, wp2l, hp2, 0, 0, BQ * PP, 128, DDC, 384, 0,
       0, 0, (long)BQ * PP * 128, 1, 0, 0, 0, 128, 0);

    // final assembly
    outasm_k<<<(BQ * PP * 81 + 255) / 256, 256>>>(spc, hp1, hp2, fa_b, cbc, out);
}

// round 15
// speedup vs baseline: 1.5215x; 1.0241x over previous
#include <cuda_runtime.h>
#include <cuda_fp16.h>
#include <math.h>
#include <stdint.h>

#define BQ 4
#define PP 1024
#define DDA 1024
#define DDC 3072
#define HID 512
typedef __half h16;

// ---------------- scratch ----------------
__device__ float g_acos[(size_t)BQ*PP*PP];
__device__ float g_na[BQ*PP];
__device__ float g_nc[BQ*PP];
__device__ h16 g_ah[(size_t)BQ*PP*DDA], g_al[(size_t)BQ*PP*DDA];
__device__ h16 g_ch[(size_t)BQ*PP*DDC], g_cl[(size_t)BQ*PP*DDC];
__device__ h16 g_t2h[(size_t)BQ*PP*HID], g_t2l[(size_t)BQ*PP*HID];
__device__ h16 g_w1ah[DDA*HID], g_w1al[DDA*HID];
__device__ h16 g_w2ah[HID*DDA], g_w2al[HID*DDA];
__device__ h16 g_w1ch[DDC*HID], g_w1cl[DDC*HID];
__device__ h16 g_w2ch[HID*DDC], g_w2cl[HID*DDC];
__device__ h16 g_wp1h[DDA*128], g_wp1l[DDA*128];
__device__ h16 g_wp2h[DDC*128], g_wp2l[DDC*128];
__device__ h16 g_s1h[HID*128], g_s1l[HID*128];
__device__ h16 g_s2h[HID*128], g_s2l[HID*128];
__device__ float g_hp1[(size_t)8*BQ*PP*128];
__device__ float g_hp2[(size_t)8*BQ*PP*128];
__device__ float g_kp[(size_t)2*BQ*PP*HID];
__device__ float g_t1f[(size_t)BQ*PP*HID];
__device__ float g_spa[(size_t)BQ*PP*128];
__device__ float g_spc[(size_t)BQ*PP*128];
__device__ float g_cba[128], g_cbc[128];
__device__ int   g_sidx[(size_t)BQ*PP*PP];
__device__ float g_swa[(size_t)BQ*PP*PP];
__device__ float g_swc[(size_t)BQ*PP*PP];
__device__ int   g_scnt[BQ*PP];

// ====================== helpers ======================
__device__ __forceinline__ uint32_t smem_u32(const void* p) {
    uint32_t a;
    asm("{ .reg .u64 t; cvta.to.shared.u64 t, %1; cvt.u32.u64 %0, t; }" : "=r"(a) : "l"(p));
    return a;
}
__device__ __forceinline__ void split2(float x, float y, uint32_t& h, uint32_t& l) {
    __half hx = __float2half_rn(x), hy = __float2half_rn(y);
    float rx = x - __half2float(hx), ry = y - __half2float(hy);
    __half lx = __float2half_rn(rx), ly = __float2half_rn(ry);
    h = (uint32_t)__half_as_ushort(hx) | ((uint32_t)__half_as_ushort(hy) << 16);
    l = (uint32_t)__half_as_ushort(lx) | ((uint32_t)__half_as_ushort(ly) << 16);
}
__device__ __forceinline__ void split1(float x, unsigned short& h, unsigned short& l) {
    __half hx = __float2half_rn(x);
    float rx = x - __half2float(hx);
    h = __half_as_ushort(hx);
    l = __half_as_ushort(__float2half_rn(rx));
}
__device__ __forceinline__ void ldmx4(uint32_t* r, uint32_t addr) {
    asm volatile("ldmatrix.sync.aligned.m8n8.x4.shared.b16 {%0,%1,%2,%3}, [%4];"
                 : "=r"(r[0]), "=r"(r[1]), "=r"(r[2]), "=r"(r[3]) : "r"(addr));
}
__device__ __forceinline__ void ldmx4t(uint32_t* r, uint32_t addr) {
    asm volatile("ldmatrix.sync.aligned.m8n8.x4.trans.shared.b16 {%0,%1,%2,%3}, [%4];"
                 : "=r"(r[0]), "=r"(r[1]), "=r"(r[2]), "=r"(r[3]) : "r"(addr));
}
__device__ __forceinline__ void mma_f16(float* c, const uint32_t* a, const uint32_t* b) {
    asm volatile(
        "mma.sync.aligned.m16n8k16.row.col.f32.f16.f16.f32 "
        "{%0,%1,%2,%3}, {%4,%5,%6,%7}, {%8,%9}, {%0,%1,%2,%3};"
        : "+f"(c[0]), "+f"(c[1]), "+f"(c[2]), "+f"(c[3])
        : "r"(a[0]), "r"(a[1]), "r"(a[2]), "r"(a[3]), "r"(b[0]), "r"(b[1]));
}
__device__ __forceinline__ void cp16(uint32_t dst, const void* src) {
    asm volatile("cp.async.cg.shared.global [%0], [%1], 16;" :: "r"(dst), "l"(src) : "memory");
}
#define CP_COMMIT() asm volatile("cp.async.commit_group;" ::: "memory")

__device__ __forceinline__ uint32_t ksw(int row, int c) {
    return (uint32_t)(row * 64) + ((uint32_t)(c ^ ((row >> 1) & 3)) << 4);
}

// ====================== fp16 pair GEMM ======================
#define ATILE 8192
#define ASTG  16384
#define SBYTES 32768
#define NSTAGE 3
#define GSMEM (NSTAGE*SBYTES)

template<int TBK, int TERMS>
__global__ __launch_bounds__(256, 2)
void gemmx_k(const h16* __restrict__ Ah, const h16* __restrict__ Al,
             const h16* __restrict__ Bh, const h16* __restrict__ Bl,
             float* __restrict__ C, h16* __restrict__ Ch, h16* __restrict__ Cl,
             int N, int K, int Klen, int symm,
             long sA, long sB, long sC,
             const float* __restrict__ bias,
             const float* __restrict__ resid, long sR,
             int ldc, int relu_flag)
{
    if (!Klen && symm && blockIdx.x < blockIdx.y) return;
    extern __shared__ char sm[];
    uint32_t smb = smem_u32(sm);

    const int tid = threadIdx.x;
    const int lane = tid & 31;
    const int wid = tid >> 5;
    const int wm = (wid >> 2) * 64;
    const int wn = (wid & 3) * 32;

    long bz = blockIdx.z;
    const int bm = blockIdx.y * 128;
    const int nxt = N >> 7;
    int bn, kbase, kslice = 0;
    if (Klen) {
        kslice = (int)blockIdx.x / nxt;
        bn = ((int)blockIdx.x - kslice * nxt) << 7;
        kbase = kslice * Klen;
    } else {
        bn = (int)blockIdx.x << 7;
        kbase = 0;
    }
    const int KL = Klen ? Klen : K;

    const h16* Ahb = Ah + bz * sA + (size_t)bm * K + kbase;
    const h16* Alb = Al + bz * sA + (size_t)bm * K + kbase;
    const h16* Bhb = TBK ? (Bh + bz * sB + (size_t)bn * K + kbase)
                         : (Bh + bz * sB + (size_t)kbase * N + bn);
    const h16* Blb = TBK ? (Bl + bz * sB + (size_t)bn * K + kbase)
                         : (Bl + bz * sB + (size_t)kbase * N + bn);
    float* Cb = C ? (Klen ? C + (size_t)kslice * sC : C + bz * sC) : (float*)0;
    h16* Chb = Ch ? Ch + bz * sC : (h16*)0;
    h16* Clb = Cl ? Cl + bz * sC : (h16*)0;
    const float* Rb = resid ? resid + bz * sR : (const float*)0;

    float acc[4][4][4];
#pragma unroll
    for (int i = 0; i < 4; i++)
#pragma unroll
        for (int j = 0; j < 4; j++)
#pragma unroll
            for (int r = 0; r < 4; r++) acc[i][j][r] = 0.f;

    const int nch = KL >> 5;

    auto load_stage = [&](int kt, int s) {
        uint32_t base = smb + (uint32_t)s * SBYTES;
        int k0 = kt << 5;
#pragma unroll
        for (int it = 0; it < 4; it++) {
            int id = it * 256 + tid;
            int hl = id >> 9, rid = id & 511;
            int row = rid >> 2, c = rid & 3;
            if (TERMS >= 3 || hl == 0)
                cp16(base + hl * ATILE + ksw(row, c),
                     (hl ? Alb : Ahb) + (size_t)row * K + k0 + c * 8);
        }
        if (TBK) {
#pragma unroll
            for (int it = 0; it < 4; it++) {
                int id = it * 256 + tid;
                int hl = id >> 9, rid = id & 511;
                int row = rid >> 2, c = rid & 3;
                cp16(base + ASTG + hl * ATILE + ksw(row, c),
                     (hl ? Blb : Bhb) + (size_t)row * K + k0 + c * 8);
            }
        } else {
#pragma unroll
            for (int it = 0; it < 4; it++) {
                int id = it * 256 + tid;
                int hl = id >> 9, rid = id & 511;
                int k = rid >> 4, c = rid & 15;
                cp16(base + ASTG + hl * ATILE + k * 256 + ((c ^ (k & 7)) << 4),
                     (hl ? Blb : Bhb) + (size_t)(k0 + k) * N + c * 8);
            }
        }
        CP_COMMIT();
    };

    load_stage(0, 0);
    load_stage(1, 1);

    int sc = 0, sl = 2;
    for (int kt = 0; kt < nch; kt++) {
        asm volatile("cp.async.wait_group 1;" ::: "memory");
        __syncthreads();
        if (kt + 2 < nch) {
            load_stage(kt + 2, sl);
            sl = (sl + 1 == NSTAGE) ? 0 : sl + 1;
        } else {
            CP_COMMIT();
        }
        uint32_t aB = smb + (uint32_t)sc * SBYTES;
        uint32_t bB = aB + ASTG;
        sc = (sc + 1 == NSTAGE) ? 0 : sc + 1;

#pragma unroll
        for (int kh = 0; kh < 2; kh++) {
            uint32_t ahi[4][4], alo[4][4];
            {
                int u = kh * 2 + (lane >> 4);
#pragma unroll
                for (int i = 0; i < 4; i++) {
                    int r = wm + (lane & 15) + i * 16;
                    uint32_t ro = ksw(r, u);
                    ldmx4(ahi[i], aB + ro);
                    if (TERMS >= 3) ldmx4(alo[i], aB + ATILE + ro);
                }
            }
#pragma unroll
            for (int jp = 0; jp < 2; jp++) {
                uint32_t bh2[4], bl2[4];
                if (TBK) {
                    int row = wn + jp * 16 + ((lane >> 4) << 3) + (lane & 7);
                    int u = kh * 2 + ((lane >> 3) & 1);
                    uint32_t ro = ksw(row, u);
                    ldmx4(bh2, bB + ro);
                    ldmx4(bl2, bB + ATILE + ro);
                } else {
                    int k = kh * 16 + ((lane >> 3) & 1) * 8 + (lane & 7);
                    uint32_t kro = (uint32_t)k << 8;
                    int colblk = (wn >> 3) + 2 * jp + (lane >> 4);
                    uint32_t ad = kro + ((uint32_t)(colblk ^ (k & 7)) << 4);
                    ldmx4t(bh2, bB + ad);
                    ldmx4t(bl2, bB + ATILE + ad);
                }
                int j0 = 2 * jp, j1 = 2 * jp + 1;
#pragma unroll
                for (int i = 0; i < 4; i++) {
                    mma_f16(acc[i][j0], ahi[i], bh2 + 0);
                    mma_f16(acc[i][j1], ahi[i], bh2 + 2);
                }
#pragma unroll
                for (int i = 0; i < 4; i++) {
                    mma_f16(acc[i][j0], ahi[i], bl2 + 0);
                    mma_f16(acc[i][j1], ahi[i], bl2 + 2);
                }
                if (TERMS >= 3) {
#pragma unroll
                    for (int i = 0; i < 4; i++) {
                        mma_f16(acc[i][j0], alo[i], bh2 + 0);
                        mma_f16(acc[i][j1], alo[i], bh2 + 2);
                    }
                }
            }
        }
    }

#pragma unroll
    for (int i = 0; i < 4; i++) {
        int r0 = bm + wm + i * 16 + (lane >> 2);
        int r1 = r0 + 8;
#pragma unroll
        for (int j = 0; j < 4; j++) {
            int gc = bn + wn + j * 8 + (lane & 3) * 2;
            float2 v0 = make_float2(acc[i][j][0], acc[i][j][1]);
            float2 v1 = make_float2(acc[i][j][2], acc[i][j][3]);
            if (bias) {
                float2 bv = *reinterpret_cast<const float2*>(bias + gc);
                v0.x += bv.x; v0.y += bv.y;
                v1.x += bv.x; v1.y += bv.y;
            }
            if (Rb) {
                float2 q0 = *reinterpret_cast<const float2*>(Rb + (size_t)r0 * ldc + gc);
                float2 q1 = *reinterpret_cast<const float2*>(Rb + (size_t)r1 * ldc + gc);
                v0.x += q0.x; v0.y += q0.y;
                v1.x += q1.x; v1.y += q1.y;
            }
            if (relu_flag) {
                v0.x = fmaxf(v0.x, 0.f); v0.y = fmaxf(v0.y, 0.f);
                v1.x = fmaxf(v1.x, 0.f); v1.y = fmaxf(v1.y, 0.f);
            }
            if (Cb) {
                *reinterpret_cast<float2*>(Cb + (size_t)r0 * ldc + gc) = v0;
                *reinterpret_cast<float2*>(Cb + (size_t)r1 * ldc + gc) = v1;
            }
            if (Chb) {
                uint32_t h0, l0, h1, l1;
                split2(v0.x, v0.y, h0, l0);
                split2(v1.x, v1.y, h1, l1);
                *reinterpret_cast<uint32_t*>(Chb + (size_t)r0 * ldc + gc) = h0;
                *reinterpret_cast<uint32_t*>(Clb + (size_t)r0 * ldc + gc) = l0;
                *reinterpret_cast<uint32_t*>(Chb + (size_t)r1 * ldc + gc) = h1;
                *reinterpret_cast<uint32_t*>(Clb + (size_t)r1 * ldc + gc) = l1;
            }
        }
    }
}

// ====================== wide SpMM (fp16 pair out) ======================
template<int NPT>
__global__ __launch_bounds__(256)
void spmm_k(const int* __restrict__ scnt, const int* __restrict__ sidx,
            const float* __restrict__ swgt, const float* __restrict__ X,
            const float* __restrict__ bias,
            h16* __restrict__ outH, h16* __restrict__ outL, int relu_flag)
{
    constexpr int W = NPT * 256;
    __shared__ int s_i[PP];
    __shared__ float s_w[PP];
    int row = blockIdx.x;
    int b = row >> 10;
    int tid = threadIdx.x;
    int cnt = scnt[row];
    const int* ip = sidx + (size_t)row * PP;
    const float* wp = swgt + (size_t)row * PP;
    for (int i = tid; i < cnt; i += 256) { s_i[i] = ip[i]; s_w[i] = wp[i]; }
    __syncthreads();
    const float* Xb = X + (((size_t)b << 10) * W);
    float a0[NPT], a1[NPT], a2[NPT], a3[NPT];
#pragma unroll
    for (int r = 0; r < NPT; r++) { a0[r] = a1[r] = a2[r] = a3[r] = 0.f; }
    int e = 0;
    for (; e + 4 <= cnt; e += 4) {
        const float* x0 = Xb + (size_t)s_i[e + 0] * W;
        const float* x1 = Xb + (size_t)s_i[e + 1] * W;
        const float* x2 = Xb + (size_t)s_i[e + 2] * W;
        const float* x3 = Xb + (size_t)s_i[e + 3] * W;
        float w0 = s_w[e], w1 = s_w[e + 1], w2 = s_w[e + 2], w3 = s_w[e + 3];
#pragma unroll
        for (int r = 0; r < NPT; r++) {
            int c = r * 256 + tid;
            a0[r] += w0 * x0[c];
            a1[r] += w1 * x1[c];
            a2[r] += w2 * x2[c];
            a3[r] += w3 * x3[c];
        }
    }
    for (; e < cnt; e++) {
        const float* x0 = Xb + (size_t)s_i[e] * W;
        float w0 = s_w[e];
#pragma unroll
        for (int r = 0; r < NPT; r++) a0[r] += w0 * x0[r * 256 + tid];
    }
    unsigned short* oh = reinterpret_cast<unsigned short*>(outH) + (size_t)row * W;
    unsigned short* ol = reinterpret_cast<unsigned short*>(outL) + (size_t)row * W;
#pragma unroll
    for (int r = 0; r < NPT; r++) {
        int c = r * 256 + tid;
        float v = (a0[r] + a1[r]) + (a2[r] + a3[r]);
        if (bias) v += bias[c];
        if (relu_flag) v = fmaxf(v, 0.f);
        unsigned short hq, lq;
        split1(v, hq, lq);
        oh[c] = hq;
        ol[c] = lq;
    }
}

// narrow SpMM: 128 cols, fp32 out
__global__ __launch_bounds__(128)
void spmms_k(const int* __restrict__ scnt, const int* __restrict__ sidx,
             const float* __restrict__ swgt, const float* __restrict__ X,
             float* __restrict__ out)
{
    __shared__ int s_i[PP];
    __shared__ float s_w[PP];
    int row = blockIdx.x;
    int b = row >> 10;
    int tid = threadIdx.x;
    int cnt = scnt[row];
    const int* ip = sidx + (size_t)row * PP;
    const float* wp = swgt + (size_t)row * PP;
    for (int i = tid; i < cnt; i += 128) { s_i[i] = ip[i]; s_w[i] = wp[i]; }
    __syncthreads();
    const float* Xb = X + (((size_t)b << 10) * 128);
    float a0 = 0.f, a1 = 0.f, a2 = 0.f, a3 = 0.f;
    int e = 0;
    for (; e + 4 <= cnt; e += 4) {
        a0 += s_w[e]     * Xb[(size_t)s_i[e]     * 128 + tid];
        a1 += s_w[e + 1] * Xb[(size_t)s_i[e + 1] * 128 + tid];
        a2 += s_w[e + 2] * Xb[(size_t)s_i[e + 2] * 128 + tid];
        a3 += s_w[e + 3] * Xb[(size_t)s_i[e + 3] * 128 + tid];
    }
    for (; e < cnt; e++) a0 += s_w[e] * Xb[(size_t)s_i[e] * 128 + tid];
    out[(size_t)row * 128 + tid] = (a0 + a1) + (a2 + a3);
}

// edge-wise comp cosine; own row fp32 in smem, gathered rows fp16-hi
__global__ __launch_bounds__(256)
void dotc_k(const int* __restrict__ scnt, const int* __restrict__ sidx,
            float* __restrict__ swc, const float* __restrict__ comp,
            const h16* __restrict__ ch, const float* __restrict__ nc)
{
    __shared__ float xp[DDC];
    __shared__ int s_i[PP];
    __shared__ float s_m[PP];
    int row = blockIdx.x, b = row >> 10, tid = threadIdx.x;
    int cnt = scnt[row];
    const int* ip = sidx + (size_t)row * PP;
    float* wp = swc + (size_t)row * PP;
    for (int i = tid; i < cnt; i += 256) { s_i[i] = ip[i]; s_m[i] = wp[i]; }
    {
        const float4* cp4 = reinterpret_cast<const float4*>(comp + (size_t)row * DDC);
        for (int i = tid; i < DDC / 4; i += 256) {
            float4 v = cp4[i];
            xp[i * 4 + 0] = v.x; xp[i * 4 + 1] = v.y;
            xp[i * 4 + 2] = v.z; xp[i * 4 + 3] = v.w;
        }
    }
    __syncthreads();
    float ncp = nc[row];
    int wid = tid >> 5, lane = tid & 31;
    for (int e = wid; e < cnt; e += 8) {
        int q = s_i[e];
        const uint4* xq = reinterpret_cast<const uint4*>(
            ch + ((size_t)(b << 10) + q) * DDC);
        float acc = 0.f;
#pragma unroll 2
        for (int i = lane; i < DDC / 8; i += 32) {
            uint4 u = __ldg(xq + i);
            float2 f0 = __half22float2(*reinterpret_cast<__half2*>(&u.x));
            float2 f1 = __half22float2(*reinterpret_cast<__half2*>(&u.y));
            float2 f2 = __half22float2(*reinterpret_cast<__half2*>(&u.z));
            float2 f3 = __half22float2(*reinterpret_cast<__half2*>(&u.w));
            int o = i * 8;
            acc += xp[o+0]*f0.x + xp[o+1]*f0.y + xp[o+2]*f1.x + xp[o+3]*f1.y
                 + xp[o+4]*f2.x + xp[o+5]*f2.y + xp[o+6]*f3.x + xp[o+7]*f3.y;
        }
#pragma unroll
        for (int o = 16; o; o >>= 1) acc += __shfl_xor_sync(0xffffffffu, acc, o);
        if (lane == 0) {
            float cv = acc / (ncp * nc[(b << 10) + q] + 1e-6f);
            wp[e] = fmaxf(cv * s_m[e], 0.f);
        }
    }
}

// direct L2 norms of comp rows
__global__ __launch_bounds__(256)
void ncdirect_k(const float* __restrict__ comp, float* __restrict__ nc)
{
    int row = blockIdx.x * 8 + (threadIdx.x >> 5);
    int lane = threadIdx.x & 31;
    const float4* r4 = reinterpret_cast<const float4*>(comp + (size_t)row * DDC);
    float acc = 0.f;
#pragma unroll 4
    for (int i = lane; i < DDC / 4; i += 32) {
        float4 a = __ldg(r4 + i);
        acc += a.x * a.x + a.y * a.y + a.z * a.z + a.w * a.w;
    }
#pragma unroll
    for (int o = 16; o; o >>= 1) acc += __shfl_xor_sync(0xffffffffu, acc, o);
    if (lane == 0) nc[row] = sqrtf(acc);
}

// parallel constant head rows
__global__ __launch_bounds__(256)
void cbias1p_k(const float* __restrict__ b2, const float* __restrict__ w,
               const float* __restrict__ bb, float* __restrict__ cb)
{
    __shared__ float ws[8];
    int c = blockIdx.x;
    int tid = threadIdx.x;
    float acc = 0.f;
    if (c < 21)
        for (int k = tid; k < DDA; k += 256) acc += b2[k] * w[k * 21 + c];
#pragma unroll
    for (int o = 16; o; o >>= 1) acc += __shfl_xor_sync(0xffffffffu, acc, o);
    if ((tid & 31) == 0) ws[tid >> 5] = acc;
    __syncthreads();
    if (tid == 0) {
        float v = 0.f;
        for (int i = 0; i < 8; i++) v += ws[i];
        cb[c] = (c < 21) ? v + bb[c] : 0.f;
    }
}

__global__ __launch_bounds__(256)
void cbias2p_k(const float* __restrict__ b2,
               const float* __restrict__ wc, const float* __restrict__ bc,
               const float* __restrict__ wr, const float* __restrict__ br,
               float* __restrict__ cb)
{
    __shared__ float ws[8];
    int c = blockIdx.x;
    int tid = threadIdx.x;
    float acc = 0.f;
    if (c < 20) {
        for (int k = tid; k < DDC; k += 256) acc += b2[k] * wc[k * 20 + c];
    } else if (c < 60) {
        int c2 = c - 20;
        for (int k = tid; k < DDC; k += 256) acc += b2[k] * wr[k * 40 + c2];
    }
#pragma unroll
    for (int o = 16; o; o >>= 1) acc += __shfl_xor_sync(0xffffffffu, acc, o);
    if ((tid & 31) == 0) ws[tid >> 5] = acc;
    __syncthreads();
    if (tid == 0) {
        float v = 0.f;
        for (int i = 0; i < 8; i++) v += ws[i];
        if (c < 20) v += bc[c];
        else if (c < 60) v += br[c - 20];
        else v = 0.f;
        cb[c] = v;
    }
}

// ====================== elementwise kernels ======================
__global__ void split_k(const float* __restrict__ s, h16* __restrict__ h,
                        h16* __restrict__ l, size_t n4)
{
    for (size_t i = (size_t)blockIdx.x * blockDim.x + threadIdx.x; i < n4;
         i += (size_t)gridDim.x * blockDim.x) {
        float4 v = reinterpret_cast<const float4*>(s)[i];
        uint32_t h0, l0, h1, l1;
        split2(v.x, v.y, h0, l0);
        split2(v.z, v.w, h1, l1);
        reinterpret_cast<uint2*>(h)[i] = make_uint2(h0, h1);
        reinterpret_cast<uint2*>(l)[i] = make_uint2(l0, l1);
    }
}

__global__ void addn_k(const float* __restrict__ p, size_t n4, int nsl,
                       float* __restrict__ o)
{
    for (size_t i = (size_t)blockIdx.x * blockDim.x + threadIdx.x; i < n4;
         i += (size_t)gridDim.x * blockDim.x) {
        float4 a = reinterpret_cast<const float4*>(p)[i];
        for (int s = 1; s < nsl; s++) {
            float4 b = reinterpret_cast<const float4*>(p)[(size_t)s * n4 + i];
            a.x += b.x; a.y += b.y; a.z += b.z; a.w += b.w;
        }
        reinterpret_cast<float4*>(o)[i] = a;
    }
}

__global__ void rednsplit_k(const float* __restrict__ p, size_t n4, int nsl,
                            h16* __restrict__ h, h16* __restrict__ l)
{
    for (size_t i = (size_t)blockIdx.x * blockDim.x + threadIdx.x; i < n4;
         i += (size_t)gridDim.x * blockDim.x) {
        float4 a = reinterpret_cast<const float4*>(p)[i];
        for (int s = 1; s < nsl; s++) {
            float4 b = reinterpret_cast<const float4*>(p)[(size_t)s * n4 + i];
            a.x += b.x; a.y += b.y; a.z += b.z; a.w += b.w;
        }
        uint32_t h0, l0, h1, l1;
        split2(a.x, a.y, h0, l0);
        split2(a.z, a.w, h1, l1);
        reinterpret_cast<uint2*>(h)[i] = make_uint2(h0, h1);
        reinterpret_cast<uint2*>(l)[i] = make_uint2(l0, l1);
    }
}

__global__ void zero_k(uint4* __restrict__ p, size_t n16)
{
    for (size_t i = (size_t)blockIdx.x * blockDim.x + threadIdx.x; i < n16;
         i += (size_t)gridDim.x * blockDim.x)
        p[i] = make_uint4(0, 0, 0, 0);
}

__global__ void padsplit_k(const float* __restrict__ src, h16* __restrict__ h,
                           h16* __restrict__ l, int K, int Nsrc, int col0)
{
    int total = K * Nsrc;
    for (int i = blockIdx.x * blockDim.x + threadIdx.x; i < total;
         i += gridDim.x * blockDim.x) {
        int k = i / Nsrc, n = i - k * Nsrc;
        unsigned short hq, lq;
        split1(src[i], hq, lq);
        size_t d = (size_t)k * 128 + col0 + n;
        reinterpret_cast<unsigned short*>(h)[d] = hq;
        reinterpret_cast<unsigned short*>(l)[d] = lq;
    }
}

__global__ void norms_k(const float* __restrict__ G, float* __restrict__ nrm)
{
    int i = blockIdx.x * blockDim.x + threadIdx.x;
    if (i < BQ * PP) {
        int b = i >> 10, p = i & (PP - 1);
        nrm[i] = sqrtf(G[((size_t)b * PP + p) * PP + p]);
    }
}

__global__ __launch_bounds__(256)
void mirror1_k(float* __restrict__ A)
{
    int tj = blockIdx.x, ti = blockIdx.y, b = blockIdx.z;
    if (ti <= tj || (ti >> 2) == (tj >> 2)) return;
    __shared__ float ta[32][33];
    int tx = threadIdx.x & 31, ty = threadIdx.x >> 5;
    size_t base = (size_t)b * PP * PP;
#pragma unroll
    for (int it = 0; it < 4; it++) {
        int r = ty + it * 8;
        ta[r][tx] = A[base + (size_t)(tj * 32 + r) * PP + ti * 32 + tx];
    }
    __syncthreads();
#pragma unroll
    for (int it = 0; it < 4; it++) {
        int r = ty + it * 8;
        A[base + (size_t)(ti * 32 + r) * PP + tj * 32 + tx] = ta[tx][r];
    }
}

__global__ void outasm_k(const float* __restrict__ spa, const float* __restrict__ spc,
                         const float* __restrict__ hp1, const float* __restrict__ hp2,
                         const float* __restrict__ cba, const float* __restrict__ cbc,
                         float* __restrict__ out)
{
    int i = blockIdx.x * blockDim.x + threadIdx.x;
    int total = BQ * PP * 81;
    if (i >= total) return;
    int row = i / 81, col = i - row * 81;
    float v;
    if (col < 21) {
        v = cba[col] + spa[(size_t)row * 128 + col];
#pragma unroll
        for (int s = 0; s < 8; s++)
            v += hp1[((size_t)s * BQ * PP + row) * 128 + col];
    } else {
        int c2 = col - 21;
        v = cbc[c2] + spc[(size_t)row * 128 + c2];
#pragma unroll
        for (int s = 0; s < 8; s++)
            v += hp2[((size_t)s * BQ * PP + row) * 128 + c2];
    }
    out[i] = v;
}

// ---------------- graph construction ----------------
__device__ __forceinline__ void warp_argmin(float& v, int& l)
{
#pragma unroll
    for (int off = 16; off; off >>= 1) {
        float ov = __shfl_down_sync(0xffffffffu, v, off);
        int ol = __shfl_down_sync(0xffffffffu, l, off);
        if (ov < v) { v = ov; l = ol; }
    }
    v = __shfl_sync(0xffffffffu, v, 0);
    l = __shfl_sync(0xffffffffu, l, 0);
}
__device__ __forceinline__ void warp_argmax(float& v, int& l)
{
#pragma unroll
    for (int off = 16; off; off >>= 1) {
        float ov = __shfl_down_sync(0xffffffffu, v, off);
        int ol = __shfl_down_sync(0xffffffffu, l, off);
        if (ov > v) { v = ov; l = ol; }
    }
    v = __shfl_sync(0xffffffffu, v, 0);
    l = __shfl_sync(0xffffffffu, l, 0);
}

__global__ __launch_bounds__(128)
void build_adj_k(const float* __restrict__ iou, const float* __restrict__ dis,
                 const float* __restrict__ acos_, const float* __restrict__ na,
                 const int* __restrict__ props,
                 int* __restrict__ sidx, float* __restrict__ swa,
                 float* __restrict__ swm, int* __restrict__ scnt)
{
    __shared__ float sio[4][PP];
    int warp = threadIdx.x >> 5, lane = threadIdx.x & 31;
    int row = blockIdx.x * 4 + warp;
    if (row >= BQ * PP) return;
    int b = row >> 10;
    int p = row & (PP - 1);
    const float* iour = iou + (size_t)row * PP;
    const float* disr = dis + (size_t)row * PP;
    const float* ar = acos_ + (size_t)row * PP;
    const float* nab = na + (b << 10);
    float npa = nab[p];
    int pn = props[b];
    bool pv = p < pn;

    float* io_s = sio[warp];
    for (int q = lane; q < PP; q += 32) io_s[q] = iour[q];
    __syncwarp();

    float dv[6]; int di[6];
#pragma unroll
    for (int j = 0; j < 6; j++) { dv[j] = 3.0e38f; di[j] = -1; }
    float sv[2] = {-3.0e38f, -3.0e38f};
    int si2[2] = {-1, -1};

    for (int q = lane; q < PP; q += 32) {
        float io = io_s[q];
        bool ip = io > 0.0f;
        bool qv = q < pn;
        bool v2 = pv && qv;

        float dm = v2 ? (ip ? 2.0f : disr[q]) : 1.0e9f;
        if (dm < dv[5]) {
            dv[5] = dm; di[5] = q;
#pragma unroll
            for (int j = 5; j > 0; j--) {
                if (dv[j] < dv[j - 1]) {
                    float tv = dv[j]; dv[j] = dv[j - 1]; dv[j - 1] = tv;
                    int ti = di[j]; di[j] = di[j - 1]; di[j - 1] = ti;
                }
            }
        }
        float av = ar[q] / (npa * nab[q] + 1e-6f);
        float sm = v2 ? (ip ? 0.0f : (av - (q == p ? 1.0f : 0.0f))) : -1.0e9f;
        if (sm > sv[1]) {
            if (sm > sv[0]) { sv[1] = sv[0]; si2[1] = si2[0]; sv[0] = sm; si2[0] = q; }
            else            { sv[1] = sm; si2[1] = q; }
        }
    }

    int sel[8];
    {
        int ptr = 0;
        for (int k = 0; k < 6; k++) {
            float cv = (ptr < 6) ? dv[ptr] : 3.0e38f;
            int ci = (ptr < 6) ? di[ptr] : -1;
            float v = cv; int l = lane;
            warp_argmin(v, l);
            sel[k] = __shfl_sync(0xffffffffu, ci, l);
            if (lane == l) ptr++;
        }
    }
    {
        int ptr = 0;
        for (int k = 0; k < 2; k++) {
            float cv = (ptr < 2) ? sv[ptr] : -3.0e38f;
            int ci = (ptr < 2) ? si2[ptr] : -1;
            float v = cv; int l = lane;
            warp_argmax(v, l);
            sel[6 + k] = __shfl_sync(0xffffffffu, ci, l);
            if (lane == l) ptr++;
        }
    }
#pragma unroll
    for (int k = 0; k < 8; k++) {
        int q = sel[k];
        bool ok = (q >= 0) && pv && (q < pn) && !(io_s[q] > 0.0f);
        sel[k] = ok ? q : -1;
    }

    unsigned mbits = 0;
    for (int i = 0; i < 32; i++) {
        int q = lane + 32 * i;
        float io = io_s[q];
        bool bit = (q != p) && (io > 0.7f);
#pragma unroll
        for (int k = 0; k < 8; k++) bit |= (sel[k] == q);
        mbits |= (bit ? 1u : 0u) << i;
    }
    int cnt = __popc(mbits);
#pragma unroll
    for (int off = 16; off; off >>= 1) cnt += __shfl_xor_sync(0xffffffffu, cnt, off);
    float inv = 1.0f / ((float)cnt + 1e-6f);

    int* rI = sidx + (size_t)row * PP;
    float* rA = swa + (size_t)row * PP;
    float* rM = swm + (size_t)row * PP;
    int base = 0;
    for (int i = 0; i < 32; i++) {
        int q = lane + 32 * i;
        float m = ((mbits >> i) & 1u) ? inv : 0.0f;
        if (q == p) m += 1.0f;
        bool en = m > 0.f;
        unsigned bal = __ballot_sync(0xffffffffu, en);
        if (en) {
            int pos = base + __popc(bal & ((1u << lane) - 1u));
            float av = ar[q] / (npa * nab[q] + 1e-6f);
            rI[pos] = q;
            rA[pos] = fmaxf(av * m, 0.f);
            rM[pos] = m;
        }
        base += __popc(bal);
    }
    if (lane == 0) scnt[row] = base;
}

// ---------------- host ----------------
static void gx(int tbk, int terms,
               const h16* Ah, const h16* Al, const h16* Bh, const h16* Bl,
               float* C, h16* Ch, h16* Cl,
               int M, int N, int K, int Klen, int symm,
               long sA, long sB, long sC, int batch,
               const float* bias, const float* resid, long sR,
               int ldc, int relu)
{
    int nxt = N >> 7;
    int gxd = Klen ? nxt * (K / Klen) : nxt;
    dim3 grid(gxd, M / 128, batch);
    if (tbk == 1 && terms == 3) {
        cudaFuncSetAttribute(gemmx_k<1,3>, cudaFuncAttributeMaxDynamicSharedMemorySize, GSMEM);
        gemmx_k<1,3><<<grid, 256, GSMEM>>>(Ah, Al, Bh, Bl, C, Ch, Cl, N, K, Klen, symm,
                                           sA, sB, sC, bias, resid, sR, ldc, relu);
    } else if (tbk == 0 && terms == 2) {
        cudaFuncSetAttribute(gemmx_k<0,2>, cudaFuncAttributeMaxDynamicSharedMemorySize, GSMEM);
        gemmx_k<0,2><<<grid, 256, GSMEM>>>(Ah, Al, Bh, Bl, C, Ch, Cl, N, K, Klen, symm,
                                           sA, sB, sC, bias, resid, sR, ldc, relu);
    } else {
        cudaFuncSetAttribute(gemmx_k<0,3>, cudaFuncAttributeMaxDynamicSharedMemorySize, GSMEM);
        gemmx_k<0,3><<<grid, 256, GSMEM>>>(Ah, Al, Bh, Bl, C, Ch, Cl, N, K, Klen, symm,
                                           sA, sB, sC, bias, resid, sR, ldc, relu);
    }
}

#define SYM(var, sym) cudaGetSymbolAddress((void**)&var, sym)

extern "C" void kernel_launch(void* const* d_in, const int* in_sizes, int n_in,
                              void* d_out, int out_size)
{
    const float* act   = (const float*)d_in[0];
    const float* comp  = (const float*)d_in[1];
    const float* iou   = (const float*)d_in[2];
    const float* dis   = (const float*)d_in[3];
    const int*   props = (const int*)d_in[4];
    const float* a_w1  = (const float*)d_in[5];
    const float* a_b1  = (const float*)d_in[6];
    const float* a_w2  = (const float*)d_in[7];
    const float* a_b2  = (const float*)d_in[8];
    const float* c_w1  = (const float*)d_in[9];
    const float* c_b1  = (const float*)d_in[10];
    const float* c_w2  = (const float*)d_in[11];
    const float* c_b2  = (const float*)d_in[12];
    const float* fa_w  = (const float*)d_in[13];
    const float* fa_b  = (const float*)d_in[14];
    const float* fc_w  = (const float*)d_in[15];
    const float* fc_b  = (const float*)d_in[16];
    const float* fr_w  = (const float*)d_in[17];
    const float* fr_b  = (const float*)d_in[18];
    float* out = (float*)d_out;

    float *acos_, *na, *nc, *hp1, *hp2, *kp, *t1f, *spa, *spc, *cba, *cbc;
    float *swa, *swc;
    h16 *ah, *al, *ch_, *cl_, *t2h, *t2l;
    h16 *w1ah, *w1al, *w2ah, *w2al, *w1ch, *w1cl, *w2ch, *w2cl;
    h16 *wp1h, *wp1l, *wp2h, *wp2l, *s1h, *s1l, *s2h, *s2l;
    int *sidx, *scnt;
    SYM(acos_, g_acos); SYM(na, g_na); SYM(nc, g_nc);
    SYM(ah, g_ah); SYM(al, g_al); SYM(ch_, g_ch); SYM(cl_, g_cl);
    SYM(t2h, g_t2h); SYM(t2l, g_t2l);
    SYM(w1ah, g_w1ah); SYM(w1al, g_w1al); SYM(w2ah, g_w2ah); SYM(w2al, g_w2al);
    SYM(w1ch, g_w1ch); SYM(w1cl, g_w1cl); SYM(w2ch, g_w2ch); SYM(w2cl, g_w2cl);
    SYM(wp1h, g_wp1h); SYM(wp1l, g_wp1l); SYM(wp2h, g_wp2h); SYM(wp2l, g_wp2l);
    SYM(s1h, g_s1h); SYM(s1l, g_s1l); SYM(s2h, g_s2h); SYM(s2l, g_s2l);
    SYM(hp1, g_hp1); SYM(hp2, g_hp2); SYM(kp, g_kp);
    SYM(t1f, g_t1f); SYM(spa, g_spa); SYM(spc, g_spc);
    SYM(cba, g_cba); SYM(cbc, g_cbc);
    SYM(sidx, g_sidx); SYM(swa, g_swa); SYM(swc, g_swc); SYM(scnt, g_scnt);

    // splits
    split_k<<<1024, 256>>>(act, ah, al, (size_t)BQ * PP * DDA / 4);
    split_k<<<2048, 256>>>(comp, ch_, cl_, (size_t)BQ * PP * DDC / 4);
    split_k<<<256, 256>>>(a_w1, w1ah, w1al, (size_t)DDA * HID / 4);
    split_k<<<256, 256>>>(a_w2, w2ah, w2al, (size_t)HID * DDA / 4);
    split_k<<<512, 256>>>(c_w1, w1ch, w1cl, (size_t)DDC * HID / 4);
    gx(1, 3, ah, al, ah, al, acos_, 0, 0, PP, PP, DDA, 0, 1,
       (long)PP * DDA, (long)PP * DDA, (long)PP * PP, BQ, 0, 0, 0, PP, 0);

    split_k<<<512, 256>>>(c_w2, w2ch, w2cl, (size_t)HID * DDC / 4);
    zero_k<<<64, 256>>>((uint4*)wp1h, (size_t)DDA * 128 * 2 / 16);
    zero_k<<<64, 256>>>((uint4*)wp1l, (size_t)DDA * 128 * 2 / 16);
    zero_k<<<128, 256>>>((uint4*)wp2h, (size_t)DDC * 128 * 2 / 16);
    zero_k<<<128, 256>>>((uint4*)wp2l, (size_t)DDC * 128 * 2 / 16);
    padsplit_k<<<128, 256>>>(fa_w, wp1h, wp1l, DDA, 21, 0);
    padsplit_k<<<256, 256>>>(fc_w, wp2h, wp2l, DDC, 20, 0);
    padsplit_k<<<512, 256>>>(fr_w, wp2h, wp2l, DDC, 40, 20);

    // S1 = w2a @ Wh1 [512x128]; K=1024, 8 slices of 128
    gx(0, 3, w2ah, w2al, wp1h, wp1l, kp, 0, 0, HID, 128, DDA, 128, 0,
       0, 0, (long)HID * 128, 1, 0, 0, 0, 128, 0);
    rednsplit_k<<<64, 256>>>(kp, (size_t)HID * 128 / 4, 8, s1h, s1l);
    // S2 = w2c @ Wh2 [512x128]; K=3072, 16 slices of 192
    gx(0, 3, w2ch, w2cl, wp2h, wp2l, kp, 0, 0, HID, 128, DDC, 192, 0,
       0, 0, (long)HID * 128, 1, 0, 0, 0, 128, 0);
    rednsplit_k<<<64, 256>>>(kp, (size_t)HID * 128 / 4, 16, s2h, s2l);
    cbias1p_k<<<128, 256>>>(a_b2, fa_w, fa_b, cba);
    cbias2p_k<<<128, 256>>>(c_b2, fc_w, fc_b, fr_w, fr_b, cbc);

    // norms + mirror + graph + edge dots
    norms_k<<<(BQ * PP + 255) / 256, 256>>>(acos_, na);
    ncdirect_k<<<BQ * PP / 8, 256>>>(comp, nc);
    mirror1_k<<<dim3(32, 32, BQ), 256>>>(acos_);
    build_adj_k<<<BQ * PP / 4, 128>>>(iou, dis, acos_, na, props,
                                      sidx, swa, swc, scnt);
    dotc_k<<<BQ * PP, 256>>>(scnt, sidx, swc, comp, ch_, nc);

    // ---- Act chain (head-associated) ----
    gx(0, 2, ah, al, w1ah, w1al, kp, 0, 0, BQ * PP, HID, DDA, 512, 0,
       0, 0, (long)BQ * PP * HID, 1, 0, 0, 0, HID, 0);
    addn_k<<<2048, 256>>>(kp, (size_t)BQ * PP * HID / 4, 2, t1f);
    spmm_k<2><<<BQ * PP, 256>>>(scnt, sidx, swa, t1f, a_b1, t2h, t2l, 1);
    gx(0, 3, t2h, t2l, s1h, s1l, kp, 0, 0, BQ * PP, 128, HID, 128, 0,
       0, 0, (long)BQ * PP * 128, 1, 0, 0, 0, 128, 0);
    addn_k<<<1024, 256>>>(kp, (size_t)BQ * PP * 128 / 4, 4, t1f);
    spmms_k<<<BQ * PP, 128>>>(scnt, sidx, swa, t1f, spa);
    gx(0, 2, ah, al, wp1h, wp1l, hp1, 0, 0, BQ * PP, 128, DDA, 128, 0,
       0, 0, (long)BQ * PP * 128, 1, 0, 0, 0, 128, 0);

    // ---- Comp chain (head-associated) ----
    gx(0, 2, ch_, cl_, w1ch, w1cl, kp, 0, 0, BQ * PP, HID, DDC, 1536, 0,
       0, 0, (long)BQ * PP * HID, 1, 0, 0, 0, HID, 0);
    addn_k<<<2048, 256>>>(kp, (size_t)BQ * PP * HID / 4, 2, t1f);
    spmm_k<2><<<BQ * PP, 256>>>(scnt, sidx, swc, t1f, c_b1, t2h, t2l, 1);
    gx(0, 3, t2h, t2l, s2h, s2l, kp, 0, 0, BQ * PP, 128, HID, 128, 0,
       0, 0, (long)BQ * PP * 128, 1, 0, 0, 0, 128, 0);
    addn_k<<<1024, 256>>>(kp, (size_t)BQ * PP * 128 / 4, 4, t1f);
    spmms_k<<<BQ * PP, 128>>>(scnt, sidx, swc, t1f, spc);
    gx(0, 2, ch_, cl_, wp2h, wp2l, hp2, 0, 0, BQ * PP, 128, DDC, 384, 0,
       0, 0, (long)BQ * PP * 128, 1, 0, 0, 0, 128, 0);

    // final assembly
    outasm_k<<<(BQ * PP * 81 + 255) / 256, 256>>>(spa, spc, hp1, hp2, cba, cbc, out);
}

// round 16
// speedup vs baseline: 1.6931x; 1.1128x over previous
#include <cuda_runtime.h>
#include <cuda_fp16.h>
#include <math.h>
#include <stdint.h>

#define BQ 4
#define PP 1024
#define DDA 1024
#define DDC 3072
#define HID 512
typedef __half h16;

// ---------------- scratch ----------------
__device__ float g_acos[(size_t)BQ*PP*PP];
__device__ float g_na[BQ*PP];
__device__ float g_nc[BQ*PP];
__device__ h16 g_ah[(size_t)BQ*PP*DDA], g_al[(size_t)BQ*PP*DDA];
__device__ h16 g_ch[(size_t)BQ*PP*DDC];
__device__ h16 g_t1h[(size_t)BQ*PP*HID], g_t1l[(size_t)BQ*PP*HID];
__device__ h16 g_t2h[(size_t)BQ*PP*HID], g_t2l[(size_t)BQ*PP*HID];
__device__ h16 g_w1ah[DDA*HID];
__device__ h16 g_w2ah[HID*DDA], g_w2al[HID*DDA];
__device__ h16 g_w1ch[DDC*HID];
__device__ h16 g_w2ch[HID*DDC], g_w2cl[HID*DDC];
__device__ h16 g_wp1h[DDA*128], g_wp1l[DDA*128];
__device__ h16 g_wp2h[DDC*128], g_wp2l[DDC*128];
__device__ h16 g_s1h[HID*128], g_s1l[HID*128];
__device__ h16 g_s2h[HID*128], g_s2l[HID*128];
__device__ float g_hp1[(size_t)8*BQ*PP*128];
__device__ float g_hp2[(size_t)8*BQ*PP*128];
__device__ float g_kp[(size_t)2*BQ*PP*HID];
__device__ float g_t1f[(size_t)BQ*PP*128];
__device__ float g_spa[(size_t)BQ*PP*128];
__device__ float g_spc[(size_t)BQ*PP*128];
__device__ float g_cba[128], g_cbc[128];
__device__ int   g_sidx[(size_t)BQ*PP*PP];
__device__ float g_swa[(size_t)BQ*PP*PP];
__device__ float g_swc[(size_t)BQ*PP*PP];
__device__ int   g_scnt[BQ*PP];

// ====================== helpers ======================
__device__ __forceinline__ uint32_t smem_u32(const void* p) {
    uint32_t a;
    asm("{ .reg .u64 t; cvta.to.shared.u64 t, %1; cvt.u32.u64 %0, t; }" : "=r"(a) : "l"(p));
    return a;
}
__device__ __forceinline__ void split2(float x, float y, uint32_t& h, uint32_t& l) {
    __half hx = __float2half_rn(x), hy = __float2half_rn(y);
    float rx = x - __half2float(hx), ry = y - __half2float(hy);
    __half lx = __float2half_rn(rx), ly = __float2half_rn(ry);
    h = (uint32_t)__half_as_ushort(hx) | ((uint32_t)__half_as_ushort(hy) << 16);
    l = (uint32_t)__half_as_ushort(lx) | ((uint32_t)__half_as_ushort(ly) << 16);
}
__device__ __forceinline__ void split1(float x, unsigned short& h, unsigned short& l) {
    __half hx = __float2half_rn(x);
    float rx = x - __half2float(hx);
    h = __half_as_ushort(hx);
    l = __half_as_ushort(__float2half_rn(rx));
}
__device__ __forceinline__ void ldmx4(uint32_t* r, uint32_t addr) {
    asm volatile("ldmatrix.sync.aligned.m8n8.x4.shared.b16 {%0,%1,%2,%3}, [%4];"
                 : "=r"(r[0]), "=r"(r[1]), "=r"(r[2]), "=r"(r[3]) : "r"(addr));
}
__device__ __forceinline__ void ldmx4t(uint32_t* r, uint32_t addr) {
    asm volatile("ldmatrix.sync.aligned.m8n8.x4.trans.shared.b16 {%0,%1,%2,%3}, [%4];"
                 : "=r"(r[0]), "=r"(r[1]), "=r"(r[2]), "=r"(r[3]) : "r"(addr));
}
__device__ __forceinline__ void mma_f16(float* c, const uint32_t* a, const uint32_t* b) {
    asm volatile(
        "mma.sync.aligned.m16n8k16.row.col.f32.f16.f16.f32 "
        "{%0,%1,%2,%3}, {%4,%5,%6,%7}, {%8,%9}, {%0,%1,%2,%3};"
        : "+f"(c[0]), "+f"(c[1]), "+f"(c[2]), "+f"(c[3])
        : "r"(a[0]), "r"(a[1]), "r"(a[2]), "r"(a[3]), "r"(b[0]), "r"(b[1]));
}
__device__ __forceinline__ void cp16(uint32_t dst, const void* src) {
    asm volatile("cp.async.cg.shared.global [%0], [%1], 16;" :: "r"(dst), "l"(src) : "memory");
}
#define CP_COMMIT() asm volatile("cp.async.commit_group;" ::: "memory")

__device__ __forceinline__ uint32_t ksw(int row, int c) {
    return (uint32_t)(row * 64) + ((uint32_t)(c ^ ((row >> 1) & 3)) << 4);
}

// ====================== fp16 pair GEMM (TERMS = 1/2/3) ======================
#define ATILE 8192
#define ASTG  16384
#define SBYTES 32768
#define NSTAGE 3
#define GSMEM (NSTAGE*SBYTES)

template<int TBK, int TERMS>
__global__ __launch_bounds__(256, 2)
void gemmx_k(const h16* __restrict__ Ah, const h16* __restrict__ Al,
             const h16* __restrict__ Bh, const h16* __restrict__ Bl,
             float* __restrict__ C, h16* __restrict__ Ch, h16* __restrict__ Cl,
             int N, int K, int Klen, int symm,
             long sA, long sB, long sC,
             const float* __restrict__ bias,
             const float* __restrict__ resid, long sR,
             int ldc, int relu_flag)
{
    if (!Klen && symm && blockIdx.x < blockIdx.y) return;
    extern __shared__ char sm[];
    uint32_t smb = smem_u32(sm);

    const int tid = threadIdx.x;
    const int lane = tid & 31;
    const int wid = tid >> 5;
    const int wm = (wid >> 2) * 64;
    const int wn = (wid & 3) * 32;

    long bz = blockIdx.z;
    const int bm = blockIdx.y * 128;
    const int nxt = N >> 7;
    int bn, kbase, kslice = 0;
    if (Klen) {
        kslice = (int)blockIdx.x / nxt;
        bn = ((int)blockIdx.x - kslice * nxt) << 7;
        kbase = kslice * Klen;
    } else {
        bn = (int)blockIdx.x << 7;
        kbase = 0;
    }
    const int KL = Klen ? Klen : K;

    const h16* Ahb = Ah + bz * sA + (size_t)bm * K + kbase;
    const h16* Alb = Al ? Al + bz * sA + (size_t)bm * K + kbase : (const h16*)0;
    const h16* Bhb = TBK ? (Bh + bz * sB + (size_t)bn * K + kbase)
                         : (Bh + bz * sB + (size_t)kbase * N + bn);
    const h16* Blb = Bl ? (TBK ? (Bl + bz * sB + (size_t)bn * K + kbase)
                               : (Bl + bz * sB + (size_t)kbase * N + bn))
                        : (const h16*)0;
    float* Cb = C ? (Klen ? C + (size_t)kslice * sC : C + bz * sC) : (float*)0;
    h16* Chb = Ch ? Ch + bz * sC : (h16*)0;
    h16* Clb = Cl ? Cl + bz * sC : (h16*)0;
    const float* Rb = resid ? resid + bz * sR : (const float*)0;

    float acc[4][4][4];
#pragma unroll
    for (int i = 0; i < 4; i++)
#pragma unroll
        for (int j = 0; j < 4; j++)
#pragma unroll
            for (int r = 0; r < 4; r++) acc[i][j][r] = 0.f;

    const int nch = KL >> 5;

    auto load_stage = [&](int kt, int s) {
        uint32_t base = smb + (uint32_t)s * SBYTES;
        int k0 = kt << 5;
#pragma unroll
        for (int it = 0; it < 4; it++) {
            int id = it * 256 + tid;
            int hl = id >> 9, rid = id & 511;
            int row = rid >> 2, c = rid & 3;
            if (TERMS >= 3 || hl == 0)
                cp16(base + hl * ATILE + ksw(row, c),
                     (hl ? Alb : Ahb) + (size_t)row * K + k0 + c * 8);
        }
        if (TBK) {
#pragma unroll
            for (int it = 0; it < 4; it++) {
                int id = it * 256 + tid;
                int hl = id >> 9, rid = id & 511;
                int row = rid >> 2, c = rid & 3;
                if (TERMS >= 2 || hl == 0)
                    cp16(base + ASTG + hl * ATILE + ksw(row, c),
                         (hl ? Blb : Bhb) + (size_t)row * K + k0 + c * 8);
            }
        } else {
#pragma unroll
            for (int it = 0; it < 4; it++) {
                int id = it * 256 + tid;
                int hl = id >> 9, rid = id & 511;
                int k = rid >> 4, c = rid & 15;
                if (TERMS >= 2 || hl == 0)
                    cp16(base + ASTG + hl * ATILE + k * 256 + ((c ^ (k & 7)) << 4),
                         (hl ? Blb : Bhb) + (size_t)(k0 + k) * N + c * 8);
            }
        }
        CP_COMMIT();
    };

    load_stage(0, 0);
    load_stage(1, 1);

    int sc = 0, sl = 2;
    for (int kt = 0; kt < nch; kt++) {
        asm volatile("cp.async.wait_group 1;" ::: "memory");
        __syncthreads();
        if (kt + 2 < nch) {
            load_stage(kt + 2, sl);
            sl = (sl + 1 == NSTAGE) ? 0 : sl + 1;
        } else {
            CP_COMMIT();
        }
        uint32_t aB = smb + (uint32_t)sc * SBYTES;
        uint32_t bB = aB + ASTG;
        sc = (sc + 1 == NSTAGE) ? 0 : sc + 1;

#pragma unroll
        for (int kh = 0; kh < 2; kh++) {
            uint32_t ahi[4][4], alo[4][4];
            {
                int u = kh * 2 + (lane >> 4);
#pragma unroll
                for (int i = 0; i < 4; i++) {
                    int r = wm + (lane & 15) + i * 16;
                    uint32_t ro = ksw(r, u);
                    ldmx4(ahi[i], aB + ro);
                    if (TERMS >= 3) ldmx4(alo[i], aB + ATILE + ro);
                }
            }
#pragma unroll
            for (int jp = 0; jp < 2; jp++) {
                uint32_t bh2[4], bl2[4];
                if (TBK) {
                    int row = wn + jp * 16 + ((lane >> 4) << 3) + (lane & 7);
                    int u = kh * 2 + ((lane >> 3) & 1);
                    uint32_t ro = ksw(row, u);
                    ldmx4(bh2, bB + ro);
                    if (TERMS >= 2) ldmx4(bl2, bB + ATILE + ro);
                } else {
                    int k = kh * 16 + ((lane >> 3) & 1) * 8 + (lane & 7);
                    uint32_t kro = (uint32_t)k << 8;
                    int colblk = (wn >> 3) + 2 * jp + (lane >> 4);
                    uint32_t ad = kro + ((uint32_t)(colblk ^ (k & 7)) << 4);
                    ldmx4t(bh2, bB + ad);
                    if (TERMS >= 2) ldmx4t(bl2, bB + ATILE + ad);
                }
                int j0 = 2 * jp, j1 = 2 * jp + 1;
#pragma unroll
                for (int i = 0; i < 4; i++) {
                    mma_f16(acc[i][j0], ahi[i], bh2 + 0);
                    mma_f16(acc[i][j1], ahi[i], bh2 + 2);
                }
                if (TERMS >= 2) {
#pragma unroll
                    for (int i = 0; i < 4; i++) {
                        mma_f16(acc[i][j0], ahi[i], bl2 + 0);
                        mma_f16(acc[i][j1], ahi[i], bl2 + 2);
                    }
                }
                if (TERMS >= 3) {
#pragma unroll
                    for (int i = 0; i < 4; i++) {
                        mma_f16(acc[i][j0], alo[i], bh2 + 0);
                        mma_f16(acc[i][j1], alo[i], bh2 + 2);
                    }
                }
            }
        }
    }

#pragma unroll
    for (int i = 0; i < 4; i++) {
        int r0 = bm + wm + i * 16 + (lane >> 2);
        int r1 = r0 + 8;
#pragma unroll
        for (int j = 0; j < 4; j++) {
            int gc = bn + wn + j * 8 + (lane & 3) * 2;
            float2 v0 = make_float2(acc[i][j][0], acc[i][j][1]);
            float2 v1 = make_float2(acc[i][j][2], acc[i][j][3]);
            if (bias) {
                float2 bv = *reinterpret_cast<const float2*>(bias + gc);
                v0.x += bv.x; v0.y += bv.y;
                v1.x += bv.x; v1.y += bv.y;
            }
            if (Rb) {
                float2 q0 = *reinterpret_cast<const float2*>(Rb + (size_t)r0 * ldc + gc);
                float2 q1 = *reinterpret_cast<const float2*>(Rb + (size_t)r1 * ldc + gc);
                v0.x += q0.x; v0.y += q0.y;
                v1.x += q1.x; v1.y += q1.y;
            }
            if (relu_flag) {
                v0.x = fmaxf(v0.x, 0.f); v0.y = fmaxf(v0.y, 0.f);
                v1.x = fmaxf(v1.x, 0.f); v1.y = fmaxf(v1.y, 0.f);
            }
            if (Cb) {
                *reinterpret_cast<float2*>(Cb + (size_t)r0 * ldc + gc) = v0;
                *reinterpret_cast<float2*>(Cb + (size_t)r1 * ldc + gc) = v1;
            }
            if (Chb) {
                uint32_t h0, l0, h1, l1;
                split2(v0.x, v0.y, h0, l0);
                split2(v1.x, v1.y, h1, l1);
                *reinterpret_cast<uint32_t*>(Chb + (size_t)r0 * ldc + gc) = h0;
                *reinterpret_cast<uint32_t*>(Clb + (size_t)r0 * ldc + gc) = l0;
                *reinterpret_cast<uint32_t*>(Chb + (size_t)r1 * ldc + gc) = h1;
                *reinterpret_cast<uint32_t*>(Clb + (size_t)r1 * ldc + gc) = l1;
            }
        }
    }
}

// ====================== SpMM gathering fp16-hi, fp16 pair out ======================
template<int NPT>
__global__ __launch_bounds__(256)
void spmmh_k(const int* __restrict__ scnt, const int* __restrict__ sidx,
             const float* __restrict__ swgt, const h16* __restrict__ X,
             const float* __restrict__ bias,
             h16* __restrict__ outH, h16* __restrict__ outL, int relu_flag)
{
    constexpr int W = NPT * 256;
    __shared__ int s_i[PP];
    __shared__ float s_w[PP];
    int row = blockIdx.x;
    int b = row >> 10;
    int tid = threadIdx.x;
    int cnt = scnt[row];
    const int* ip = sidx + (size_t)row * PP;
    const float* wp = swgt + (size_t)row * PP;
    for (int i = tid; i < cnt; i += 256) { s_i[i] = ip[i]; s_w[i] = wp[i]; }
    __syncthreads();
    const unsigned short* Xb =
        reinterpret_cast<const unsigned short*>(X) + (((size_t)b << 10) * W);
    float a0[NPT], a1[NPT], a2[NPT], a3[NPT];
#pragma unroll
    for (int r = 0; r < NPT; r++) { a0[r] = a1[r] = a2[r] = a3[r] = 0.f; }
    int e = 0;
    for (; e + 4 <= cnt; e += 4) {
        const unsigned short* x0 = Xb + (size_t)s_i[e + 0] * W;
        const unsigned short* x1 = Xb + (size_t)s_i[e + 1] * W;
        const unsigned short* x2 = Xb + (size_t)s_i[e + 2] * W;
        const unsigned short* x3 = Xb + (size_t)s_i[e + 3] * W;
        float w0 = s_w[e], w1 = s_w[e + 1], w2 = s_w[e + 2], w3 = s_w[e + 3];
#pragma unroll
        for (int r = 0; r < NPT; r++) {
            int c = r * 256 + tid;
            a0[r] += w0 * __half2float(__ushort_as_half(x0[c]));
            a1[r] += w1 * __half2float(__ushort_as_half(x1[c]));
            a2[r] += w2 * __half2float(__ushort_as_half(x2[c]));
            a3[r] += w3 * __half2float(__ushort_as_half(x3[c]));
        }
    }
    for (; e < cnt; e++) {
        const unsigned short* x0 = Xb + (size_t)s_i[e] * W;
        float w0 = s_w[e];
#pragma unroll
        for (int r = 0; r < NPT; r++)
            a0[r] += w0 * __half2float(__ushort_as_half(x0[r * 256 + tid]));
    }
    unsigned short* oh = reinterpret_cast<unsigned short*>(outH) + (size_t)row * W;
    unsigned short* ol = reinterpret_cast<unsigned short*>(outL) + (size_t)row * W;
#pragma unroll
    for (int r = 0; r < NPT; r++) {
        int c = r * 256 + tid;
        float v = (a0[r] + a1[r]) + (a2[r] + a3[r]);
        if (bias) v += bias[c];
        if (relu_flag) v = fmaxf(v, 0.f);
        unsigned short hq, lq;
        split1(v, hq, lq);
        oh[c] = hq;
        ol[c] = lq;
    }
}

// narrow SpMM: 128 cols, fp32 in/out
__global__ __launch_bounds__(128)
void spmms_k(const int* __restrict__ scnt, const int* __restrict__ sidx,
             const float* __restrict__ swgt, const float* __restrict__ X,
             float* __restrict__ out)
{
    __shared__ int s_i[PP];
    __shared__ float s_w[PP];
    int row = blockIdx.x;
    int b = row >> 10;
    int tid = threadIdx.x;
    int cnt = scnt[row];
    const int* ip = sidx + (size_t)row * PP;
    const float* wp = swgt + (size_t)row * PP;
    for (int i = tid; i < cnt; i += 128) { s_i[i] = ip[i]; s_w[i] = wp[i]; }
    __syncthreads();
    const float* Xb = X + (((size_t)b << 10) * 128);
    float a0 = 0.f, a1 = 0.f, a2 = 0.f, a3 = 0.f;
    int e = 0;
    for (; e + 4 <= cnt; e += 4) {
        a0 += s_w[e]     * Xb[(size_t)s_i[e]     * 128 + tid];
        a1 += s_w[e + 1] * Xb[(size_t)s_i[e + 1] * 128 + tid];
        a2 += s_w[e + 2] * Xb[(size_t)s_i[e + 2] * 128 + tid];
        a3 += s_w[e + 3] * Xb[(size_t)s_i[e + 3] * 128 + tid];
    }
    for (; e < cnt; e++) a0 += s_w[e] * Xb[(size_t)s_i[e] * 128 + tid];
    out[(size_t)row * 128 + tid] = (a0 + a1) + (a2 + a3);
}

// edge-wise comp cosine; own row fp32 in smem, gathered rows fp16-hi
__global__ __launch_bounds__(256)
void dotc_k(const int* __restrict__ scnt, const int* __restrict__ sidx,
            float* __restrict__ swc, const float* __restrict__ comp,
            const h16* __restrict__ ch, const float* __restrict__ nc)
{
    __shared__ float xp[DDC];
    __shared__ int s_i[PP];
    __shared__ float s_m[PP];
    int row = blockIdx.x, b = row >> 10, tid = threadIdx.x;
    int cnt = scnt[row];
    const int* ip = sidx + (size_t)row * PP;
    float* wp = swc + (size_t)row * PP;
    for (int i = tid; i < cnt; i += 256) { s_i[i] = ip[i]; s_m[i] = wp[i]; }
    {
        const float4* cp4 = reinterpret_cast<const float4*>(comp + (size_t)row * DDC);
        for (int i = tid; i < DDC / 4; i += 256) {
            float4 v = cp4[i];
            xp[i * 4 + 0] = v.x; xp[i * 4 + 1] = v.y;
            xp[i * 4 + 2] = v.z; xp[i * 4 + 3] = v.w;
        }
    }
    __syncthreads();
    float ncp = nc[row];
    int wid = tid >> 5, lane = tid & 31;
    for (int e = wid; e < cnt; e += 8) {
        int q = s_i[e];
        const uint4* xq = reinterpret_cast<const uint4*>(
            ch + ((size_t)(b << 10) + q) * DDC);
        float acc = 0.f;
#pragma unroll 2
        for (int i = lane; i < DDC / 8; i += 32) {
            uint4 u = __ldg(xq + i);
            float2 f0 = __half22float2(*reinterpret_cast<__half2*>(&u.x));
            float2 f1 = __half22float2(*reinterpret_cast<__half2*>(&u.y));
            float2 f2 = __half22float2(*reinterpret_cast<__half2*>(&u.z));
            float2 f3 = __half22float2(*reinterpret_cast<__half2*>(&u.w));
            int o = i * 8;
            acc += xp[o+0]*f0.x + xp[o+1]*f0.y + xp[o+2]*f1.x + xp[o+3]*f1.y
                 + xp[o+4]*f2.x + xp[o+5]*f2.y + xp[o+6]*f3.x + xp[o+7]*f3.y;
        }
#pragma unroll
        for (int o = 16; o; o >>= 1) acc += __shfl_xor_sync(0xffffffffu, acc, o);
        if (lane == 0) {
            float cv = acc / (ncp * nc[(b << 10) + q] + 1e-6f);
            wp[e] = fmaxf(cv * s_m[e], 0.f);
        }
    }
}

__global__ __launch_bounds__(256)
void ncdirect_k(const float* __restrict__ comp, float* __restrict__ nc)
{
    int row = blockIdx.x * 8 + (threadIdx.x >> 5);
    int lane = threadIdx.x & 31;
    const float4* r4 = reinterpret_cast<const float4*>(comp + (size_t)row * DDC);
    float acc = 0.f;
#pragma unroll 4
    for (int i = lane; i < DDC / 4; i += 32) {
        float4 a = __ldg(r4 + i);
        acc += a.x * a.x + a.y * a.y + a.z * a.z + a.w * a.w;
    }
#pragma unroll
    for (int o = 16; o; o >>= 1) acc += __shfl_xor_sync(0xffffffffu, acc, o);
    if (lane == 0) nc[row] = sqrtf(acc);
}

// fused constant head rows: blocks 0..127 -> cba, 128..255 -> cbc
__global__ __launch_bounds__(256)
void cbias12_k(const float* __restrict__ ab2, const float* __restrict__ aw,
               const float* __restrict__ ab,
               const float* __restrict__ cb2,
               const float* __restrict__ wc, const float* __restrict__ bc,
               const float* __restrict__ wr, const float* __restrict__ br,
               float* __restrict__ cba, float* __restrict__ cbc)
{
    __shared__ float ws[8];
    int blk = blockIdx.x;
    int tid = threadIdx.x;
    float acc = 0.f;
    if (blk < 128) {
        int c = blk;
        if (c < 21)
            for (int k = tid; k < DDA; k += 256) acc += ab2[k] * aw[k * 21 + c];
    } else {
        int c = blk - 128;
        if (c < 20) {
            for (int k = tid; k < DDC; k += 256) acc += cb2[k] * wc[k * 20 + c];
        } else if (c < 60) {
            int c2 = c - 20;
            for (int k = tid; k < DDC; k += 256) acc += cb2[k] * wr[k * 40 + c2];
        }
    }
#pragma unroll
    for (int o = 16; o; o >>= 1) acc += __shfl_xor_sync(0xffffffffu, acc, o);
    if ((tid & 31) == 0) ws[tid >> 5] = acc;
    __syncthreads();
    if (tid == 0) {
        float v = 0.f;
        for (int i = 0; i < 8; i++) v += ws[i];
        if (blk < 128) {
            cba[blk] = (blk < 21) ? v + ab[blk] : 0.f;
        } else {
            int c = blk - 128;
            if (c < 20) v += bc[c];
            else if (c < 60) v += br[c - 20];
            else v = 0.f;
            cbc[c] = v;
        }
    }
}

// ====================== elementwise kernels ======================
__global__ void split_k(const float* __restrict__ s, h16* __restrict__ h,
                        h16* __restrict__ l, size_t n4)
{
    for (size_t i = (size_t)blockIdx.x * blockDim.x + threadIdx.x; i < n4;
         i += (size_t)gridDim.x * blockDim.x) {
        float4 v = reinterpret_cast<const float4*>(s)[i];
        uint32_t h0, l0, h1, l1;
        split2(v.x, v.y, h0, l0);
        split2(v.z, v.w, h1, l1);
        reinterpret_cast<uint2*>(h)[i] = make_uint2(h0, h1);
        reinterpret_cast<uint2*>(l)[i] = make_uint2(l0, l1);
    }
}

// hi-only split
__global__ void splith_k(const float* __restrict__ s, h16* __restrict__ h, size_t n4)
{
    for (size_t i = (size_t)blockIdx.x * blockDim.x + threadIdx.x; i < n4;
         i += (size_t)gridDim.x * blockDim.x) {
        float4 v = reinterpret_cast<const float4*>(s)[i];
        __half2 p0 = __floats2half2_rn(v.x, v.y);
        __half2 p1 = __floats2half2_rn(v.z, v.w);
        reinterpret_cast<uint2*>(h)[i] =
            make_uint2(*reinterpret_cast<uint32_t*>(&p0), *reinterpret_cast<uint32_t*>(&p1));
    }
}

__global__ void addn_k(const float* __restrict__ p, size_t n4, int nsl,
                       float* __restrict__ o)
{
    for (size_t i = (size_t)blockIdx.x * blockDim.x + threadIdx.x; i < n4;
         i += (size_t)gridDim.x * blockDim.x) {
        float4 a = reinterpret_cast<const float4*>(p)[i];
        for (int s = 1; s < nsl; s++) {
            float4 b = reinterpret_cast<const float4*>(p)[(size_t)s * n4 + i];
            a.x += b.x; a.y += b.y; a.z += b.z; a.w += b.w;
        }
        reinterpret_cast<float4*>(o)[i] = a;
    }
}

__global__ void rednsplit_k(const float* __restrict__ p, size_t n4, int nsl,
                            h16* __restrict__ h, h16* __restrict__ l)
{
    for (size_t i = (size_t)blockIdx.x * blockDim.x + threadIdx.x; i < n4;
         i += (size_t)gridDim.x * blockDim.x) {
        float4 a = reinterpret_cast<const float4*>(p)[i];
        for (int s = 1; s < nsl; s++) {
            float4 b = reinterpret_cast<const float4*>(p)[(size_t)s * n4 + i];
            a.x += b.x; a.y += b.y; a.z += b.z; a.w += b.w;
        }
        uint32_t h0, l0, h1, l1;
        split2(a.x, a.y, h0, l0);
        split2(a.z, a.w, h1, l1);
        reinterpret_cast<uint2*>(h)[i] = make_uint2(h0, h1);
        reinterpret_cast<uint2*>(l)[i] = make_uint2(l0, l1);
    }
}

// head panel with fused zero-fill: dst [K,128], cols [0,Ns1) from s1, [Ns1,Ns1+Ns2) from s2
__global__ void padsplitz_k(const float* __restrict__ s1, int Ns1,
                            const float* __restrict__ s2, int Ns2,
                            h16* __restrict__ h, h16* __restrict__ l, int K)
{
    int total = K * 128;
    for (int i = blockIdx.x * blockDim.x + threadIdx.x; i < total;
         i += gridDim.x * blockDim.x) {
        int k = i >> 7, n = i & 127;
        float v = 0.f;
        if (n < Ns1) v = s1[k * Ns1 + n];
        else if (s2 && n < Ns1 + Ns2) v = s2[k * Ns2 + (n - Ns1)];
        unsigned short hq, lq;
        split1(v, hq, lq);
        reinterpret_cast<unsigned short*>(h)[i] = hq;
        reinterpret_cast<unsigned short*>(l)[i] = lq;
    }
}

__global__ void norms_k(const float* __restrict__ G, float* __restrict__ nrm)
{
    int i = blockIdx.x * blockDim.x + threadIdx.x;
    if (i < BQ * PP) {
        int b = i >> 10, p = i & (PP - 1);
        nrm[i] = sqrtf(G[((size_t)b * PP + p) * PP + p]);
    }
}

__global__ __launch_bounds__(256)
void mirror1_k(float* __restrict__ A)
{
    int tj = blockIdx.x, ti = blockIdx.y, b = blockIdx.z;
    if (ti <= tj || (ti >> 2) == (tj >> 2)) return;
    __shared__ float ta[32][33];
    int tx = threadIdx.x & 31, ty = threadIdx.x >> 5;
    size_t base = (size_t)b * PP * PP;
#pragma unroll
    for (int it = 0; it < 4; it++) {
        int r = ty + it * 8;
        ta[r][tx] = A[base + (size_t)(tj * 32 + r) * PP + ti * 32 + tx];
    }
    __syncthreads();
#pragma unroll
    for (int it = 0; it < 4; it++) {
        int r = ty + it * 8;
        A[base + (size_t)(ti * 32 + r) * PP + tj * 32 + tx] = ta[tx][r];
    }
}

__global__ void outasm_k(const float* __restrict__ spa, const float* __restrict__ spc,
                         const float* __restrict__ hp1, const float* __restrict__ hp2,
                         const float* __restrict__ cba, const float* __restrict__ cbc,
                         float* __restrict__ out)
{
    int i = blockIdx.x * blockDim.x + threadIdx.x;
    int total = BQ * PP * 81;
    if (i >= total) return;
    int row = i / 81, col = i - row * 81;
    float v;
    if (col < 21) {
        v = cba[col] + spa[(size_t)row * 128 + col];
#pragma unroll
        for (int s = 0; s < 8; s++)
            v += hp1[((size_t)s * BQ * PP + row) * 128 + col];
    } else {
        int c2 = col - 21;
        v = cbc[c2] + spc[(size_t)row * 128 + c2];
#pragma unroll
        for (int s = 0; s < 8; s++)
            v += hp2[((size_t)s * BQ * PP + row) * 128 + c2];
    }
    out[i] = v;
}

// ---------------- graph construction ----------------
__device__ __forceinline__ void warp_argmin(float& v, int& l)
{
#pragma unroll
    for (int off = 16; off; off >>= 1) {
        float ov = __shfl_down_sync(0xffffffffu, v, off);
        int ol = __shfl_down_sync(0xffffffffu, l, off);
        if (ov < v) { v = ov; l = ol; }
    }
    v = __shfl_sync(0xffffffffu, v, 0);
    l = __shfl_sync(0xffffffffu, l, 0);
}
__device__ __forceinline__ void warp_argmax(float& v, int& l)
{
#pragma unroll
    for (int off = 16; off; off >>= 1) {
        float ov = __shfl_down_sync(0xffffffffu, v, off);
        int ol = __shfl_down_sync(0xffffffffu, l, off);
        if (ov > v) { v = ov; l = ol; }
    }
    v = __shfl_sync(0xffffffffu, v, 0);
    l = __shfl_sync(0xffffffffu, l, 0);
}

__global__ __launch_bounds__(128)
void build_adj_k(const float* __restrict__ iou, const float* __restrict__ dis,
                 const float* __restrict__ acos_, const float* __restrict__ na,
                 const int* __restrict__ props,
                 int* __restrict__ sidx, float* __restrict__ swa,
                 float* __restrict__ swm, int* __restrict__ scnt)
{
    __shared__ float sio[4][PP];
    int warp = threadIdx.x >> 5, lane = threadIdx.x & 31;
    int row = blockIdx.x * 4 + warp;
    if (row >= BQ * PP) return;
    int b = row >> 10;
    int p = row & (PP - 1);
    const float* iour = iou + (size_t)row * PP;
    const float* disr = dis + (size_t)row * PP;
    const float* ar = acos_ + (size_t)row * PP;
    const float* nab = na + (b << 10);
    float npa = nab[p];
    int pn = props[b];
    bool pv = p < pn;

    float* io_s = sio[warp];
    for (int q = lane; q < PP; q += 32) io_s[q] = iour[q];
    __syncwarp();

    float dv[6]; int di[6];
#pragma unroll
    for (int j = 0; j < 6; j++) { dv[j] = 3.0e38f; di[j] = -1; }
    float sv[2] = {-3.0e38f, -3.0e38f};
    int si2[2] = {-1, -1};

    for (int q = lane; q < PP; q += 32) {
        float io = io_s[q];
        bool ip = io > 0.0f;
        bool qv = q < pn;
        bool v2 = pv && qv;

        float dm = v2 ? (ip ? 2.0f : disr[q]) : 1.0e9f;
        if (dm < dv[5]) {
            dv[5] = dm; di[5] = q;
#pragma unroll
            for (int j = 5; j > 0; j--) {
                if (dv[j] < dv[j - 1]) {
                    float tv = dv[j]; dv[j] = dv[j - 1]; dv[j - 1] = tv;
                    int ti = di[j]; di[j] = di[j - 1]; di[j - 1] = ti;
                }
            }
        }
        float av = ar[q] / (npa * nab[q] + 1e-6f);
        float sm = v2 ? (ip ? 0.0f : (av - (q == p ? 1.0f : 0.0f))) : -1.0e9f;
        if (sm > sv[1]) {
            if (sm > sv[0]) { sv[1] = sv[0]; si2[1] = si2[0]; sv[0] = sm; si2[0] = q; }
            else            { sv[1] = sm; si2[1] = q; }
        }
    }

    int sel[8];
    {
        int ptr = 0;
        for (int k = 0; k < 6; k++) {
            float cv = (ptr < 6) ? dv[ptr] : 3.0e38f;
            int ci = (ptr < 6) ? di[ptr] : -1;
            float v = cv; int l = lane;
            warp_argmin(v, l);
            sel[k] = __shfl_sync(0xffffffffu, ci, l);
            if (lane == l) ptr++;
        }
    }
    {
        int ptr = 0;
        for (int k = 0; k < 2; k++) {
            float cv = (ptr < 2) ? sv[ptr] : -3.0e38f;
            int ci = (ptr < 2) ? si2[ptr] : -1;
            float v = cv; int l = lane;
            warp_argmax(v, l);
            sel[6 + k] = __shfl_sync(0xffffffffu, ci, l);
            if (lane == l) ptr++;
        }
    }
#pragma unroll
    for (int k = 0; k < 8; k++) {
        int q = sel[k];
        bool ok = (q >= 0) && pv && (q < pn) && !(io_s[q] > 0.0f);
        sel[k] = ok ? q : -1;
    }

    unsigned mbits = 0;
    for (int i = 0; i < 32; i++) {
        int q = lane + 32 * i;
        float io = io_s[q];
        bool bit = (q != p) && (io > 0.7f);
#pragma unroll
        for (int k = 0; k < 8; k++) bit |= (sel[k] == q);
        mbits |= (bit ? 1u : 0u) << i;
    }
    int cnt = __popc(mbits);
#pragma unroll
    for (int off = 16; off; off >>= 1) cnt += __shfl_xor_sync(0xffffffffu, cnt, off);
    float inv = 1.0f / ((float)cnt + 1e-6f);

    int* rI = sidx + (size_t)row * PP;
    float* rA = swa + (size_t)row * PP;
    float* rM = swm + (size_t)row * PP;
    int base = 0;
    for (int i = 0; i < 32; i++) {
        int q = lane + 32 * i;
        float m = ((mbits >> i) & 1u) ? inv : 0.0f;
        if (q == p) m += 1.0f;
        bool en = m > 0.f;
        unsigned bal = __ballot_sync(0xffffffffu, en);
        if (en) {
            int pos = base + __popc(bal & ((1u << lane) - 1u));
            float av = ar[q] / (npa * nab[q] + 1e-6f);
            rI[pos] = q;
            rA[pos] = fmaxf(av * m, 0.f);
            rM[pos] = m;
        }
        base += __popc(bal);
    }
    if (lane == 0) scnt[row] = base;
}

// ---------------- host ----------------
static void gx(int tbk, int terms,
               const h16* Ah, const h16* Al, const h16* Bh, const h16* Bl,
               float* C, h16* Ch, h16* Cl,
               int M, int N, int K, int Klen, int symm,
               long sA, long sB, long sC, int batch,
               const float* bias, const float* resid, long sR,
               int ldc, int relu)
{
    int nxt = N >> 7;
    int gxd = Klen ? nxt * (K / Klen) : nxt;
    dim3 grid(gxd, M / 128, batch);
    if (tbk == 1 && terms == 3) {
        cudaFuncSetAttribute(gemmx_k<1,3>, cudaFuncAttributeMaxDynamicSharedMemorySize, GSMEM);
        gemmx_k<1,3><<<grid, 256, GSMEM>>>(Ah, Al, Bh, Bl, C, Ch, Cl, N, K, Klen, symm,
                                           sA, sB, sC, bias, resid, sR, ldc, relu);
    } else if (tbk == 0 && terms == 1) {
        cudaFuncSetAttribute(gemmx_k<0,1>, cudaFuncAttributeMaxDynamicSharedMemorySize, GSMEM);
        gemmx_k<0,1><<<grid, 256, GSMEM>>>(Ah, Al, Bh, Bl, C, Ch, Cl, N, K, Klen, symm,
                                           sA, sB, sC, bias, resid, sR, ldc, relu);
    } else if (tbk == 0 && terms == 2) {
        cudaFuncSetAttribute(gemmx_k<0,2>, cudaFuncAttributeMaxDynamicSharedMemorySize, GSMEM);
        gemmx_k<0,2><<<grid, 256, GSMEM>>>(Ah, Al, Bh, Bl, C, Ch, Cl, N, K, Klen, symm,
                                           sA, sB, sC, bias, resid, sR, ldc, relu);
    } else {
        cudaFuncSetAttribute(gemmx_k<0,3>, cudaFuncAttributeMaxDynamicSharedMemorySize, GSMEM);
        gemmx_k<0,3><<<grid, 256, GSMEM>>>(Ah, Al, Bh, Bl, C, Ch, Cl, N, K, Klen, symm,
                                           sA, sB, sC, bias, resid, sR, ldc, relu);
    }
}

#define SYM(var, sym) cudaGetSymbolAddress((void**)&var, sym)

extern "C" void kernel_launch(void* const* d_in, const int* in_sizes, int n_in,
                              void* d_out, int out_size)
{
    const float* act   = (const float*)d_in[0];
    const float* comp  = (const float*)d_in[1];
    const float* iou   = (const float*)d_in[2];
    const float* dis   = (const float*)d_in[3];
    const int*   props = (const int*)d_in[4];
    const float* a_w1  = (const float*)d_in[5];
    const float* a_b1  = (const float*)d_in[6];
    const float* a_w2  = (const float*)d_in[7];
    const float* a_b2  = (const float*)d_in[8];
    const float* c_w1  = (const float*)d_in[9];
    const float* c_b1  = (const float*)d_in[10];
    const float* c_w2  = (const float*)d_in[11];
    const float* c_b2  = (const float*)d_in[12];
    const float* fa_w  = (const float*)d_in[13];
    const float* fa_b  = (const float*)d_in[14];
    const float* fc_w  = (const float*)d_in[15];
    const float* fc_b  = (const float*)d_in[16];
    const float* fr_w  = (const float*)d_in[17];
    const float* fr_b  = (const float*)d_in[18];
    float* out = (float*)d_out;

    float *acos_, *na, *nc, *hp1, *hp2, *kp, *t1f, *spa, *spc, *cba, *cbc;
    float *swa, *swc;
    h16 *ah, *al, *ch_, *t1h, *t1l, *t2h, *t2l;
    h16 *w1ah, *w2ah, *w2al, *w1ch, *w2ch, *w2cl;
    h16 *wp1h, *wp1l, *wp2h, *wp2l, *s1h, *s1l, *s2h, *s2l;
    int *sidx, *scnt;
    SYM(acos_, g_acos); SYM(na, g_na); SYM(nc, g_nc);
    SYM(ah, g_ah); SYM(al, g_al); SYM(ch_, g_ch);
    SYM(t1h, g_t1h); SYM(t1l, g_t1l); SYM(t2h, g_t2h); SYM(t2l, g_t2l);
    SYM(w1ah, g_w1ah); SYM(w2ah, g_w2ah); SYM(w2al, g_w2al);
    SYM(w1ch, g_w1ch); SYM(w2ch, g_w2ch); SYM(w2cl, g_w2cl);
    SYM(wp1h, g_wp1h); SYM(wp1l, g_wp1l); SYM(wp2h, g_wp2h); SYM(wp2l, g_wp2l);
    SYM(s1h, g_s1h); SYM(s1l, g_s1l); SYM(s2h, g_s2h); SYM(s2l, g_s2l);
    SYM(hp1, g_hp1); SYM(hp2, g_hp2); SYM(kp, g_kp);
    SYM(t1f, g_t1f); SYM(spa, g_spa); SYM(spc, g_spc);
    SYM(cba, g_cba); SYM(cbc, g_cbc);
    SYM(sidx, g_sidx); SYM(swa, g_swa); SYM(swc, g_swc); SYM(scnt, g_scnt);

    // splits (pair where needed, hi-only elsewhere)
    split_k<<<1024, 256>>>(act, ah, al, (size_t)BQ * PP * DDA / 4);
    splith_k<<<2048, 256>>>(comp, ch_, (size_t)BQ * PP * DDC / 4);
    splith_k<<<256, 256>>>(a_w1, w1ah, (size_t)DDA * HID / 4);
    split_k<<<256, 256>>>(a_w2, w2ah, w2al, (size_t)HID * DDA / 4);
    splith_k<<<512, 256>>>(c_w1, w1ch, (size_t)DDC * HID / 4);
    gx(1, 3, ah, al, ah, al, acos_, 0, 0, PP, PP, DDA, 0, 1,
       (long)PP * DDA, (long)PP * DDA, (long)PP * PP, BQ, 0, 0, 0, PP, 0);

    split_k<<<512, 256>>>(c_w2, w2ch, w2cl, (size_t)HID * DDC / 4);
    padsplitz_k<<<128, 256>>>(fa_w, 21, 0, 0, wp1h, wp1l, DDA);
    padsplitz_k<<<384, 256>>>(fc_w, 20, fr_w, 40, wp2h, wp2l, DDC);

    // S1 = w2a @ Wh1; K=1024, 8 slices of 128 (TERMS=3)
    gx(0, 3, w2ah, w2al, wp1h, wp1l, kp, 0, 0, HID, 128, DDA, 128, 0,
       0, 0, (long)HID * 128, 1, 0, 0, 0, 128, 0);
    rednsplit_k<<<64, 256>>>(kp, (size_t)HID * 128 / 4, 8, s1h, s1l);
    // S2 = w2c @ Wh2; K=3072, 16 slices of 192 (TERMS=3)
    gx(0, 3, w2ch, w2cl, wp2h, wp2l, kp, 0, 0, HID, 128, DDC, 192, 0,
       0, 0, (long)HID * 128, 1, 0, 0, 0, 128, 0);
    rednsplit_k<<<64, 256>>>(kp, (size_t)HID * 128 / 4, 16, s2h, s2l);
    cbias12_k<<<256, 256>>>(a_b2, fa_w, fa_b, c_b2, fc_w, fc_b, fr_w, fr_b, cba, cbc);

    // norms + mirror + graph + edge dots
    norms_k<<<(BQ * PP + 255) / 256, 256>>>(acos_, na);
    ncdirect_k<<<BQ * PP / 8, 256>>>(comp, nc);
    mirror1_k<<<dim3(32, 32, BQ), 256>>>(acos_);
    build_adj_k<<<BQ * PP / 4, 128>>>(iou, dis, acos_, na, props,
                                      sidx, swa, swc, scnt);
    dotc_k<<<BQ * PP, 256>>>(scnt, sidx, swc, comp, ch_, nc);

    // ---- Act chain ----
    // x@w1a: TERMS=1, no K-split (128 CTAs), write fp16 pair directly
    gx(0, 1, ah, 0, w1ah, 0, 0, t1h, t1l, BQ * PP, HID, DDA, 0, 0,
       0, 0, 0, 1, 0, 0, 0, HID, 0);
    spmmh_k<2><<<BQ * PP, 256>>>(scnt, sidx, swa, t1h, a_b1, t2h, t2l, 1);
    // t2@S1: TERMS=1, K=512, 4 slices of 128
    gx(0, 1, t2h, 0, s1h, 0, kp, 0, 0, BQ * PP, 128, HID, 128, 0,
       0, 0, (long)BQ * PP * 128, 1, 0, 0, 0, 128, 0);
    addn_k<<<1024, 256>>>(kp, (size_t)BQ * PP * 128 / 4, 4, t1f);
    spmms_k<<<BQ * PP, 128>>>(scnt, sidx, swa, t1f, spa);
    // act head: x@Wh1, TERMS=2, 8 K-slices of 128
    gx(0, 2, ah, 0, wp1h, wp1l, hp1, 0, 0, BQ * PP, 128, DDA, 128, 0,
       0, 0, (long)BQ * PP * 128, 1, 0, 0, 0, 128, 0);

    // ---- Comp chain ----
    // x@w1c: TERMS=1, K-split 2x1536 -> fp32 partials -> fp16 pair
    gx(0, 1, ch_, 0, w1ch, 0, kp, 0, 0, BQ * PP, HID, DDC, 1536, 0,
       0, 0, (long)BQ * PP * HID, 1, 0, 0, 0, HID, 0);
    rednsplit_k<<<2048, 256>>>(kp, (size_t)BQ * PP * HID / 4, 2, t1h, t1l);
    spmmh_k<2><<<BQ * PP, 256>>>(scnt, sidx, swc, t1h, c_b1, t2h, t2l, 1);
    // t2@S2: TERMS=1
    gx(0, 1, t2h, 0, s2h, 0, kp, 0, 0, BQ * PP, 128, HID, 128, 0,
       0, 0, (long)BQ * PP * 128, 1, 0, 0, 0, 128, 0);
    addn_k<<<1024, 256>>>(kp, (size_t)BQ * PP * 128 / 4, 4, t1f);
    spmms_k<<<BQ * PP, 128>>>(scnt, sidx, swc, t1f, spc);
    // comp head: x@Wh2, TERMS=2, 8 K-slices of 384
    gx(0, 2, ch_, 0, wp2h, wp2l, hp2, 0, 0, BQ * PP, 128, DDC, 384, 0,
       0, 0, (long)BQ * PP * 128, 1, 0, 0, 0, 128, 0);

    // final assembly
    outasm_k<<<(BQ * PP * 81 + 255) / 256, 256>>>(spa, spc, hp1, hp2, cba, cbc, out);
}

// round 17
// speedup vs baseline: 2.5337x; 1.4964x over previous
#include <cuda_runtime.h>
#include <cuda_fp16.h>
#include <math.h>
#include <stdint.h>

#define BQ 4
#define PP 1024
#define DDA 1024
#define DDC 3072
#define HID 512
typedef __half h16;

// ---------------- scratch ----------------
__device__ float g_acos[(size_t)BQ*PP*PP];
__device__ float g_na[BQ*PP];
__device__ float g_nc[BQ*PP];
__device__ h16 g_ah[(size_t)BQ*PP*DDA], g_al[(size_t)BQ*PP*DDA];
__device__ h16 g_ch[(size_t)BQ*PP*DDC];
__device__ h16 g_t1ah[(size_t)BQ*PP*HID], g_t1al[(size_t)BQ*PP*HID];
__device__ h16 g_t1ch[(size_t)BQ*PP*HID], g_t1cl[(size_t)BQ*PP*HID];
__device__ h16 g_t2ah[(size_t)BQ*PP*HID], g_t2al[(size_t)BQ*PP*HID];
__device__ h16 g_t2ch[(size_t)BQ*PP*HID], g_t2cl[(size_t)BQ*PP*HID];
__device__ h16 g_w1ah[DDA*HID];
__device__ h16 g_w2ah[HID*DDA], g_w2al[HID*DDA];
__device__ h16 g_w1ch[DDC*HID];
__device__ h16 g_w2ch[HID*DDC], g_w2cl[HID*DDC];
__device__ h16 g_wp1h[DDA*128], g_wp1l[DDA*128];
__device__ h16 g_wp2h[DDC*128], g_wp2l[DDC*128];
__device__ h16 g_s1h[HID*128], g_s1l[HID*128];
__device__ h16 g_s2h[HID*128], g_s2l[HID*128];
__device__ float g_hp1[(size_t)8*BQ*PP*128];
__device__ float g_hp2[(size_t)8*BQ*PP*128];
__device__ float g_kpc[(size_t)2*BQ*PP*HID];
__device__ float g_kps1[(size_t)8*HID*128];
__device__ float g_kps2[(size_t)16*HID*128];
__device__ float g_tfa[(size_t)BQ*PP*128];
__device__ float g_tfc[(size_t)BQ*PP*128];
__device__ float g_spa[(size_t)BQ*PP*128];
__device__ float g_spc[(size_t)BQ*PP*128];
__device__ float g_cba[128], g_cbc[128];
__device__ int   g_sidx[(size_t)BQ*PP*PP];
__device__ float g_swa[(size_t)BQ*PP*PP];
__device__ float g_swc[(size_t)BQ*PP*PP];
__device__ int   g_scnt[BQ*PP];

// ====================== helpers ======================
__device__ __forceinline__ uint32_t smem_u32(const void* p) {
    uint32_t a;
    asm("{ .reg .u64 t; cvta.to.shared.u64 t, %1; cvt.u32.u64 %0, t; }" : "=r"(a) : "l"(p));
    return a;
}
__device__ __forceinline__ void split2(float x, float y, uint32_t& h, uint32_t& l) {
    __half hx = __float2half_rn(x), hy = __float2half_rn(y);
    float rx = x - __half2float(hx), ry = y - __half2float(hy);
    __half lx = __float2half_rn(rx), ly = __float2half_rn(ry);
    h = (uint32_t)__half_as_ushort(hx) | ((uint32_t)__half_as_ushort(hy) << 16);
    l = (uint32_t)__half_as_ushort(lx) | ((uint32_t)__half_as_ushort(ly) << 16);
}
__device__ __forceinline__ void split1(float x, unsigned short& h, unsigned short& l) {
    __half hx = __float2half_rn(x);
    float rx = x - __half2float(hx);
    h = __half_as_ushort(hx);
    l = __half_as_ushort(__float2half_rn(rx));
}
__device__ __forceinline__ void ldmx4(uint32_t* r, uint32_t addr) {
    asm volatile("ldmatrix.sync.aligned.m8n8.x4.shared.b16 {%0,%1,%2,%3}, [%4];"
                 : "=r"(r[0]), "=r"(r[1]), "=r"(r[2]), "=r"(r[3]) : "r"(addr));
}
__device__ __forceinline__ void ldmx4t(uint32_t* r, uint32_t addr) {
    asm volatile("ldmatrix.sync.aligned.m8n8.x4.trans.shared.b16 {%0,%1,%2,%3}, [%4];"
                 : "=r"(r[0]), "=r"(r[1]), "=r"(r[2]), "=r"(r[3]) : "r"(addr));
}
__device__ __forceinline__ void mma_f16(float* c, const uint32_t* a, const uint32_t* b) {
    asm volatile(
        "mma.sync.aligned.m16n8k16.row.col.f32.f16.f16.f32 "
        "{%0,%1,%2,%3}, {%4,%5,%6,%7}, {%8,%9}, {%0,%1,%2,%3};"
        : "+f"(c[0]), "+f"(c[1]), "+f"(c[2]), "+f"(c[3])
        : "r"(a[0]), "r"(a[1]), "r"(a[2]), "r"(a[3]), "r"(b[0]), "r"(b[1]));
}
__device__ __forceinline__ void cp16(uint32_t dst, const void* src) {
    asm volatile("cp.async.cg.shared.global [%0], [%1], 16;" :: "r"(dst), "l"(src) : "memory");
}
#define CP_COMMIT() asm volatile("cp.async.commit_group;" ::: "memory")

__device__ __forceinline__ uint32_t ksw(int row, int c) {
    return (uint32_t)(row * 64) + ((uint32_t)(c ^ ((row >> 1) & 3)) << 4);
}

// ====================== fp16 pair GEMM (TERMS = 1/2/3) ======================
#define ATILE 8192
#define ASTG  16384
#define SBYTES 32768
#define NSTAGE 3
#define GSMEM (NSTAGE*SBYTES)

template<int TBK, int TERMS>
__global__ __launch_bounds__(256, 2)
void gemmx_k(const h16* __restrict__ Ah, const h16* __restrict__ Al,
             const h16* __restrict__ Bh, const h16* __restrict__ Bl,
             float* __restrict__ C, h16* __restrict__ Ch, h16* __restrict__ Cl,
             int N, int K, int Klen, int symm,
             long sA, long sB, long sC,
             const float* __restrict__ bias,
             const float* __restrict__ resid, long sR,
             int ldc, int relu_flag)
{
    if (!Klen && symm && blockIdx.x < blockIdx.y) return;
    extern __shared__ char sm[];
    uint32_t smb = smem_u32(sm);

    const int tid = threadIdx.x;
    const int lane = tid & 31;
    const int wid = tid >> 5;
    const int wm = (wid >> 2) * 64;
    const int wn = (wid & 3) * 32;

    long bz = blockIdx.z;
    const int bm = blockIdx.y * 128;
    const int nxt = N >> 7;
    int bn, kbase, kslice = 0;
    if (Klen) {
        kslice = (int)blockIdx.x / nxt;
        bn = ((int)blockIdx.x - kslice * nxt) << 7;
        kbase = kslice * Klen;
    } else {
        bn = (int)blockIdx.x << 7;
        kbase = 0;
    }
    const int KL = Klen ? Klen : K;

    const h16* Ahb = Ah + bz * sA + (size_t)bm * K + kbase;
    const h16* Alb = Al ? Al + bz * sA + (size_t)bm * K + kbase : (const h16*)0;
    const h16* Bhb = TBK ? (Bh + bz * sB + (size_t)bn * K + kbase)
                         : (Bh + bz * sB + (size_t)kbase * N + bn);
    const h16* Blb = Bl ? (TBK ? (Bl + bz * sB + (size_t)bn * K + kbase)
                               : (Bl + bz * sB + (size_t)kbase * N + bn))
                        : (const h16*)0;
    float* Cb = C ? (Klen ? C + (size_t)kslice * sC : C + bz * sC) : (float*)0;
    h16* Chb = Ch ? Ch + bz * sC : (h16*)0;
    h16* Clb = Cl ? Cl + bz * sC : (h16*)0;
    const float* Rb = resid ? resid + bz * sR : (const float*)0;

    float acc[4][4][4];
#pragma unroll
    for (int i = 0; i < 4; i++)
#pragma unroll
        for (int j = 0; j < 4; j++)
#pragma unroll
            for (int r = 0; r < 4; r++) acc[i][j][r] = 0.f;

    const int nch = KL >> 5;

    auto load_stage = [&](int kt, int s) {
        uint32_t base = smb + (uint32_t)s * SBYTES;
        int k0 = kt << 5;
#pragma unroll
        for (int it = 0; it < 4; it++) {
            int id = it * 256 + tid;
            int hl = id >> 9, rid = id & 511;
            int row = rid >> 2, c = rid & 3;
            if (TERMS >= 3 || hl == 0)
                cp16(base + hl * ATILE + ksw(row, c),
                     (hl ? Alb : Ahb) + (size_t)row * K + k0 + c * 8);
        }
        if (TBK) {
#pragma unroll
            for (int it = 0; it < 4; it++) {
                int id = it * 256 + tid;
                int hl = id >> 9, rid = id & 511;
                int row = rid >> 2, c = rid & 3;
                if (TERMS >= 2 || hl == 0)
                    cp16(base + ASTG + hl * ATILE + ksw(row, c),
                         (hl ? Blb : Bhb) + (size_t)row * K + k0 + c * 8);
            }
        } else {
#pragma unroll
            for (int it = 0; it < 4; it++) {
                int id = it * 256 + tid;
                int hl = id >> 9, rid = id & 511;
                int k = rid >> 4, c = rid & 15;
                if (TERMS >= 2 || hl == 0)
                    cp16(base + ASTG + hl * ATILE + k * 256 + ((c ^ (k & 7)) << 4),
                         (hl ? Blb : Bhb) + (size_t)(k0 + k) * N + c * 8);
            }
        }
        CP_COMMIT();
    };

    load_stage(0, 0);
    load_stage(1, 1);

    int sc = 0, sl = 2;
    for (int kt = 0; kt < nch; kt++) {
        asm volatile("cp.async.wait_group 1;" ::: "memory");
        __syncthreads();
        if (kt + 2 < nch) {
            load_stage(kt + 2, sl);
            sl = (sl + 1 == NSTAGE) ? 0 : sl + 1;
        } else {
            CP_COMMIT();
        }
        uint32_t aB = smb + (uint32_t)sc * SBYTES;
        uint32_t bB = aB + ASTG;
        sc = (sc + 1 == NSTAGE) ? 0 : sc + 1;

#pragma unroll
        for (int kh = 0; kh < 2; kh++) {
            uint32_t ahi[4][4], alo[4][4];
            {
                int u = kh * 2 + (lane >> 4);
#pragma unroll
                for (int i = 0; i < 4; i++) {
                    int r = wm + (lane & 15) + i * 16;
                    uint32_t ro = ksw(r, u);
                    ldmx4(ahi[i], aB + ro);
                    if (TERMS >= 3) ldmx4(alo[i], aB + ATILE + ro);
                }
            }
#pragma unroll
            for (int jp = 0; jp < 2; jp++) {
                uint32_t bh2[4], bl2[4];
                if (TBK) {
                    int row = wn + jp * 16 + ((lane >> 4) << 3) + (lane & 7);
                    int u = kh * 2 + ((lane >> 3) & 1);
                    uint32_t ro = ksw(row, u);
                    ldmx4(bh2, bB + ro);
                    if (TERMS >= 2) ldmx4(bl2, bB + ATILE + ro);
                } else {
                    int k = kh * 16 + ((lane >> 3) & 1) * 8 + (lane & 7);
                    uint32_t kro = (uint32_t)k << 8;
                    int colblk = (wn >> 3) + 2 * jp + (lane >> 4);
                    uint32_t ad = kro + ((uint32_t)(colblk ^ (k & 7)) << 4);
                    ldmx4t(bh2, bB + ad);
                    if (TERMS >= 2) ldmx4t(bl2, bB + ATILE + ad);
                }
                int j0 = 2 * jp, j1 = 2 * jp + 1;
#pragma unroll
                for (int i = 0; i < 4; i++) {
                    mma_f16(acc[i][j0], ahi[i], bh2 + 0);
                    mma_f16(acc[i][j1], ahi[i], bh2 + 2);
                }
                if (TERMS >= 2) {
#pragma unroll
                    for (int i = 0; i < 4; i++) {
                        mma_f16(acc[i][j0], ahi[i], bl2 + 0);
                        mma_f16(acc[i][j1], ahi[i], bl2 + 2);
                    }
                }
                if (TERMS >= 3) {
#pragma unroll
                    for (int i = 0; i < 4; i++) {
                        mma_f16(acc[i][j0], alo[i], bh2 + 0);
                        mma_f16(acc[i][j1], alo[i], bh2 + 2);
                    }
                }
            }
        }
    }

#pragma unroll
    for (int i = 0; i < 4; i++) {
        int r0 = bm + wm + i * 16 + (lane >> 2);
        int r1 = r0 + 8;
#pragma unroll
        for (int j = 0; j < 4; j++) {
            int gc = bn + wn + j * 8 + (lane & 3) * 2;
            float2 v0 = make_float2(acc[i][j][0], acc[i][j][1]);
            float2 v1 = make_float2(acc[i][j][2], acc[i][j][3]);
            if (bias) {
                float2 bv = *reinterpret_cast<const float2*>(bias + gc);
                v0.x += bv.x; v0.y += bv.y;
                v1.x += bv.x; v1.y += bv.y;
            }
            if (Rb) {
                float2 q0 = *reinterpret_cast<const float2*>(Rb + (size_t)r0 * ldc + gc);
                float2 q1 = *reinterpret_cast<const float2*>(Rb + (size_t)r1 * ldc + gc);
                v0.x += q0.x; v0.y += q0.y;
                v1.x += q1.x; v1.y += q1.y;
            }
            if (relu_flag) {
                v0.x = fmaxf(v0.x, 0.f); v0.y = fmaxf(v0.y, 0.f);
                v1.x = fmaxf(v1.x, 0.f); v1.y = fmaxf(v1.y, 0.f);
            }
            if (Cb) {
                *reinterpret_cast<float2*>(Cb + (size_t)r0 * ldc + gc) = v0;
                *reinterpret_cast<float2*>(Cb + (size_t)r1 * ldc + gc) = v1;
            }
            if (Chb) {
                uint32_t h0, l0, h1, l1;
                split2(v0.x, v0.y, h0, l0);
                split2(v1.x, v1.y, h1, l1);
                *reinterpret_cast<uint32_t*>(Chb + (size_t)r0 * ldc + gc) = h0;
                *reinterpret_cast<uint32_t*>(Clb + (size_t)r0 * ldc + gc) = l0;
                *reinterpret_cast<uint32_t*>(Chb + (size_t)r1 * ldc + gc) = h1;
                *reinterpret_cast<uint32_t*>(Clb + (size_t)r1 * ldc + gc) = l1;
            }
        }
    }
}

// ====================== SpMM gathering fp16-hi, fp16 pair out ======================
template<int NPT>
__global__ __launch_bounds__(256)
void spmmh_k(const int* __restrict__ scnt, const int* __restrict__ sidx,
             const float* __restrict__ swgt, const h16* __restrict__ X,
             const float* __restrict__ bias,
             h16* __restrict__ outH, h16* __restrict__ outL, int relu_flag)
{
    constexpr int W = NPT * 256;
    __shared__ int s_i[PP];
    __shared__ float s_w[PP];
    int row = blockIdx.x;
    int b = row >> 10;
    int tid = threadIdx.x;
    int cnt = scnt[row];
    const int* ip = sidx + (size_t)row * PP;
    const float* wp = swgt + (size_t)row * PP;
    for (int i = tid; i < cnt; i += 256) { s_i[i] = ip[i]; s_w[i] = wp[i]; }
    __syncthreads();
    const unsigned short* Xb =
        reinterpret_cast<const unsigned short*>(X) + (((size_t)b << 10) * W);
    float a0[NPT], a1[NPT], a2[NPT], a3[NPT];
#pragma unroll
    for (int r = 0; r < NPT; r++) { a0[r] = a1[r] = a2[r] = a3[r] = 0.f; }
    int e = 0;
    for (; e + 4 <= cnt; e += 4) {
        const unsigned short* x0 = Xb + (size_t)s_i[e + 0] * W;
        const unsigned short* x1 = Xb + (size_t)s_i[e + 1] * W;
        const unsigned short* x2 = Xb + (size_t)s_i[e + 2] * W;
        const unsigned short* x3 = Xb + (size_t)s_i[e + 3] * W;
        float w0 = s_w[e], w1 = s_w[e + 1], w2 = s_w[e + 2], w3 = s_w[e + 3];
#pragma unroll
        for (int r = 0; r < NPT; r++) {
            int c = r * 256 + tid;
            a0[r] += w0 * __half2float(__ushort_as_half(x0[c]));
            a1[r] += w1 * __half2float(__ushort_as_half(x1[c]));
            a2[r] += w2 * __half2float(__ushort_as_half(x2[c]));
            a3[r] += w3 * __half2float(__ushort_as_half(x3[c]));
        }
    }
    for (; e < cnt; e++) {
        const unsigned short* x0 = Xb + (size_t)s_i[e] * W;
        float w0 = s_w[e];
#pragma unroll
        for (int r = 0; r < NPT; r++)
            a0[r] += w0 * __half2float(__ushort_as_half(x0[r * 256 + tid]));
    }
    unsigned short* oh = reinterpret_cast<unsigned short*>(outH) + (size_t)row * W;
    unsigned short* ol = reinterpret_cast<unsigned short*>(outL) + (size_t)row * W;
#pragma unroll
    for (int r = 0; r < NPT; r++) {
        int c = r * 256 + tid;
        float v = (a0[r] + a1[r]) + (a2[r] + a3[r]);
        if (bias) v += bias[c];
        if (relu_flag) v = fmaxf(v, 0.f);
        unsigned short hq, lq;
        split1(v, hq, lq);
        oh[c] = hq;
        ol[c] = lq;
    }
}

// narrow SpMM: 128 cols, fp32 in/out
__global__ __launch_bounds__(128)
void spmms_k(const int* __restrict__ scnt, const int* __restrict__ sidx,
             const float* __restrict__ swgt, const float* __restrict__ X,
             float* __restrict__ out)
{
    __shared__ int s_i[PP];
    __shared__ float s_w[PP];
    int row = blockIdx.x;
    int b = row >> 10;
    int tid = threadIdx.x;
    int cnt = scnt[row];
    const int* ip = sidx + (size_t)row * PP;
    const float* wp = swgt + (size_t)row * PP;
    for (int i = tid; i < cnt; i += 128) { s_i[i] = ip[i]; s_w[i] = wp[i]; }
    __syncthreads();
    const float* Xb = X + (((size_t)b << 10) * 128);
    float a0 = 0.f, a1 = 0.f, a2 = 0.f, a3 = 0.f;
    int e = 0;
    for (; e + 4 <= cnt; e += 4) {
        a0 += s_w[e]     * Xb[(size_t)s_i[e]     * 128 + tid];
        a1 += s_w[e + 1] * Xb[(size_t)s_i[e + 1] * 128 + tid];
        a2 += s_w[e + 2] * Xb[(size_t)s_i[e + 2] * 128 + tid];
        a3 += s_w[e + 3] * Xb[(size_t)s_i[e + 3] * 128 + tid];
    }
    for (; e < cnt; e++) a0 += s_w[e] * Xb[(size_t)s_i[e] * 128 + tid];
    out[(size_t)row * 128 + tid] = (a0 + a1) + (a2 + a3);
}

// edge-wise comp cosine; own row fp32 in smem, gathered rows fp16-hi
__global__ __launch_bounds__(256)
void dotc_k(const int* __restrict__ scnt, const int* __restrict__ sidx,
            float* __restrict__ swc, const float* __restrict__ comp,
            const h16* __restrict__ ch, const float* __restrict__ nc)
{
    __shared__ float xp[DDC];
    __shared__ int s_i[PP];
    __shared__ float s_m[PP];
    int row = blockIdx.x, b = row >> 10, tid = threadIdx.x;
    int cnt = scnt[row];
    const int* ip = sidx + (size_t)row * PP;
    float* wp = swc + (size_t)row * PP;
    for (int i = tid; i < cnt; i += 256) { s_i[i] = ip[i]; s_m[i] = wp[i]; }
    {
        const float4* cp4 = reinterpret_cast<const float4*>(comp + (size_t)row * DDC);
        for (int i = tid; i < DDC / 4; i += 256) {
            float4 v = cp4[i];
            xp[i * 4 + 0] = v.x; xp[i * 4 + 1] = v.y;
            xp[i * 4 + 2] = v.z; xp[i * 4 + 3] = v.w;
        }
    }
    __syncthreads();
    float ncp = nc[row];
    int wid = tid >> 5, lane = tid & 31;
    for (int e = wid; e < cnt; e += 8) {
        int q = s_i[e];
        const uint4* xq = reinterpret_cast<const uint4*>(
            ch + ((size_t)(b << 10) + q) * DDC);
        float acc = 0.f;
#pragma unroll 2
        for (int i = lane; i < DDC / 8; i += 32) {
            uint4 u = __ldg(xq + i);
            float2 f0 = __half22float2(*reinterpret_cast<__half2*>(&u.x));
            float2 f1 = __half22float2(*reinterpret_cast<__half2*>(&u.y));
            float2 f2 = __half22float2(*reinterpret_cast<__half2*>(&u.z));
            float2 f3 = __half22float2(*reinterpret_cast<__half2*>(&u.w));
            int o = i * 8;
            acc += xp[o+0]*f0.x + xp[o+1]*f0.y + xp[o+2]*f1.x + xp[o+3]*f1.y
                 + xp[o+4]*f2.x + xp[o+5]*f2.y + xp[o+6]*f3.x + xp[o+7]*f3.y;
        }
#pragma unroll
        for (int o = 16; o; o >>= 1) acc += __shfl_xor_sync(0xffffffffu, acc, o);
        if (lane == 0) {
            float cv = acc / (ncp * nc[(b << 10) + q] + 1e-6f);
            wp[e] = fmaxf(cv * s_m[e], 0.f);
        }
    }
}

__global__ __launch_bounds__(256)
void ncdirect_k(const float* __restrict__ comp, float* __restrict__ nc)
{
    int row = blockIdx.x * 8 + (threadIdx.x >> 5);
    int lane = threadIdx.x & 31;
    const float4* r4 = reinterpret_cast<const float4*>(comp + (size_t)row * DDC);
    float acc = 0.f;
#pragma unroll 4
    for (int i = lane; i < DDC / 4; i += 32) {
        float4 a = __ldg(r4 + i);
        acc += a.x * a.x + a.y * a.y + a.z * a.z + a.w * a.w;
    }
#pragma unroll
    for (int o = 16; o; o >>= 1) acc += __shfl_xor_sync(0xffffffffu, acc, o);
    if (lane == 0) nc[row] = sqrtf(acc);
}

// fused constant head rows: blocks 0..127 -> cba, 128..255 -> cbc
__global__ __launch_bounds__(256)
void cbias12_k(const float* __restrict__ ab2, const float* __restrict__ aw,
               const float* __restrict__ ab,
               const float* __restrict__ cb2,
               const float* __restrict__ wc, const float* __restrict__ bc,
               const float* __restrict__ wr, const float* __restrict__ br,
               float* __restrict__ cba, float* __restrict__ cbc)
{
    __shared__ float ws[8];
    int blk = blockIdx.x;
    int tid = threadIdx.x;
    float acc = 0.f;
    if (blk < 128) {
        int c = blk;
        if (c < 21)
            for (int k = tid; k < DDA; k += 256) acc += ab2[k] * aw[k * 21 + c];
    } else {
        int c = blk - 128;
        if (c < 20) {
            for (int k = tid; k < DDC; k += 256) acc += cb2[k] * wc[k * 20 + c];
        } else if (c < 60) {
            int c2 = c - 20;
            for (int k = tid; k < DDC; k += 256) acc += cb2[k] * wr[k * 40 + c2];
        }
    }
#pragma unroll
    for (int o = 16; o; o >>= 1) acc += __shfl_xor_sync(0xffffffffu, acc, o);
    if ((tid & 31) == 0) ws[tid >> 5] = acc;
    __syncthreads();
    if (tid == 0) {
        float v = 0.f;
        for (int i = 0; i < 8; i++) v += ws[i];
        if (blk < 128) {
            cba[blk] = (blk < 21) ? v + ab[blk] : 0.f;
        } else {
            int c = blk - 128;
            if (c < 20) v += bc[c];
            else if (c < 60) v += br[c - 20];
            else v = 0.f;
            cbc[c] = v;
        }
    }
}

// ====================== elementwise kernels ======================
__global__ void split_k(const float* __restrict__ s, h16* __restrict__ h,
                        h16* __restrict__ l, size_t n4)
{
    for (size_t i = (size_t)blockIdx.x * blockDim.x + threadIdx.x; i < n4;
         i += (size_t)gridDim.x * blockDim.x) {
        float4 v = reinterpret_cast<const float4*>(s)[i];
        uint32_t h0, l0, h1, l1;
        split2(v.x, v.y, h0, l0);
        split2(v.z, v.w, h1, l1);
        reinterpret_cast<uint2*>(h)[i] = make_uint2(h0, h1);
        reinterpret_cast<uint2*>(l)[i] = make_uint2(l0, l1);
    }
}

__global__ void splith_k(const float* __restrict__ s, h16* __restrict__ h, size_t n4)
{
    for (size_t i = (size_t)blockIdx.x * blockDim.x + threadIdx.x; i < n4;
         i += (size_t)gridDim.x * blockDim.x) {
        float4 v = reinterpret_cast<const float4*>(s)[i];
        __half2 p0 = __floats2half2_rn(v.x, v.y);
        __half2 p1 = __floats2half2_rn(v.z, v.w);
        reinterpret_cast<uint2*>(h)[i] =
            make_uint2(*reinterpret_cast<uint32_t*>(&p0), *reinterpret_cast<uint32_t*>(&p1));
    }
}

__global__ void rednsplit_k(const float* __restrict__ p, size_t n4, int nsl,
                            h16* __restrict__ h, h16* __restrict__ l)
{
    for (size_t i = (size_t)blockIdx.x * blockDim.x + threadIdx.x; i < n4;
         i += (size_t)gridDim.x * blockDim.x) {
        float4 a = reinterpret_cast<const float4*>(p)[i];
        for (int s = 1; s < nsl; s++) {
            float4 b = reinterpret_cast<const float4*>(p)[(size_t)s * n4 + i];
            a.x += b.x; a.y += b.y; a.z += b.z; a.w += b.w;
        }
        uint32_t h0, l0, h1, l1;
        split2(a.x, a.y, h0, l0);
        split2(a.z, a.w, h1, l1);
        reinterpret_cast<uint2*>(h)[i] = make_uint2(h0, h1);
        reinterpret_cast<uint2*>(l)[i] = make_uint2(l0, l1);
    }
}

// head panel with fused zero-fill
__global__ void padsplitz_k(const float* __restrict__ s1, int Ns1,
                            const float* __restrict__ s2, int Ns2,
                            h16* __restrict__ h, h16* __restrict__ l, int K)
{
    int total = K * 128;
    for (int i = blockIdx.x * blockDim.x + threadIdx.x; i < total;
         i += gridDim.x * blockDim.x) {
        int k = i >> 7, n = i & 127;
        float v = 0.f;
        if (n < Ns1) v = s1[k * Ns1 + n];
        else if (s2 && n < Ns1 + Ns2) v = s2[k * Ns2 + (n - Ns1)];
        unsigned short hq, lq;
        split1(v, hq, lq);
        reinterpret_cast<unsigned short*>(h)[i] = hq;
        reinterpret_cast<unsigned short*>(l)[i] = lq;
    }
}

__global__ void norms_k(const float* __restrict__ G, float* __restrict__ nrm)
{
    int i = blockIdx.x * blockDim.x + threadIdx.x;
    if (i < BQ * PP) {
        int b = i >> 10, p = i & (PP - 1);
        nrm[i] = sqrtf(G[((size_t)b * PP + p) * PP + p]);
    }
}

__global__ __launch_bounds__(256)
void mirror1_k(float* __restrict__ A)
{
    int tj = blockIdx.x, ti = blockIdx.y, b = blockIdx.z;
    if (ti <= tj || (ti >> 2) == (tj >> 2)) return;
    __shared__ float ta[32][33];
    int tx = threadIdx.x & 31, ty = threadIdx.x >> 5;
    size_t base = (size_t)b * PP * PP;
#pragma unroll
    for (int it = 0; it < 4; it++) {
        int r = ty + it * 8;
        ta[r][tx] = A[base + (size_t)(tj * 32 + r) * PP + ti * 32 + tx];
    }
    __syncthreads();
#pragma unroll
    for (int it = 0; it < 4; it++) {
        int r = ty + it * 8;
        A[base + (size_t)(ti * 32 + r) * PP + tj * 32 + tx] = ta[tx][r];
    }
}

__global__ void outasm_k(const float* __restrict__ spa, const float* __restrict__ spc,
                         const float* __restrict__ hp1, const float* __restrict__ hp2,
                         const float* __restrict__ cba, const float* __restrict__ cbc,
                         float* __restrict__ out)
{
    int i = blockIdx.x * blockDim.x + threadIdx.x;
    int total = BQ * PP * 81;
    if (i >= total) return;
    int row = i / 81, col = i - row * 81;
    float v;
    if (col < 21) {
        v = cba[col] + spa[(size_t)row * 128 + col];
#pragma unroll
        for (int s = 0; s < 8; s++)
            v += hp1[((size_t)s * BQ * PP + row) * 128 + col];
    } else {
        int c2 = col - 21;
        v = cbc[c2] + spc[(size_t)row * 128 + c2];
#pragma unroll
        for (int s = 0; s < 8; s++)
            v += hp2[((size_t)s * BQ * PP + row) * 128 + c2];
    }
    out[i] = v;
}

// ---------------- graph construction ----------------
__device__ __forceinline__ void warp_argmin(float& v, int& l)
{
#pragma unroll
    for (int off = 16; off; off >>= 1) {
        float ov = __shfl_down_sync(0xffffffffu, v, off);
        int ol = __shfl_down_sync(0xffffffffu, l, off);
        if (ov < v) { v = ov; l = ol; }
    }
    v = __shfl_sync(0xffffffffu, v, 0);
    l = __shfl_sync(0xffffffffu, l, 0);
}
__device__ __forceinline__ void warp_argmax(float& v, int& l)
{
#pragma unroll
    for (int off = 16; off; off >>= 1) {
        float ov = __shfl_down_sync(0xffffffffu, v, off);
        int ol = __shfl_down_sync(0xffffffffu, l, off);
        if (ov > v) { v = ov; l = ol; }
    }
    v = __shfl_sync(0xffffffffu, v, 0);
    l = __shfl_sync(0xffffffffu, l, 0);
}

__global__ __launch_bounds__(128)
void build_adj_k(const float* __restrict__ iou, const float* __restrict__ dis,
                 const float* __restrict__ acos_, const float* __restrict__ na,
                 const int* __restrict__ props,
                 int* __restrict__ sidx, float* __restrict__ swa,
                 float* __restrict__ swm, int* __restrict__ scnt)
{
    __shared__ float sio[4][PP];
    int warp = threadIdx.x >> 5, lane = threadIdx.x & 31;
    int row = blockIdx.x * 4 + warp;
    if (row >= BQ * PP) return;
    int b = row >> 10;
    int p = row & (PP - 1);
    const float* iour = iou + (size_t)row * PP;
    const float* disr = dis + (size_t)row * PP;
    const float* ar = acos_ + (size_t)row * PP;
    const float* nab = na + (b << 10);
    float npa = nab[p];
    int pn = props[b];
    bool pv = p < pn;

    float* io_s = sio[warp];
    for (int q = lane; q < PP; q += 32) io_s[q] = iour[q];
    __syncwarp();

    float dv[6]; int di[6];
#pragma unroll
    for (int j = 0; j < 6; j++) { dv[j] = 3.0e38f; di[j] = -1; }
    float sv[2] = {-3.0e38f, -3.0e38f};
    int si2[2] = {-1, -1};

    for (int q = lane; q < PP; q += 32) {
        float io = io_s[q];
        bool ip = io > 0.0f;
        bool qv = q < pn;
        bool v2 = pv && qv;

        float dm = v2 ? (ip ? 2.0f : disr[q]) : 1.0e9f;
        if (dm < dv[5]) {
            dv[5] = dm; di[5] = q;
#pragma unroll
            for (int j = 5; j > 0; j--) {
                if (dv[j] < dv[j - 1]) {
                    float tv = dv[j]; dv[j] = dv[j - 1]; dv[j - 1] = tv;
                    int ti = di[j]; di[j] = di[j - 1]; di[j - 1] = ti;
                }
            }
        }
        float av = ar[q] / (npa * nab[q] + 1e-6f);
        float sm = v2 ? (ip ? 0.0f : (av - (q == p ? 1.0f : 0.0f))) : -1.0e9f;
        if (sm > sv[1]) {
            if (sm > sv[0]) { sv[1] = sv[0]; si2[1] = si2[0]; sv[0] = sm; si2[0] = q; }
            else            { sv[1] = sm; si2[1] = q; }
        }
    }

    int sel[8];
    {
        int ptr = 0;
        for (int k = 0; k < 6; k++) {
            float cv = (ptr < 6) ? dv[ptr] : 3.0e38f;
            int ci = (ptr < 6) ? di[ptr] : -1;
            float v = cv; int l = lane;
            warp_argmin(v, l);
            sel[k] = __shfl_sync(0xffffffffu, ci, l);
            if (lane == l) ptr++;
        }
    }
    {
        int ptr = 0;
        for (int k = 0; k < 2; k++) {
            float cv = (ptr < 2) ? sv[ptr] : -3.0e38f;
            int ci = (ptr < 2) ? si2[ptr] : -1;
            float v = cv; int l = lane;
            warp_argmax(v, l);
            sel[6 + k] = __shfl_sync(0xffffffffu, ci, l);
            if (lane == l) ptr++;
        }
    }
#pragma unroll
    for (int k = 0; k < 8; k++) {
        int q = sel[k];
        bool ok = (q >= 0) && pv && (q < pn) && !(io_s[q] > 0.0f);
        sel[k] = ok ? q : -1;
    }

    unsigned mbits = 0;
    for (int i = 0; i < 32; i++) {
        int q = lane + 32 * i;
        float io = io_s[q];
        bool bit = (q != p) && (io > 0.7f);
#pragma unroll
        for (int k = 0; k < 8; k++) bit |= (sel[k] == q);
        mbits |= (bit ? 1u : 0u) << i;
    }
    int cnt = __popc(mbits);
#pragma unroll
    for (int off = 16; off; off >>= 1) cnt += __shfl_xor_sync(0xffffffffu, cnt, off);
    float inv = 1.0f / ((float)cnt + 1e-6f);

    int* rI = sidx + (size_t)row * PP;
    float* rA = swa + (size_t)row * PP;
    float* rM = swm + (size_t)row * PP;
    int base = 0;
    for (int i = 0; i < 32; i++) {
        int q = lane + 32 * i;
        float m = ((mbits >> i) & 1u) ? inv : 0.0f;
        if (q == p) m += 1.0f;
        bool en = m > 0.f;
        unsigned bal = __ballot_sync(0xffffffffu, en);
        if (en) {
            int pos = base + __popc(bal & ((1u << lane) - 1u));
            float av = ar[q] / (npa * nab[q] + 1e-6f);
            rI[pos] = q;
            rA[pos] = fmaxf(av * m, 0.f);
            rM[pos] = m;
        }
        base += __popc(bal);
    }
    if (lane == 0) scnt[row] = base;
}

// ---------------- host ----------------
static void gx(cudaStream_t st, int tbk, int terms,
               const h16* Ah, const h16* Al, const h16* Bh, const h16* Bl,
               float* C, h16* Ch, h16* Cl,
               int M, int N, int K, int Klen, int symm,
               long sA, long sB, long sC, int batch,
               const float* bias, const float* resid, long sR,
               int ldc, int relu)
{
    int nxt = N >> 7;
    int gxd = Klen ? nxt * (K / Klen) : nxt;
    dim3 grid(gxd, M / 128, batch);
    if (tbk == 1 && terms == 3) {
        cudaFuncSetAttribute(gemmx_k<1,3>, cudaFuncAttributeMaxDynamicSharedMemorySize, GSMEM);
        gemmx_k<1,3><<<grid, 256, GSMEM, st>>>(Ah, Al, Bh, Bl, C, Ch, Cl, N, K, Klen, symm,
                                               sA, sB, sC, bias, resid, sR, ldc, relu);
    } else if (tbk == 0 && terms == 1) {
        cudaFuncSetAttribute(gemmx_k<0,1>, cudaFuncAttributeMaxDynamicSharedMemorySize, GSMEM);
        gemmx_k<0,1><<<grid, 256, GSMEM, st>>>(Ah, Al, Bh, Bl, C, Ch, Cl, N, K, Klen, symm,
                                               sA, sB, sC, bias, resid, sR, ldc, relu);
    } else if (tbk == 0 && terms == 2) {
        cudaFuncSetAttribute(gemmx_k<0,2>, cudaFuncAttributeMaxDynamicSharedMemorySize, GSMEM);
        gemmx_k<0,2><<<grid, 256, GSMEM, st>>>(Ah, Al, Bh, Bl, C, Ch, Cl, N, K, Klen, symm,
                                               sA, sB, sC, bias, resid, sR, ldc, relu);
    } else {
        cudaFuncSetAttribute(gemmx_k<0,3>, cudaFuncAttributeMaxDynamicSharedMemorySize, GSMEM);
        gemmx_k<0,3><<<grid, 256, GSMEM, st>>>(Ah, Al, Bh, Bl, C, Ch, Cl, N, K, Klen, symm,
                                               sA, sB, sC, bias, resid, sR, ldc, relu);
    }
}

#define SYM(var, sym) cudaGetSymbolAddress((void**)&var, sym)

extern "C" void kernel_launch(void* const* d_in, const int* in_sizes, int n_in,
                              void* d_out, int out_size)
{
    const float* act   = (const float*)d_in[0];
    const float* comp  = (const float*)d_in[1];
    const float* iou   = (const float*)d_in[2];
    const float* dis   = (const float*)d_in[3];
    const int*   props = (const int*)d_in[4];
    const float* a_w1  = (const float*)d_in[5];
    const float* a_b1  = (const float*)d_in[6];
    const float* a_w2  = (const float*)d_in[7];
    const float* a_b2  = (const float*)d_in[8];
    const float* c_w1  = (const float*)d_in[9];
    const float* c_b1  = (const float*)d_in[10];
    const float* c_w2  = (const float*)d_in[11];
    const float* c_b2  = (const float*)d_in[12];
    const float* fa_w  = (const float*)d_in[13];
    const float* fa_b  = (const float*)d_in[14];
    const float* fc_w  = (const float*)d_in[15];
    const float* fc_b  = (const float*)d_in[16];
    const float* fr_w  = (const float*)d_in[17];
    const float* fr_b  = (const float*)d_in[18];
    float* out = (float*)d_out;

    float *acos_, *na, *nc, *hp1, *hp2, *kpc, *kps1, *kps2;
    float *tfa, *tfc, *spa, *spc, *cba, *cbc, *swa, *swc;
    h16 *ah, *al, *ch_;
    h16 *t1ah, *t1al, *t1ch, *t1cl, *t2ah, *t2al, *t2ch, *t2cl;
    h16 *w1ah, *w2ah, *w2al, *w1ch, *w2ch, *w2cl;
    h16 *wp1h, *wp1l, *wp2h, *wp2l, *s1h, *s1l, *s2h, *s2l;
    int *sidx, *scnt;
    SYM(acos_, g_acos); SYM(na, g_na); SYM(nc, g_nc);
    SYM(ah, g_ah); SYM(al, g_al); SYM(ch_, g_ch);
    SYM(t1ah, g_t1ah); SYM(t1al, g_t1al); SYM(t1ch, g_t1ch); SYM(t1cl, g_t1cl);
    SYM(t2ah, g_t2ah); SYM(t2al, g_t2al); SYM(t2ch, g_t2ch); SYM(t2cl, g_t2cl);
    SYM(w1ah, g_w1ah); SYM(w2ah, g_w2ah); SYM(w2al, g_w2al);
    SYM(w1ch, g_w1ch); SYM(w2ch, g_w2ch); SYM(w2cl, g_w2cl);
    SYM(wp1h, g_wp1h); SYM(wp1l, g_wp1l); SYM(wp2h, g_wp2h); SYM(wp2l, g_wp2l);
    SYM(s1h, g_s1h); SYM(s1l, g_s1l); SYM(s2h, g_s2h); SYM(s2l, g_s2l);
    SYM(hp1, g_hp1); SYM(hp2, g_hp2);
    SYM(kpc, g_kpc); SYM(kps1, g_kps1); SYM(kps2, g_kps2);
    SYM(tfa, g_tfa); SYM(tfc, g_tfc); SYM(spa, g_spa); SYM(spc, g_spc);
    SYM(cba, g_cba); SYM(cbc, g_cbc);
    SYM(sidx, g_sidx); SYM(swa, g_swa); SYM(swc, g_swc); SYM(scnt, g_scnt);

    // streams/events created once (host-side objects only; no device memory)
    static cudaStream_t sB = 0, sC = 0;
    static cudaEvent_t eFork, eAH, eCH, eT1C, eS2, eAdj, eSPA, eBEnd;
    if (!sB) {
        cudaStreamCreateWithFlags(&sB, cudaStreamNonBlocking);
        cudaStreamCreateWithFlags(&sC, cudaStreamNonBlocking);
        cudaEventCreateWithFlags(&eFork, cudaEventDisableTiming);
        cudaEventCreateWithFlags(&eAH,   cudaEventDisableTiming);
        cudaEventCreateWithFlags(&eCH,   cudaEventDisableTiming);
        cudaEventCreateWithFlags(&eT1C,  cudaEventDisableTiming);
        cudaEventCreateWithFlags(&eS2,   cudaEventDisableTiming);
        cudaEventCreateWithFlags(&eAdj,  cudaEventDisableTiming);
        cudaEventCreateWithFlags(&eSPA,  cudaEventDisableTiming);
        cudaEventCreateWithFlags(&eBEnd, cudaEventDisableTiming);
    }
    cudaStream_t s0 = 0;   // capture-origin (legacy default) stream

    // ---------------- fork ----------------
    cudaEventRecord(eFork, s0);
    cudaStreamWaitEvent(sB, eFork, 0);
    cudaStreamWaitEvent(sC, eFork, 0);

    // ---- s0: act split -> gram -> graph ----
    split_k<<<1024, 256, 0, s0>>>(act, ah, al, (size_t)BQ * PP * DDA / 4);
    cudaEventRecord(eAH, s0);
    gx(s0, 1, 3, ah, al, ah, al, acos_, 0, 0, PP, PP, DDA, 0, 1,
       (long)PP * DDA, (long)PP * DDA, (long)PP * PP, BQ, 0, 0, 0, PP, 0);
    norms_k<<<(BQ * PP + 255) / 256, 256, 0, s0>>>(acos_, na);
    mirror1_k<<<dim3(32, 32, BQ), 256, 0, s0>>>(acos_);
    build_adj_k<<<BQ * PP / 4, 128, 0, s0>>>(iou, dis, acos_, na, props,
                                             sidx, swa, swc, scnt);
    cudaEventRecord(eAdj, s0);

    // ---- sB: comp prep + comp t1 + S2 + comp head ----
    splith_k<<<2048, 256, 0, sB>>>(comp, ch_, (size_t)BQ * PP * DDC / 4);
    ncdirect_k<<<BQ * PP / 8, 256, 0, sB>>>(comp, nc);
    cudaEventRecord(eCH, sB);
    splith_k<<<512, 256, 0, sB>>>(c_w1, w1ch, (size_t)DDC * HID / 4);
    gx(sB, 0, 1, ch_, 0, w1ch, 0, kpc, 0, 0, BQ * PP, HID, DDC, 1536, 0,
       0, 0, (long)BQ * PP * HID, 1, 0, 0, 0, HID, 0);
    rednsplit_k<<<2048, 256, 0, sB>>>(kpc, (size_t)BQ * PP * HID / 4, 2, t1ch, t1cl);
    cudaEventRecord(eT1C, sB);
    split_k<<<512, 256, 0, sB>>>(c_w2, w2ch, w2cl, (size_t)HID * DDC / 4);
    padsplitz_k<<<384, 256, 0, sB>>>(fc_w, 20, fr_w, 40, wp2h, wp2l, DDC);
    gx(sB, 0, 3, w2ch, w2cl, wp2h, wp2l, kps2, 0, 0, HID, 128, DDC, 192, 0,
       0, 0, (long)HID * 128, 1, 0, 0, 0, 128, 0);
    rednsplit_k<<<64, 256, 0, sB>>>(kps2, (size_t)HID * 128 / 4, 16, s2h, s2l);
    cudaEventRecord(eS2, sB);
    // comp head: x@Wh2, TERMS=2, 8 K-slices of 384
    gx(sB, 0, 2, ch_, 0, wp2h, wp2l, hp2, 0, 0, BQ * PP, 128, DDC, 384, 0,
       0, 0, (long)BQ * PP * 128, 1, 0, 0, 0, 128, 0);
    cudaEventRecord(eBEnd, sB);

    // ---- sC: act weight prep + act chain + act head ----
    splith_k<<<256, 256, 0, sC>>>(a_w1, w1ah, (size_t)DDA * HID / 4);
    split_k<<<256, 256, 0, sC>>>(a_w2, w2ah, w2al, (size_t)HID * DDA / 4);
    padsplitz_k<<<128, 256, 0, sC>>>(fa_w, 21, 0, 0, wp1h, wp1l, DDA);
    gx(sC, 0, 3, w2ah, w2al, wp1h, wp1l, kps1, 0, 0, HID, 128, DDA, 128, 0,
       0, 0, (long)HID * 128, 1, 0, 0, 0, 128, 0);
    rednsplit_k<<<64, 256, 0, sC>>>(kps1, (size_t)HID * 128 / 4, 8, s1h, s1l);
    cbias12_k<<<256, 256, 0, sC>>>(a_b2, fa_w, fa_b, c_b2, fc_w, fc_b, fr_w, fr_b,
                                   cba, cbc);
    cudaStreamWaitEvent(sC, eAH, 0);
    // x@w1a: TERMS=1, fp16 pair out
    gx(sC, 0, 1, ah, 0, w1ah, 0, 0, t1ah, t1al, BQ * PP, HID, DDA, 0, 0,
       0, 0, 0, 1, 0, 0, 0, HID, 0);
    // act head: x@Wh1, TERMS=2, 8 K-slices of 128
    gx(sC, 0, 2, ah, 0, wp1h, wp1l, hp1, 0, 0, BQ * PP, 128, DDA, 128, 0,
       0, 0, (long)BQ * PP * 128, 1, 0, 0, 0, 128, 0);
    cudaStreamWaitEvent(sC, eAdj, 0);
    spmmh_k<2><<<BQ * PP, 256, 0, sC>>>(scnt, sidx, swa, t1ah, a_b1, t2ah, t2al, 1);
    // t2@S1: TERMS=1, no K-split, fp32 out
    gx(sC, 0, 1, t2ah, 0, s1h, 0, tfa, 0, 0, BQ * PP, 128, HID, 0, 0,
       0, 0, 0, 1, 0, 0, 0, 128, 0);
    spmms_k<<<BQ * PP, 128, 0, sC>>>(scnt, sidx, swa, tfa, spa);
    cudaEventRecord(eSPA, sC);

    // ---- s0: dotc + comp sparse chain ----
    cudaStreamWaitEvent(s0, eCH, 0);
    dotc_k<<<BQ * PP, 256, 0, s0>>>(scnt, sidx, swc, comp, ch_, nc);
    cudaStreamWaitEvent(s0, eT1C, 0);
    spmmh_k<2><<<BQ * PP, 256, 0, s0>>>(scnt, sidx, swc, t1ch, c_b1, t2ch, t2cl, 1);
    cudaStreamWaitEvent(s0, eS2, 0);
    gx(s0, 0, 1, t2ch, 0, s2h, 0, tfc, 0, 0, BQ * PP, 128, HID, 0, 0,
       0, 0, 0, 1, 0, 0, 0, 128, 0);
    spmms_k<<<BQ * PP, 128, 0, s0>>>(scnt, sidx, swc, tfc, spc);

    // ---------------- join + final assembly ----------------
    cudaStreamWaitEvent(s0, eSPA, 0);
    cudaStreamWaitEvent(s0, eBEnd, 0);
    outasm_k<<<(BQ * PP * 81 + 255) / 256, 256, 0, s0>>>(spa, spc, hp1, hp2,
                                                         cba, cbc, out);
}